// round 1
// baseline (speedup 1.0000x reference)
#include <cuda_runtime.h>

// Problem constants
#define NB    4
#define LSEQ  2048
#define EMB   1024
#define NH    16
#define HD    64
#define MROWS (NB * LSEQ)   // 8192

// Scratch (static device arrays — no allocation allowed)
__device__ float g_q[MROWS * EMB];
__device__ float g_k[MROWS * EMB];
__device__ float g_v[MROWS * EMB];
__device__ float g_att[MROWS * EMB];

// ---------------------------------------------------------------------------
// GEMM: C[M,N] = A[M,K] @ W[N,K]^T + bias[N]   (Linear layer, row-major)
// 128x128 block tile, BK=16, 256 threads, 8x8 per-thread microtile.
// M=8192, N=1024, K=1024 — all dims divide tiles exactly, no bounds checks.
// ---------------------------------------------------------------------------
#define BM 128
#define BN 128
#define BK 16

__global__ __launch_bounds__(256) void gemm_bias_kernel(
    const float* __restrict__ A,
    const float* __restrict__ W,
    const float* __restrict__ bias,
    float* __restrict__ C,
    int M, int N, int K)
{
    __shared__ float As[BK][BM];
    __shared__ float Bs[BK][BN];

    const int tid = threadIdx.x;
    const int tx = tid & 15;         // 0..15 -> N microtile
    const int ty = tid >> 4;         // 0..15 -> M microtile
    const int row0 = blockIdx.y * BM;
    const int col0 = blockIdx.x * BN;

    float acc[8][8];
#pragma unroll
    for (int i = 0; i < 8; i++)
#pragma unroll
        for (int j = 0; j < 8; j++) acc[i][j] = 0.0f;

    for (int kt = 0; kt < K; kt += BK) {
        // Load A tile (128x16) transposed into As[k][m]
#pragma unroll
        for (int i = 0; i < 2; i++) {
            int idx = tid + i * 256;         // 0..511
            int r  = idx >> 2;               // 0..127
            int kv = idx & 3;                // float4 slot within row
            float4 a = *(const float4*)&A[(size_t)(row0 + r) * K + kt + kv * 4];
            As[kv * 4 + 0][r] = a.x;
            As[kv * 4 + 1][r] = a.y;
            As[kv * 4 + 2][r] = a.z;
            As[kv * 4 + 3][r] = a.w;
        }
        // Load W tile (128x16) transposed into Bs[k][n]
#pragma unroll
        for (int i = 0; i < 2; i++) {
            int idx = tid + i * 256;
            int r  = idx >> 2;
            int kv = idx & 3;
            float4 b = *(const float4*)&W[(size_t)(col0 + r) * K + kt + kv * 4];
            Bs[kv * 4 + 0][r] = b.x;
            Bs[kv * 4 + 1][r] = b.y;
            Bs[kv * 4 + 2][r] = b.z;
            Bs[kv * 4 + 3][r] = b.w;
        }
        __syncthreads();

#pragma unroll
        for (int kk = 0; kk < BK; kk++) {
            float ra[8], rb[8];
            *(float4*)(ra + 0) = *(const float4*)&As[kk][ty * 8 + 0];
            *(float4*)(ra + 4) = *(const float4*)&As[kk][ty * 8 + 4];
            *(float4*)(rb + 0) = *(const float4*)&Bs[kk][tx * 8 + 0];
            *(float4*)(rb + 4) = *(const float4*)&Bs[kk][tx * 8 + 4];
#pragma unroll
            for (int i = 0; i < 8; i++)
#pragma unroll
                for (int j = 0; j < 8; j++)
                    acc[i][j] += ra[i] * rb[j];
        }
        __syncthreads();
    }

    // Epilogue: add bias, store
#pragma unroll
    for (int i = 0; i < 8; i++) {
        int r = row0 + ty * 8 + i;
#pragma unroll
        for (int j = 0; j < 8; j += 4) {
            int c = col0 + tx * 8 + j;
            float4 o;
            o.x = acc[i][j + 0] + bias[c + 0];
            o.y = acc[i][j + 1] + bias[c + 1];
            o.z = acc[i][j + 2] + bias[c + 2];
            o.w = acc[i][j + 3] + bias[c + 3];
            *(float4*)&C[(size_t)r * N + c] = o;
        }
    }
}

// ---------------------------------------------------------------------------
// Flash-style attention. One CTA per (n, h, 32-query tile).
// 256 threads: tx (0..15) owns 4 strided cols (tx + 16j), ty (0..15) owns
// 2 query rows (2ty + i). Key tiles of 64 with online softmax.
// P (post-softmax probs) is written back into the Ks buffer to save smem.
// V is stored transposed so the PV GEMM reads float4 along k.
// ---------------------------------------------------------------------------
#define AQ 32
#define AK 64
#define APAD 68   // row stride (floats): 16B-aligned, limits conflicts to 2-way

__global__ __launch_bounds__(256) void attn_kernel()
{
    __shared__ float Qs[AQ][APAD];
    __shared__ float Ks[AK][APAD];   // also reused for P (rows 0..31)
    __shared__ float VsT[HD][APAD];  // transposed: VsT[d][k]

    const int tid = threadIdx.x;
    const int tx = tid & 15;
    const int ty = tid >> 4;
    const int qt = blockIdx.x;       // 0..63
    const int h  = blockIdx.y;       // 0..15
    const int n  = blockIdx.z;       // 0..3
    const int q0 = qt * AQ;
    const float scale = 0.125f;      // 1/sqrt(64)

    // Load Q tile, pre-scaled
#pragma unroll
    for (int i = 0; i < 2; i++) {
        int idx = tid + i * 256;     // 0..511
        int r  = idx >> 4;           // 0..31
        int dv = idx & 15;           // float4 within head dim
        float4 qv = *(const float4*)&g_q[(size_t)(n * LSEQ + q0 + r) * EMB + h * HD + dv * 4];
        Qs[r][dv * 4 + 0] = qv.x * scale;
        Qs[r][dv * 4 + 1] = qv.y * scale;
        Qs[r][dv * 4 + 2] = qv.z * scale;
        Qs[r][dv * 4 + 3] = qv.w * scale;
    }

    float o0[4] = {0.f, 0.f, 0.f, 0.f};
    float o1[4] = {0.f, 0.f, 0.f, 0.f};
    float m0 = -1e30f, m1 = -1e30f;
    float l0 = 0.f, l1 = 0.f;

    for (int kt = 0; kt < LSEQ; kt += AK) {
        // Load K tile (row-major) and V tile (transposed)
#pragma unroll
        for (int i = 0; i < 4; i++) {
            int idx = tid + i * 256;     // 0..1023
            int r  = idx >> 4;           // 0..63
            int dv = idx & 15;
            size_t base = (size_t)(n * LSEQ + kt + r) * EMB + h * HD + dv * 4;
            float4 kv4 = *(const float4*)&g_k[base];
            Ks[r][dv * 4 + 0] = kv4.x;
            Ks[r][dv * 4 + 1] = kv4.y;
            Ks[r][dv * 4 + 2] = kv4.z;
            Ks[r][dv * 4 + 3] = kv4.w;
            float4 vv = *(const float4*)&g_v[base];
            VsT[dv * 4 + 0][r] = vv.x;
            VsT[dv * 4 + 1][r] = vv.y;
            VsT[dv * 4 + 2][r] = vv.z;
            VsT[dv * 4 + 3][r] = vv.w;
        }
        __syncthreads();

        // S = Qs @ Ks^T  (per thread: 2 rows x 4 strided cols)
        float s0[4] = {0.f, 0.f, 0.f, 0.f};
        float s1[4] = {0.f, 0.f, 0.f, 0.f};
#pragma unroll
        for (int d4 = 0; d4 < HD; d4 += 4) {
            float4 qa0 = *(const float4*)&Qs[2 * ty + 0][d4];
            float4 qa1 = *(const float4*)&Qs[2 * ty + 1][d4];
#pragma unroll
            for (int j = 0; j < 4; j++) {
                float4 kb = *(const float4*)&Ks[tx + 16 * j][d4];
                s0[j] += qa0.x * kb.x + qa0.y * kb.y + qa0.z * kb.z + qa0.w * kb.w;
                s1[j] += qa1.x * kb.x + qa1.y * kb.y + qa1.z * kb.z + qa1.w * kb.w;
            }
        }

        // Online softmax (row stats shared across the 16-lane tx group)
        {
            float mm0 = fmaxf(fmaxf(s0[0], s0[1]), fmaxf(s0[2], s0[3]));
            float mm1 = fmaxf(fmaxf(s1[0], s1[1]), fmaxf(s1[2], s1[3]));
#pragma unroll
            for (int off = 8; off > 0; off >>= 1) {
                mm0 = fmaxf(mm0, __shfl_xor_sync(0xffffffffu, mm0, off));
                mm1 = fmaxf(mm1, __shfl_xor_sync(0xffffffffu, mm1, off));
            }
            float mn0 = fmaxf(m0, mm0);
            float mn1 = fmaxf(m1, mm1);
            float c0 = __expf(m0 - mn0);
            float c1 = __expf(m1 - mn1);
            float ss0 = 0.f, ss1 = 0.f;
#pragma unroll
            for (int j = 0; j < 4; j++) {
                s0[j] = __expf(s0[j] - mn0); ss0 += s0[j];
                s1[j] = __expf(s1[j] - mn1); ss1 += s1[j];
            }
#pragma unroll
            for (int off = 8; off > 0; off >>= 1) {
                ss0 += __shfl_xor_sync(0xffffffffu, ss0, off);
                ss1 += __shfl_xor_sync(0xffffffffu, ss1, off);
            }
            l0 = l0 * c0 + ss0;
            l1 = l1 * c1 + ss1;
            m0 = mn0; m1 = mn1;
#pragma unroll
            for (int j = 0; j < 4; j++) { o0[j] *= c0; o1[j] *= c1; }
        }

        __syncthreads();   // everyone done reading Ks

        // Write P into the Ks buffer (rows 0..31)
#pragma unroll
        for (int j = 0; j < 4; j++) {
            Ks[2 * ty + 0][tx + 16 * j] = s0[j];
            Ks[2 * ty + 1][tx + 16 * j] = s1[j];
        }
        __syncthreads();   // P visible

        // O += P @ V   (read V transposed: float4 along k)
#pragma unroll
        for (int k4 = 0; k4 < AK; k4 += 4) {
            float4 pa0 = *(const float4*)&Ks[2 * ty + 0][k4];
            float4 pa1 = *(const float4*)&Ks[2 * ty + 1][k4];
#pragma unroll
            for (int j = 0; j < 4; j++) {
                float4 vb = *(const float4*)&VsT[tx + 16 * j][k4];
                o0[j] += pa0.x * vb.x + pa0.y * vb.y + pa0.z * vb.z + pa0.w * vb.w;
                o1[j] += pa1.x * vb.x + pa1.y * vb.y + pa1.z * vb.z + pa1.w * vb.w;
            }
        }
        __syncthreads();   // done reading Ks/VsT, safe to overwrite next iter
    }

    // Final normalization + store
    float inv0 = 1.0f / l0;
    float inv1 = 1.0f / l1;
#pragma unroll
    for (int j = 0; j < 4; j++) {
        g_att[(size_t)(n * LSEQ + q0 + 2 * ty + 0) * EMB + h * HD + tx + 16 * j] = o0[j] * inv0;
        g_att[(size_t)(n * LSEQ + q0 + 2 * ty + 1) * EMB + h * HD + tx + 16 * j] = o1[j] * inv1;
    }
}

// ---------------------------------------------------------------------------
// Launch
// ---------------------------------------------------------------------------
extern "C" void kernel_launch(void* const* d_in, const int* in_sizes, int n_in,
                              void* d_out, int out_size)
{
    const float* Q  = (const float*)d_in[0];
    const float* K  = (const float*)d_in[1];
    const float* V  = (const float*)d_in[2];
    const float* Wq = (const float*)d_in[3];
    const float* bq = (const float*)d_in[4];
    const float* Wk = (const float*)d_in[5];
    const float* bk = (const float*)d_in[6];
    const float* Wv = (const float*)d_in[7];
    const float* bv = (const float*)d_in[8];
    const float* Wo = (const float*)d_in[9];
    const float* bo = (const float*)d_in[10];
    float* out = (float*)d_out;

    float *pq, *pk, *pv, *patt;
    cudaGetSymbolAddress((void**)&pq,   g_q);
    cudaGetSymbolAddress((void**)&pk,   g_k);
    cudaGetSymbolAddress((void**)&pv,   g_v);
    cudaGetSymbolAddress((void**)&patt, g_att);

    dim3 gg(EMB / BN, MROWS / BM);   // (8, 64)
    gemm_bias_kernel<<<gg, 256>>>(Q, Wq, bq, pq, MROWS, EMB, EMB);
    gemm_bias_kernel<<<gg, 256>>>(K, Wk, bk, pk, MROWS, EMB, EMB);
    gemm_bias_kernel<<<gg, 256>>>(V, Wv, bv, pv, MROWS, EMB, EMB);

    dim3 ga(LSEQ / AQ, NH, NB);      // (64, 16, 4)
    attn_kernel<<<ga, 256>>>();

    gemm_bias_kernel<<<gg, 256>>>(patt, Wo, bo, out, MROWS, EMB, EMB);
}

// round 3
// speedup vs baseline: 1.2271x; 1.2271x over previous
#include <cuda_runtime.h>
#include <cuda_bf16.h>
#include <cstdint>

// Problem constants
#define NB    4
#define LSEQ  2048
#define EMB   1024
#define NH    16
#define HD    64
#define MROWS (NB * LSEQ)   // 8192

// Scratch (static device arrays — no allocation allowed)
__device__ float g_q[MROWS * EMB];
__device__ float g_k[MROWS * EMB];
__device__ float g_v[MROWS * EMB];
__device__ float g_att[MROWS * EMB];
// bf16 split buffers (reused across the 4 GEMMs; stream-serialized)
__device__ __nv_bfloat16 g_ahi[MROWS * EMB];
__device__ __nv_bfloat16 g_alo[MROWS * EMB];
__device__ __nv_bfloat16 g_whi[EMB * EMB];
__device__ __nv_bfloat16 g_wlo[EMB * EMB];

// ---------------------------------------------------------------------------
// Warp-level tensor-core primitives (baseline ISA: legal on compute_103)
// ---------------------------------------------------------------------------
__device__ __forceinline__ uint32_t smem_u32(const void* p) {
    uint32_t a;
    asm("{ .reg .u64 t; cvta.to.shared.u64 t, %1; cvt.u32.u64 %0, t; }" : "=r"(a) : "l"(p));
    return a;
}

__device__ __forceinline__ void ldsm_x4(uint32_t* r, uint32_t addr) {
    asm volatile("ldmatrix.sync.aligned.m8n8.x4.shared.b16 {%0,%1,%2,%3}, [%4];"
        : "=r"(r[0]), "=r"(r[1]), "=r"(r[2]), "=r"(r[3]) : "r"(addr));
}

__device__ __forceinline__ void mma_bf16(float* d, const uint32_t* a, uint32_t b0, uint32_t b1) {
    asm volatile(
        "mma.sync.aligned.m16n8k16.row.col.f32.bf16.bf16.f32 "
        "{%0,%1,%2,%3}, {%4,%5,%6,%7}, {%8,%9}, {%0,%1,%2,%3};"
        : "+f"(d[0]), "+f"(d[1]), "+f"(d[2]), "+f"(d[3])
        : "r"(a[0]), "r"(a[1]), "r"(a[2]), "r"(a[3]), "r"(b0), "r"(b1));
}

// ---------------------------------------------------------------------------
// fp32 -> bf16 hi/lo split
// ---------------------------------------------------------------------------
__global__ __launch_bounds__(256) void split_bf16_kernel(
    const float* __restrict__ in, __nv_bfloat16* __restrict__ hi,
    __nv_bfloat16* __restrict__ lo, int n4)
{
    int i = blockIdx.x * 256 + threadIdx.x;
    if (i >= n4) return;
    float4 x = ((const float4*)in)[i];
    __nv_bfloat16 h0 = __float2bfloat16(x.x), h1 = __float2bfloat16(x.y);
    __nv_bfloat16 h2 = __float2bfloat16(x.z), h3 = __float2bfloat16(x.w);
    __nv_bfloat16 l0 = __float2bfloat16(x.x - __bfloat162float(h0));
    __nv_bfloat16 l1 = __float2bfloat16(x.y - __bfloat162float(h1));
    __nv_bfloat16 l2 = __float2bfloat16(x.z - __bfloat162float(h2));
    __nv_bfloat16 l3 = __float2bfloat16(x.w - __bfloat162float(h3));
    ((__nv_bfloat162*)hi)[i * 2 + 0] = __nv_bfloat162(h0, h1);
    ((__nv_bfloat162*)hi)[i * 2 + 1] = __nv_bfloat162(h2, h3);
    ((__nv_bfloat162*)lo)[i * 2 + 0] = __nv_bfloat162(l0, l1);
    ((__nv_bfloat162*)lo)[i * 2 + 1] = __nv_bfloat162(l2, l3);
}

// ---------------------------------------------------------------------------
// HMMA GEMM: C[M,1024] = A[M,1024] @ W[1024,1024]^T + bias
// CTA 128x128, BK=32, 8 warps in 2x4 grid, warp tile 64x32.
// 3-term bf16 split: hi*hi + hi*lo + lo*hi accumulated in fp32.
// Smem row stride 40 bf16 (80B) -> conflict-free ldmatrix.
// ---------------------------------------------------------------------------
#define BK   32
#define TSTR 40

__global__ __launch_bounds__(256) void gemm_mma_kernel(
    const __nv_bfloat16* __restrict__ Ahi, const __nv_bfloat16* __restrict__ Alo,
    const __nv_bfloat16* __restrict__ Whi, const __nv_bfloat16* __restrict__ Wlo,
    const float* __restrict__ bias, float* __restrict__ C)
{
    __shared__ __nv_bfloat16 sAhi[128 * TSTR];
    __shared__ __nv_bfloat16 sAlo[128 * TSTR];
    __shared__ __nv_bfloat16 sBhi[128 * TSTR];
    __shared__ __nv_bfloat16 sBlo[128 * TSTR];

    const int tid  = threadIdx.x;
    const int wid  = tid >> 5;
    const int lane = tid & 31;
    const int wm   = wid >> 2;          // 0..1 -> 64-row slice
    const int wn   = wid & 3;           // 0..3 -> 32-col slice
    const int row0 = blockIdx.y * 128;
    const int col0 = blockIdx.x * 128;

    const uint32_t uAhi = smem_u32(sAhi);
    const uint32_t uAlo = smem_u32(sAlo);
    const uint32_t uBhi = smem_u32(sBhi);
    const uint32_t uBlo = smem_u32(sBlo);

    // ldmatrix per-lane byte offsets (within a 16x16 tile at given base)
    // A tile: row = (lane&15), col = (lane>>4)*8
    const uint32_t aLane = (uint32_t)(((lane & 15) * TSTR + (lane >> 4) * 8) * 2);
    // B tile: row = ((lane>>4)<<3) + (lane&7), col = ((lane>>3)&1)*8
    const uint32_t bLane = (uint32_t)(((((lane >> 4) << 3) + (lane & 7)) * TSTR + ((lane >> 3) & 1) * 8) * 2);

    float acc[4][4][4];
#pragma unroll
    for (int mi = 0; mi < 4; mi++)
#pragma unroll
        for (int ni = 0; ni < 4; ni++)
#pragma unroll
            for (int r = 0; r < 4; r++) acc[mi][ni][r] = 0.0f;

    for (int kt = 0; kt < EMB; kt += BK) {
        // Load 4 tiles: 128 rows x 32 bf16 (4 int4 chunks per row) each
#pragma unroll
        for (int j = 0; j < 2; j++) {
            int idx = tid + j * 256;        // 0..511
            int r = idx >> 2;               // 0..127
            int c = idx & 3;                // int4 chunk
            int sd = r * TSTR + c * 8;      // bf16 index (16B aligned in bytes)
            size_t ga = (size_t)(row0 + r) * EMB + kt + c * 8;
            size_t gw = (size_t)(col0 + r) * EMB + kt + c * 8;
            *(int4*)&sAhi[sd] = *(const int4*)&Ahi[ga];
            *(int4*)&sAlo[sd] = *(const int4*)&Alo[ga];
            *(int4*)&sBhi[sd] = *(const int4*)&Whi[gw];
            *(int4*)&sBlo[sd] = *(const int4*)&Wlo[gw];
        }
        __syncthreads();

#pragma unroll
        for (int ks = 0; ks < 2; ks++) {
            // B fragments: 2 x ldmatrix.x4 per precision (covers n=32)
            uint32_t bh[2][4], bl[2][4];
#pragma unroll
            for (int nb = 0; nb < 2; nb++) {
                uint32_t boff = (uint32_t)(((wn * 32 + nb * 16) * TSTR + ks * 16) * 2) + bLane;
                ldsm_x4(bh[nb], uBhi + boff);
                ldsm_x4(bl[nb], uBlo + boff);
            }
#pragma unroll
            for (int mi = 0; mi < 4; mi++) {
                uint32_t aoff = (uint32_t)(((wm * 64 + mi * 16) * TSTR + ks * 16) * 2) + aLane;
                uint32_t ah[4], al[4];
                ldsm_x4(ah, uAhi + aoff);
                ldsm_x4(al, uAlo + aoff);
#pragma unroll
                for (int ni = 0; ni < 4; ni++) {
                    uint32_t b0h = bh[ni >> 1][(ni & 1) * 2];
                    uint32_t b1h = bh[ni >> 1][(ni & 1) * 2 + 1];
                    uint32_t b0l = bl[ni >> 1][(ni & 1) * 2];
                    uint32_t b1l = bl[ni >> 1][(ni & 1) * 2 + 1];
                    mma_bf16(acc[mi][ni], ah, b0h, b1h);   // hi*hi
                    mma_bf16(acc[mi][ni], ah, b0l, b1l);   // hi*lo
                    mma_bf16(acc[mi][ni], al, b0h, b1h);   // lo*hi
                }
            }
        }
        __syncthreads();
    }

    // Epilogue: bias + store (C fragment layout: rows lane/4, lane/4+8; cols 2*(lane%4))
    const int er = lane >> 2;
    const int ec = (lane & 3) * 2;
#pragma unroll
    for (int mi = 0; mi < 4; mi++) {
#pragma unroll
        for (int ni = 0; ni < 4; ni++) {
            int r = row0 + wm * 64 + mi * 16 + er;
            int c = col0 + wn * 32 + ni * 8 + ec;
            float b0 = bias[c], b1 = bias[c + 1];
            float2 v0 = make_float2(acc[mi][ni][0] + b0, acc[mi][ni][1] + b1);
            float2 v1 = make_float2(acc[mi][ni][2] + b0, acc[mi][ni][3] + b1);
            *(float2*)&C[(size_t)r * EMB + c] = v0;
            *(float2*)&C[(size_t)(r + 8) * EMB + c] = v1;
        }
    }
}

// ---------------------------------------------------------------------------
// Flash-style attention (unchanged from R1-passing version)
// ---------------------------------------------------------------------------
#define AQ 32
#define AK 64
#define APAD 68

__global__ __launch_bounds__(256) void attn_kernel()
{
    __shared__ float Qs[AQ][APAD];
    __shared__ float Ks[AK][APAD];
    __shared__ float VsT[HD][APAD];

    const int tid = threadIdx.x;
    const int tx = tid & 15;
    const int ty = tid >> 4;
    const int qt = blockIdx.x;
    const int h  = blockIdx.y;
    const int n  = blockIdx.z;
    const int q0 = qt * AQ;
    const float scale = 0.125f;

#pragma unroll
    for (int i = 0; i < 2; i++) {
        int idx = tid + i * 256;
        int r  = idx >> 4;
        int dv = idx & 15;
        float4 qv = *(const float4*)&g_q[(size_t)(n * LSEQ + q0 + r) * EMB + h * HD + dv * 4];
        Qs[r][dv * 4 + 0] = qv.x * scale;
        Qs[r][dv * 4 + 1] = qv.y * scale;
        Qs[r][dv * 4 + 2] = qv.z * scale;
        Qs[r][dv * 4 + 3] = qv.w * scale;
    }

    float o0[4] = {0.f, 0.f, 0.f, 0.f};
    float o1[4] = {0.f, 0.f, 0.f, 0.f};
    float m0 = -1e30f, m1 = -1e30f;
    float l0 = 0.f, l1 = 0.f;

    for (int kt = 0; kt < LSEQ; kt += AK) {
#pragma unroll
        for (int i = 0; i < 4; i++) {
            int idx = tid + i * 256;
            int r  = idx >> 4;
            int dv = idx & 15;
            size_t base = (size_t)(n * LSEQ + kt + r) * EMB + h * HD + dv * 4;
            float4 kv4 = *(const float4*)&g_k[base];
            Ks[r][dv * 4 + 0] = kv4.x;
            Ks[r][dv * 4 + 1] = kv4.y;
            Ks[r][dv * 4 + 2] = kv4.z;
            Ks[r][dv * 4 + 3] = kv4.w;
            float4 vv = *(const float4*)&g_v[base];
            VsT[dv * 4 + 0][r] = vv.x;
            VsT[dv * 4 + 1][r] = vv.y;
            VsT[dv * 4 + 2][r] = vv.z;
            VsT[dv * 4 + 3][r] = vv.w;
        }
        __syncthreads();

        float s0[4] = {0.f, 0.f, 0.f, 0.f};
        float s1[4] = {0.f, 0.f, 0.f, 0.f};
#pragma unroll
        for (int d4 = 0; d4 < HD; d4 += 4) {
            float4 qa0 = *(const float4*)&Qs[2 * ty + 0][d4];
            float4 qa1 = *(const float4*)&Qs[2 * ty + 1][d4];
#pragma unroll
            for (int j = 0; j < 4; j++) {
                float4 kb = *(const float4*)&Ks[tx + 16 * j][d4];
                s0[j] += qa0.x * kb.x + qa0.y * kb.y + qa0.z * kb.z + qa0.w * kb.w;
                s1[j] += qa1.x * kb.x + qa1.y * kb.y + qa1.z * kb.z + qa1.w * kb.w;
            }
        }

        {
            float mm0 = fmaxf(fmaxf(s0[0], s0[1]), fmaxf(s0[2], s0[3]));
            float mm1 = fmaxf(fmaxf(s1[0], s1[1]), fmaxf(s1[2], s1[3]));
#pragma unroll
            for (int off = 8; off > 0; off >>= 1) {
                mm0 = fmaxf(mm0, __shfl_xor_sync(0xffffffffu, mm0, off));
                mm1 = fmaxf(mm1, __shfl_xor_sync(0xffffffffu, mm1, off));
            }
            float mn0 = fmaxf(m0, mm0);
            float mn1 = fmaxf(m1, mm1);
            float c0 = __expf(m0 - mn0);
            float c1 = __expf(m1 - mn1);
            float ss0 = 0.f, ss1 = 0.f;
#pragma unroll
            for (int j = 0; j < 4; j++) {
                s0[j] = __expf(s0[j] - mn0); ss0 += s0[j];
                s1[j] = __expf(s1[j] - mn1); ss1 += s1[j];
            }
#pragma unroll
            for (int off = 8; off > 0; off >>= 1) {
                ss0 += __shfl_xor_sync(0xffffffffu, ss0, off);
                ss1 += __shfl_xor_sync(0xffffffffu, ss1, off);
            }
            l0 = l0 * c0 + ss0;
            l1 = l1 * c1 + ss1;
            m0 = mn0; m1 = mn1;
#pragma unroll
            for (int j = 0; j < 4; j++) { o0[j] *= c0; o1[j] *= c1; }
        }

        __syncthreads();

#pragma unroll
        for (int j = 0; j < 4; j++) {
            Ks[2 * ty + 0][tx + 16 * j] = s0[j];
            Ks[2 * ty + 1][tx + 16 * j] = s1[j];
        }
        __syncthreads();

#pragma unroll
        for (int k4 = 0; k4 < AK; k4 += 4) {
            float4 pa0 = *(const float4*)&Ks[2 * ty + 0][k4];
            float4 pa1 = *(const float4*)&Ks[2 * ty + 1][k4];
#pragma unroll
            for (int j = 0; j < 4; j++) {
                float4 vb = *(const float4*)&VsT[tx + 16 * j][k4];
                o0[j] += pa0.x * vb.x + pa0.y * vb.y + pa0.z * vb.z + pa0.w * vb.w;
                o1[j] += pa1.x * vb.x + pa1.y * vb.y + pa1.z * vb.z + pa1.w * vb.w;
            }
        }
        __syncthreads();
    }

    float inv0 = 1.0f / l0;
    float inv1 = 1.0f / l1;
#pragma unroll
    for (int j = 0; j < 4; j++) {
        g_att[(size_t)(n * LSEQ + q0 + 2 * ty + 0) * EMB + h * HD + tx + 16 * j] = o0[j] * inv0;
        g_att[(size_t)(n * LSEQ + q0 + 2 * ty + 1) * EMB + h * HD + tx + 16 * j] = o1[j] * inv1;
    }
}

// ---------------------------------------------------------------------------
// Launch
// ---------------------------------------------------------------------------
extern "C" void kernel_launch(void* const* d_in, const int* in_sizes, int n_in,
                              void* d_out, int out_size)
{
    const float* Q  = (const float*)d_in[0];
    const float* K  = (const float*)d_in[1];
    const float* V  = (const float*)d_in[2];
    const float* Wq = (const float*)d_in[3];
    const float* bq = (const float*)d_in[4];
    const float* Wk = (const float*)d_in[5];
    const float* bk = (const float*)d_in[6];
    const float* Wv = (const float*)d_in[7];
    const float* bv = (const float*)d_in[8];
    const float* Wo = (const float*)d_in[9];
    const float* bo = (const float*)d_in[10];
    float* out = (float*)d_out;

    float *pq, *pk, *pv, *patt;
    __nv_bfloat16 *ahi, *alo, *whi, *wlo;
    cudaGetSymbolAddress((void**)&pq,   g_q);
    cudaGetSymbolAddress((void**)&pk,   g_k);
    cudaGetSymbolAddress((void**)&pv,   g_v);
    cudaGetSymbolAddress((void**)&patt, g_att);
    cudaGetSymbolAddress((void**)&ahi,  g_ahi);
    cudaGetSymbolAddress((void**)&alo,  g_alo);
    cudaGetSymbolAddress((void**)&whi,  g_whi);
    cudaGetSymbolAddress((void**)&wlo,  g_wlo);

    const int nA4 = MROWS * EMB / 4;
    const int nW4 = EMB * EMB / 4;
    dim3 gg(EMB / 128, MROWS / 128);   // (8, 64)

    // Q projection
    split_bf16_kernel<<<(nA4 + 255) / 256, 256>>>(Q, ahi, alo, nA4);
    split_bf16_kernel<<<(nW4 + 255) / 256, 256>>>(Wq, whi, wlo, nW4);
    gemm_mma_kernel<<<gg, 256>>>(ahi, alo, whi, wlo, bq, pq);
    // K projection
    split_bf16_kernel<<<(nA4 + 255) / 256, 256>>>(K, ahi, alo, nA4);
    split_bf16_kernel<<<(nW4 + 255) / 256, 256>>>(Wk, whi, wlo, nW4);
    gemm_mma_kernel<<<gg, 256>>>(ahi, alo, whi, wlo, bk, pk);
    // V projection
    split_bf16_kernel<<<(nA4 + 255) / 256, 256>>>(V, ahi, alo, nA4);
    split_bf16_kernel<<<(nW4 + 255) / 256, 256>>>(Wv, whi, wlo, nW4);
    gemm_mma_kernel<<<gg, 256>>>(ahi, alo, whi, wlo, bv, pv);

    // Attention
    dim3 ga(LSEQ / AQ, NH, NB);
    attn_kernel<<<ga, 256>>>();

    // Output projection
    split_bf16_kernel<<<(nA4 + 255) / 256, 256>>>(patt, ahi, alo, nA4);
    split_bf16_kernel<<<(nW4 + 255) / 256, 256>>>(Wo, whi, wlo, nW4);
    gemm_mma_kernel<<<gg, 256>>>(ahi, alo, whi, wlo, bo, out);
}

// round 5
// speedup vs baseline: 2.9514x; 2.4052x over previous
#include <cuda_runtime.h>
#include <cuda_bf16.h>
#include <cstdint>

// Problem constants
#define NB    4
#define LSEQ  2048
#define EMB   1024
#define NH    16
#define HD    64
#define MROWS (NB * LSEQ)   // 8192

// Scratch (static device arrays — no allocation allowed)
__device__ __nv_bfloat16 g_qhi[MROWS * EMB];
__device__ __nv_bfloat16 g_qlo[MROWS * EMB];
__device__ __nv_bfloat16 g_khi[MROWS * EMB];
__device__ __nv_bfloat16 g_klo[MROWS * EMB];
__device__ __nv_bfloat16 g_vhi[MROWS * EMB];
__device__ __nv_bfloat16 g_vlo[MROWS * EMB];
__device__ __nv_bfloat16 g_vthi[MROWS * EMB];  // transposed: [(n*16+h)*64+d][j]
__device__ __nv_bfloat16 g_vtlo[MROWS * EMB];
__device__ __nv_bfloat16 g_ahi[MROWS * EMB];   // GEMM A-side / attn output hi
__device__ __nv_bfloat16 g_alo[MROWS * EMB];   // GEMM A-side / attn output lo
__device__ __nv_bfloat16 g_whi[EMB * EMB];
__device__ __nv_bfloat16 g_wlo[EMB * EMB];

// ---------------------------------------------------------------------------
// Warp-level tensor-core primitives (baseline ISA: legal on compute_103)
// ---------------------------------------------------------------------------
__device__ __forceinline__ uint32_t smem_u32(const void* p) {
    uint32_t a;
    asm("{ .reg .u64 t; cvta.to.shared.u64 t, %1; cvt.u32.u64 %0, t; }" : "=r"(a) : "l"(p));
    return a;
}

__device__ __forceinline__ void ldsm_x4(uint32_t* r, uint32_t addr) {
    asm volatile("ldmatrix.sync.aligned.m8n8.x4.shared.b16 {%0,%1,%2,%3}, [%4];"
        : "=r"(r[0]), "=r"(r[1]), "=r"(r[2]), "=r"(r[3]) : "r"(addr));
}

__device__ __forceinline__ void mma_bf16(float* d, const uint32_t* a, uint32_t b0, uint32_t b1) {
    asm volatile(
        "mma.sync.aligned.m16n8k16.row.col.f32.bf16.bf16.f32 "
        "{%0,%1,%2,%3}, {%4,%5,%6,%7}, {%8,%9}, {%0,%1,%2,%3};"
        : "+f"(d[0]), "+f"(d[1]), "+f"(d[2]), "+f"(d[3])
        : "r"(a[0]), "r"(a[1]), "r"(a[2]), "r"(a[3]), "r"(b0), "r"(b1));
}

__device__ __forceinline__ uint32_t pack_bf16x2(float lo, float hi) {
    __nv_bfloat162 p = __float22bfloat162_rn(make_float2(lo, hi));
    return *(uint32_t*)&p;
}

// ---------------------------------------------------------------------------
// fp32 -> bf16 hi/lo split
// ---------------------------------------------------------------------------
__global__ __launch_bounds__(256) void split_bf16_kernel(
    const float* __restrict__ in, __nv_bfloat16* __restrict__ hi,
    __nv_bfloat16* __restrict__ lo, int n4)
{
    int i = blockIdx.x * 256 + threadIdx.x;
    if (i >= n4) return;
    float4 x = ((const float4*)in)[i];
    __nv_bfloat16 h0 = __float2bfloat16(x.x), h1 = __float2bfloat16(x.y);
    __nv_bfloat16 h2 = __float2bfloat16(x.z), h3 = __float2bfloat16(x.w);
    __nv_bfloat16 l0 = __float2bfloat16(x.x - __bfloat162float(h0));
    __nv_bfloat16 l1 = __float2bfloat16(x.y - __bfloat162float(h1));
    __nv_bfloat16 l2 = __float2bfloat16(x.z - __bfloat162float(h2));
    __nv_bfloat16 l3 = __float2bfloat16(x.w - __bfloat162float(h3));
    ((__nv_bfloat162*)hi)[i * 2 + 0] = __nv_bfloat162(h0, h1);
    ((__nv_bfloat162*)hi)[i * 2 + 1] = __nv_bfloat162(h2, h3);
    ((__nv_bfloat162*)lo)[i * 2 + 0] = __nv_bfloat162(l0, l1);
    ((__nv_bfloat162*)lo)[i * 2 + 1] = __nv_bfloat162(l2, l3);
}

// ---------------------------------------------------------------------------
// HMMA GEMM: C = A @ W^T + bias, 3-term bf16 split.
// OM=0: fp32 single output. OM=2: bf16 hi/lo split pair output.
// ---------------------------------------------------------------------------
#define BK   32
#define TSTR 40

template <int OM>
__global__ __launch_bounds__(256) void gemm_mma_kernel(
    const __nv_bfloat16* __restrict__ Ahi, const __nv_bfloat16* __restrict__ Alo,
    const __nv_bfloat16* __restrict__ Whi, const __nv_bfloat16* __restrict__ Wlo,
    const float* __restrict__ bias, void* __restrict__ Cout, void* __restrict__ Cout2)
{
    __shared__ __nv_bfloat16 sAhi[128 * TSTR];
    __shared__ __nv_bfloat16 sAlo[128 * TSTR];
    __shared__ __nv_bfloat16 sBhi[128 * TSTR];
    __shared__ __nv_bfloat16 sBlo[128 * TSTR];

    const int tid  = threadIdx.x;
    const int wid  = tid >> 5;
    const int lane = tid & 31;
    const int wm   = wid >> 2;
    const int wn   = wid & 3;
    const int row0 = blockIdx.y * 128;
    const int col0 = blockIdx.x * 128;

    const uint32_t uAhi = smem_u32(sAhi);
    const uint32_t uAlo = smem_u32(sAlo);
    const uint32_t uBhi = smem_u32(sBhi);
    const uint32_t uBlo = smem_u32(sBlo);

    const uint32_t aLane = (uint32_t)(((lane & 15) * TSTR + (lane >> 4) * 8) * 2);
    const uint32_t bLane = (uint32_t)(((((lane >> 4) << 3) + (lane & 7)) * TSTR + ((lane >> 3) & 1) * 8) * 2);

    float acc[4][4][4];
#pragma unroll
    for (int mi = 0; mi < 4; mi++)
#pragma unroll
        for (int ni = 0; ni < 4; ni++)
#pragma unroll
            for (int r = 0; r < 4; r++) acc[mi][ni][r] = 0.0f;

    for (int kt = 0; kt < EMB; kt += BK) {
#pragma unroll
        for (int j = 0; j < 2; j++) {
            int idx = tid + j * 256;
            int r = idx >> 2;
            int c = idx & 3;
            int sd = r * TSTR + c * 8;
            size_t ga = (size_t)(row0 + r) * EMB + kt + c * 8;
            size_t gw = (size_t)(col0 + r) * EMB + kt + c * 8;
            *(int4*)&sAhi[sd] = *(const int4*)&Ahi[ga];
            *(int4*)&sAlo[sd] = *(const int4*)&Alo[ga];
            *(int4*)&sBhi[sd] = *(const int4*)&Whi[gw];
            *(int4*)&sBlo[sd] = *(const int4*)&Wlo[gw];
        }
        __syncthreads();

#pragma unroll
        for (int ks = 0; ks < 2; ks++) {
            uint32_t bh[2][4], bl[2][4];
#pragma unroll
            for (int nb = 0; nb < 2; nb++) {
                uint32_t boff = (uint32_t)(((wn * 32 + nb * 16) * TSTR + ks * 16) * 2) + bLane;
                ldsm_x4(bh[nb], uBhi + boff);
                ldsm_x4(bl[nb], uBlo + boff);
            }
#pragma unroll
            for (int mi = 0; mi < 4; mi++) {
                uint32_t aoff = (uint32_t)(((wm * 64 + mi * 16) * TSTR + ks * 16) * 2) + aLane;
                uint32_t ah[4], al[4];
                ldsm_x4(ah, uAhi + aoff);
                ldsm_x4(al, uAlo + aoff);
#pragma unroll
                for (int ni = 0; ni < 4; ni++) {
                    uint32_t b0h = bh[ni >> 1][(ni & 1) * 2];
                    uint32_t b1h = bh[ni >> 1][(ni & 1) * 2 + 1];
                    uint32_t b0l = bl[ni >> 1][(ni & 1) * 2];
                    uint32_t b1l = bl[ni >> 1][(ni & 1) * 2 + 1];
                    mma_bf16(acc[mi][ni], ah, b0h, b1h);
                    mma_bf16(acc[mi][ni], ah, b0l, b1l);
                    mma_bf16(acc[mi][ni], al, b0h, b1h);
                }
            }
        }
        __syncthreads();
    }

    const int er = lane >> 2;
    const int ec = (lane & 3) * 2;
#pragma unroll
    for (int mi = 0; mi < 4; mi++) {
#pragma unroll
        for (int ni = 0; ni < 4; ni++) {
            int r = row0 + wm * 64 + mi * 16 + er;
            int c = col0 + wn * 32 + ni * 8 + ec;
            float b0 = bias[c], b1 = bias[c + 1];
            float v00 = acc[mi][ni][0] + b0, v01 = acc[mi][ni][1] + b1;
            float v10 = acc[mi][ni][2] + b0, v11 = acc[mi][ni][3] + b1;
            if (OM == 0) {
                float* C = (float*)Cout;
                *(float2*)&C[(size_t)r * EMB + c] = make_float2(v00, v01);
                *(float2*)&C[(size_t)(r + 8) * EMB + c] = make_float2(v10, v11);
            } else {
                __nv_bfloat16* Ch = (__nv_bfloat16*)Cout;
                __nv_bfloat16* Cl = (__nv_bfloat16*)Cout2;
                float h00 = __bfloat162float(__float2bfloat16(v00));
                float h01 = __bfloat162float(__float2bfloat16(v01));
                float h10 = __bfloat162float(__float2bfloat16(v10));
                float h11 = __bfloat162float(__float2bfloat16(v11));
                *(uint32_t*)&Ch[(size_t)r * EMB + c]       = pack_bf16x2(h00, h01);
                *(uint32_t*)&Ch[(size_t)(r + 8) * EMB + c] = pack_bf16x2(h10, h11);
                *(uint32_t*)&Cl[(size_t)r * EMB + c]       = pack_bf16x2(v00 - h00, v01 - h01);
                *(uint32_t*)&Cl[(size_t)(r + 8) * EMB + c] = pack_bf16x2(v10 - h10, v11 - h11);
            }
        }
    }
}

// ---------------------------------------------------------------------------
// V transpose (hi+lo): [n*2048+j][h*64+d] -> [(n*16+h)*64+d][j]
// ---------------------------------------------------------------------------
__global__ __launch_bounds__(256) void vt_kernel(
    const __nv_bfloat16* __restrict__ vhi, const __nv_bfloat16* __restrict__ vlo,
    __nv_bfloat16* __restrict__ vthi, __nv_bfloat16* __restrict__ vtlo)
{
    __shared__ __nv_bfloat16 th[32][33];
    __shared__ __nv_bfloat16 tl[32][33];
    const int tx = threadIdx.x & 31;
    const int ty = threadIdx.x >> 5;
    const int j0 = blockIdx.x * 32;
    const int d0 = blockIdx.y * 32;
    const int nh = blockIdx.z;
    const int n  = nh >> 4;
    const int h  = nh & 15;

#pragma unroll
    for (int k = 0; k < 4; k++) {
        int j = j0 + ty + 8 * k;
        size_t src = (size_t)(n * LSEQ + j) * EMB + h * HD + d0 + tx;
        th[ty + 8 * k][tx] = vhi[src];
        tl[ty + 8 * k][tx] = vlo[src];
    }
    __syncthreads();
#pragma unroll
    for (int k = 0; k < 4; k++) {
        int d = d0 + ty + 8 * k;
        size_t dst = (size_t)(nh * HD + d) * LSEQ + j0 + tx;
        vthi[dst] = th[tx][ty + 8 * k];
        vtlo[dst] = tl[tx][ty + 8 * k];
    }
}

// ---------------------------------------------------------------------------
// Tensor-core flash attention, full 3-term bf16 split on QK and PV.
// CTA: (q-tile 128, h, n). 8 warps x 16 q rows. Key tiles of 64.
// One 36.9KB smem buffer: phase 1 = Qhi/Qlo (frags hoisted), then K/V tiles.
// ---------------------------------------------------------------------------
#define ATSTR 72

__global__ __launch_bounds__(256, 1) void attn_mma_kernel()
{
    __shared__ __nv_bfloat16 sbuf[256 * ATSTR];   // 36864 B

    const int tid  = threadIdx.x;
    const int wid  = tid >> 5;
    const int lane = tid & 31;
    const int q0 = blockIdx.x * 128;
    const int h  = blockIdx.y;
    const int n  = blockIdx.z;

    const uint32_t uS = smem_u32(sbuf);
    const uint32_t aLane = (uint32_t)(((lane & 15) * ATSTR + (lane >> 4) * 8) * 2);
    const uint32_t bLane = (uint32_t)(((((lane >> 4) << 3) + (lane & 7)) * ATSTR + ((lane >> 3) & 1) * 8) * 2);

    // Phase 1: load Qhi (rows 0..127) and Qlo (rows 128..255), scaled by 1/8 (exact)
    const __nv_bfloat162 sc2 = __float2bfloat162_rn(0.125f);
#pragma unroll
    for (int i = 0; i < 4; i++) {
        int idx = tid + i * 256;           // 0..1023
        int r = idx >> 3;                  // 0..127
        int c = idx & 7;
        size_t src = (size_t)(n * LSEQ + q0 + r) * EMB + h * HD + c * 8;
        int4 vh = *(const int4*)&g_qhi[src];
        int4 vl = *(const int4*)&g_qlo[src];
        __nv_bfloat162* ph = (__nv_bfloat162*)&vh;
        __nv_bfloat162* pl = (__nv_bfloat162*)&vl;
#pragma unroll
        for (int z = 0; z < 4; z++) { ph[z] = __hmul2(ph[z], sc2); pl[z] = __hmul2(pl[z], sc2); }
        *(int4*)&sbuf[r * ATSTR + c * 8] = vh;
        *(int4*)&sbuf[(128 + r) * ATSTR + c * 8] = vl;
    }
    __syncthreads();

    uint32_t qh[4][4], ql[4][4];
#pragma unroll
    for (int kk = 0; kk < 4; kk++) {
        ldsm_x4(qh[kk], uS + (uint32_t)((wid * 16 * ATSTR + kk * 16) * 2) + aLane);
        ldsm_x4(ql[kk], uS + (uint32_t)(((128 + wid * 16) * ATSTR + kk * 16) * 2) + aLane);
    }
    __syncthreads();   // Q frags in regs; sbuf reusable

    // K/V tile bases within sbuf (each 64*ATSTR bf16)
    const uint32_t oKh = 0;
    const uint32_t oKl = (uint32_t)(64 * ATSTR * 2);
    const uint32_t oVh = (uint32_t)(128 * ATSTR * 2);
    const uint32_t oVl = (uint32_t)(192 * ATSTR * 2);

    float oo[8][4];
#pragma unroll
    for (int ni = 0; ni < 8; ni++)
#pragma unroll
        for (int r = 0; r < 4; r++) oo[ni][r] = 0.0f;
    float m0 = -1e30f, m1 = -1e30f, l0 = 0.0f, l1 = 0.0f;

    for (int kt = 0; kt < LSEQ; kt += 64) {
        // Load K(hi,lo) row-major and V(hi,lo) transposed [d][j]
#pragma unroll
        for (int i = 0; i < 2; i++) {
            int idx = tid + i * 256;       // 0..511
            int r = idx >> 3;              // 0..63
            int c = idx & 7;
            int sd = r * ATSTR + c * 8;
            size_t kb = (size_t)(n * LSEQ + kt + r) * EMB + h * HD + c * 8;
            size_t vb = (size_t)((n * NH + h) * HD + r) * LSEQ + kt + c * 8;
            *(int4*)&sbuf[sd]               = *(const int4*)&g_khi[kb];
            *(int4*)&sbuf[64 * ATSTR + sd]  = *(const int4*)&g_klo[kb];
            *(int4*)&sbuf[128 * ATSTR + sd] = *(const int4*)&g_vthi[vb];
            *(int4*)&sbuf[192 * ATSTR + sd] = *(const int4*)&g_vtlo[vb];
        }
        __syncthreads();

        // S = Q @ K^T (3-term split)
        float sS[8][4];
#pragma unroll
        for (int ni = 0; ni < 8; ni++)
#pragma unroll
            for (int r = 0; r < 4; r++) sS[ni][r] = 0.0f;
#pragma unroll
        for (int nb = 0; nb < 4; nb++) {
            uint32_t kh[4][4], kl[4][4];
#pragma unroll
            for (int kk = 0; kk < 4; kk++) {
                uint32_t off = (uint32_t)((nb * 16 * ATSTR + kk * 16) * 2) + bLane;
                ldsm_x4(kh[kk], uS + oKh + off);
                ldsm_x4(kl[kk], uS + oKl + off);
            }
#pragma unroll
            for (int kk = 0; kk < 4; kk++)
#pragma unroll
                for (int i = 0; i < 2; i++) {
                    mma_bf16(sS[nb * 2 + i], qh[kk], kh[kk][i * 2], kh[kk][i * 2 + 1]);
                    mma_bf16(sS[nb * 2 + i], qh[kk], kl[kk][i * 2], kl[kk][i * 2 + 1]);
                    mma_bf16(sS[nb * 2 + i], ql[kk], kh[kk][i * 2], kh[kk][i * 2 + 1]);
                }
        }

        // Online softmax (rows lane>>2 and +8; quad reduce)
        float mt0 = -1e30f, mt1 = -1e30f;
#pragma unroll
        for (int ni = 0; ni < 8; ni++) {
            mt0 = fmaxf(mt0, fmaxf(sS[ni][0], sS[ni][1]));
            mt1 = fmaxf(mt1, fmaxf(sS[ni][2], sS[ni][3]));
        }
#pragma unroll
        for (int off = 1; off <= 2; off <<= 1) {
            mt0 = fmaxf(mt0, __shfl_xor_sync(0xffffffffu, mt0, off));
            mt1 = fmaxf(mt1, __shfl_xor_sync(0xffffffffu, mt1, off));
        }
        float mn0 = fmaxf(m0, mt0), mn1 = fmaxf(m1, mt1);
        float c0 = __expf(m0 - mn0), c1 = __expf(m1 - mn1);

        uint32_t pfh[4][4], pfl[4][4];
        float s0 = 0.0f, s1 = 0.0f;
#pragma unroll
        for (int ni = 0; ni < 8; ni++) {
            float p0 = __expf(sS[ni][0] - mn0);
            float p1 = __expf(sS[ni][1] - mn0);
            float p2 = __expf(sS[ni][2] - mn1);
            float p3 = __expf(sS[ni][3] - mn1);
            s0 += p0 + p1; s1 += p2 + p3;
            float h0 = __bfloat162float(__float2bfloat16(p0));
            float h1 = __bfloat162float(__float2bfloat16(p1));
            float h2 = __bfloat162float(__float2bfloat16(p2));
            float h3 = __bfloat162float(__float2bfloat16(p3));
            pfh[ni >> 1][(ni & 1) * 2 + 0] = pack_bf16x2(h0, h1);
            pfh[ni >> 1][(ni & 1) * 2 + 1] = pack_bf16x2(h2, h3);
            pfl[ni >> 1][(ni & 1) * 2 + 0] = pack_bf16x2(p0 - h0, p1 - h1);
            pfl[ni >> 1][(ni & 1) * 2 + 1] = pack_bf16x2(p2 - h2, p3 - h3);
        }
#pragma unroll
        for (int off = 1; off <= 2; off <<= 1) {
            s0 += __shfl_xor_sync(0xffffffffu, s0, off);
            s1 += __shfl_xor_sync(0xffffffffu, s1, off);
        }
        l0 = l0 * c0 + s0;
        l1 = l1 * c1 + s1;
        m0 = mn0; m1 = mn1;
#pragma unroll
        for (int ni = 0; ni < 8; ni++) {
            oo[ni][0] *= c0; oo[ni][1] *= c0;
            oo[ni][2] *= c1; oo[ni][3] *= c1;
        }

        // O += P @ V (3-term split)
#pragma unroll
        for (int nbd = 0; nbd < 4; nbd++) {
            uint32_t vh[4][4], vl[4][4];
#pragma unroll
            for (int kk = 0; kk < 4; kk++) {
                uint32_t off = (uint32_t)((nbd * 16 * ATSTR + kk * 16) * 2) + bLane;
                ldsm_x4(vh[kk], uS + oVh + off);
                ldsm_x4(vl[kk], uS + oVl + off);
            }
#pragma unroll
            for (int kk = 0; kk < 4; kk++)
#pragma unroll
                for (int i = 0; i < 2; i++) {
                    mma_bf16(oo[nbd * 2 + i], pfh[kk], vh[kk][i * 2], vh[kk][i * 2 + 1]);
                    mma_bf16(oo[nbd * 2 + i], pfh[kk], vl[kk][i * 2], vl[kk][i * 2 + 1]);
                    mma_bf16(oo[nbd * 2 + i], pfl[kk], vh[kk][i * 2], vh[kk][i * 2 + 1]);
                }
        }
        __syncthreads();
    }

    // Epilogue: normalize, split hi/lo, store for output projection
    float inv0 = 1.0f / l0, inv1 = 1.0f / l1;
    const int er = lane >> 2;
    const int ec = (lane & 3) * 2;
#pragma unroll
    for (int ni = 0; ni < 8; ni++) {
        int r = n * LSEQ + q0 + wid * 16 + er;
        int c = h * HD + ni * 8 + ec;
        float v00 = oo[ni][0] * inv0, v01 = oo[ni][1] * inv0;
        float v10 = oo[ni][2] * inv1, v11 = oo[ni][3] * inv1;
        float h00 = __bfloat162float(__float2bfloat16(v00));
        float h01 = __bfloat162float(__float2bfloat16(v01));
        float h10 = __bfloat162float(__float2bfloat16(v10));
        float h11 = __bfloat162float(__float2bfloat16(v11));
        *(uint32_t*)&g_ahi[(size_t)r * EMB + c]       = pack_bf16x2(h00, h01);
        *(uint32_t*)&g_ahi[(size_t)(r + 8) * EMB + c] = pack_bf16x2(h10, h11);
        *(uint32_t*)&g_alo[(size_t)r * EMB + c]       = pack_bf16x2(v00 - h00, v01 - h01);
        *(uint32_t*)&g_alo[(size_t)(r + 8) * EMB + c] = pack_bf16x2(v10 - h10, v11 - h11);
    }
}

// ---------------------------------------------------------------------------
// Launch
// ---------------------------------------------------------------------------
extern "C" void kernel_launch(void* const* d_in, const int* in_sizes, int n_in,
                              void* d_out, int out_size)
{
    const float* Q  = (const float*)d_in[0];
    const float* K  = (const float*)d_in[1];
    const float* V  = (const float*)d_in[2];
    const float* Wq = (const float*)d_in[3];
    const float* bq = (const float*)d_in[4];
    const float* Wk = (const float*)d_in[5];
    const float* bk = (const float*)d_in[6];
    const float* Wv = (const float*)d_in[7];
    const float* bv = (const float*)d_in[8];
    const float* Wo = (const float*)d_in[9];
    const float* bo = (const float*)d_in[10];
    float* out = (float*)d_out;

    __nv_bfloat16 *qhi, *qlo, *khi, *klo, *vhi, *vlo, *vthi, *vtlo, *ahi, *alo, *whi, *wlo;
    cudaGetSymbolAddress((void**)&qhi,  g_qhi);
    cudaGetSymbolAddress((void**)&qlo,  g_qlo);
    cudaGetSymbolAddress((void**)&khi,  g_khi);
    cudaGetSymbolAddress((void**)&klo,  g_klo);
    cudaGetSymbolAddress((void**)&vhi,  g_vhi);
    cudaGetSymbolAddress((void**)&vlo,  g_vlo);
    cudaGetSymbolAddress((void**)&vthi, g_vthi);
    cudaGetSymbolAddress((void**)&vtlo, g_vtlo);
    cudaGetSymbolAddress((void**)&ahi,  g_ahi);
    cudaGetSymbolAddress((void**)&alo,  g_alo);
    cudaGetSymbolAddress((void**)&whi,  g_whi);
    cudaGetSymbolAddress((void**)&wlo,  g_wlo);

    const int nA4 = MROWS * EMB / 4;
    const int nW4 = EMB * EMB / 4;
    dim3 gg(EMB / 128, MROWS / 128);   // (8, 64)

    // Q projection -> split bf16
    split_bf16_kernel<<<(nA4 + 255) / 256, 256>>>(Q, ahi, alo, nA4);
    split_bf16_kernel<<<(nW4 + 255) / 256, 256>>>(Wq, whi, wlo, nW4);
    gemm_mma_kernel<2><<<gg, 256>>>(ahi, alo, whi, wlo, bq, qhi, qlo);
    // K projection -> split bf16
    split_bf16_kernel<<<(nA4 + 255) / 256, 256>>>(K, ahi, alo, nA4);
    split_bf16_kernel<<<(nW4 + 255) / 256, 256>>>(Wk, whi, wlo, nW4);
    gemm_mma_kernel<2><<<gg, 256>>>(ahi, alo, whi, wlo, bk, khi, klo);
    // V projection -> split bf16, then transpose both
    split_bf16_kernel<<<(nA4 + 255) / 256, 256>>>(V, ahi, alo, nA4);
    split_bf16_kernel<<<(nW4 + 255) / 256, 256>>>(Wv, whi, wlo, nW4);
    gemm_mma_kernel<2><<<gg, 256>>>(ahi, alo, whi, wlo, bv, vhi, vlo);
    vt_kernel<<<dim3(LSEQ / 32, HD / 32, NB * NH), 256>>>(vhi, vlo, vthi, vtlo);

    // Full-split tensor-core attention (writes g_ahi/g_alo)
    attn_mma_kernel<<<dim3(LSEQ / 128, NH, NB), 256>>>();

    // Output projection (fp32 out)
    split_bf16_kernel<<<(nW4 + 255) / 256, 256>>>(Wo, whi, wlo, nW4);
    gemm_mma_kernel<0><<<gg, 256>>>(ahi, alo, whi, wlo, bo, out, nullptr);
}

// round 6
// speedup vs baseline: 3.7286x; 1.2633x over previous
#include <cuda_runtime.h>
#include <cuda_bf16.h>
#include <cstdint>

// Problem constants
#define NB    4
#define LSEQ  2048
#define EMB   1024
#define NH    16
#define HD    64
#define MROWS (NB * LSEQ)   // 8192

// Scratch (static device arrays — no allocation allowed)
__device__ __nv_bfloat16 g_qhi[MROWS * EMB];
__device__ __nv_bfloat16 g_qlo[MROWS * EMB];
__device__ __nv_bfloat16 g_khi[MROWS * EMB];
__device__ __nv_bfloat16 g_klo[MROWS * EMB];
__device__ __nv_bfloat16 g_vhi[MROWS * EMB];
__device__ __nv_bfloat16 g_vlo[MROWS * EMB];
__device__ __nv_bfloat16 g_vthi[MROWS * EMB];  // transposed: [(n*16+h)*64+d][j]
__device__ __nv_bfloat16 g_vtlo[MROWS * EMB];
__device__ __nv_bfloat16 g_ahi[MROWS * EMB];   // GEMM A-side / attn output hi
__device__ __nv_bfloat16 g_alo[MROWS * EMB];   // GEMM A-side / attn output lo
__device__ __nv_bfloat16 g_whi[EMB * EMB];
__device__ __nv_bfloat16 g_wlo[EMB * EMB];

// ---------------------------------------------------------------------------
// Warp-level tensor-core + async-copy primitives (baseline ISA on compute_103)
// ---------------------------------------------------------------------------
__device__ __forceinline__ uint32_t smem_u32(const void* p) {
    uint32_t a;
    asm("{ .reg .u64 t; cvta.to.shared.u64 t, %1; cvt.u32.u64 %0, t; }" : "=r"(a) : "l"(p));
    return a;
}

__device__ __forceinline__ void ldsm_x4(uint32_t* r, uint32_t addr) {
    asm volatile("ldmatrix.sync.aligned.m8n8.x4.shared.b16 {%0,%1,%2,%3}, [%4];"
        : "=r"(r[0]), "=r"(r[1]), "=r"(r[2]), "=r"(r[3]) : "r"(addr));
}

__device__ __forceinline__ void mma_bf16(float* d, const uint32_t* a, uint32_t b0, uint32_t b1) {
    asm volatile(
        "mma.sync.aligned.m16n8k16.row.col.f32.bf16.bf16.f32 "
        "{%0,%1,%2,%3}, {%4,%5,%6,%7}, {%8,%9}, {%0,%1,%2,%3};"
        : "+f"(d[0]), "+f"(d[1]), "+f"(d[2]), "+f"(d[3])
        : "r"(a[0]), "r"(a[1]), "r"(a[2]), "r"(a[3]), "r"(b0), "r"(b1));
}

__device__ __forceinline__ uint32_t pack_bf16x2(float lo, float hi) {
    __nv_bfloat162 p = __float22bfloat162_rn(make_float2(lo, hi));
    return *(uint32_t*)&p;
}

__device__ __forceinline__ void cp_async16(uint32_t saddr, const void* g) {
    asm volatile("cp.async.cg.shared.global [%0], [%1], 16;" :: "r"(saddr), "l"(g));
}
#define CP_COMMIT() asm volatile("cp.async.commit_group;")
#define CP_WAIT1()  asm volatile("cp.async.wait_group 1;")

// ---------------------------------------------------------------------------
// fp32 -> bf16 hi/lo split
// ---------------------------------------------------------------------------
__global__ __launch_bounds__(256) void split_bf16_kernel(
    const float* __restrict__ in, __nv_bfloat16* __restrict__ hi,
    __nv_bfloat16* __restrict__ lo, int n4)
{
    int i = blockIdx.x * 256 + threadIdx.x;
    if (i >= n4) return;
    float4 x = ((const float4*)in)[i];
    __nv_bfloat16 h0 = __float2bfloat16(x.x), h1 = __float2bfloat16(x.y);
    __nv_bfloat16 h2 = __float2bfloat16(x.z), h3 = __float2bfloat16(x.w);
    __nv_bfloat16 l0 = __float2bfloat16(x.x - __bfloat162float(h0));
    __nv_bfloat16 l1 = __float2bfloat16(x.y - __bfloat162float(h1));
    __nv_bfloat16 l2 = __float2bfloat16(x.z - __bfloat162float(h2));
    __nv_bfloat16 l3 = __float2bfloat16(x.w - __bfloat162float(h3));
    ((__nv_bfloat162*)hi)[i * 2 + 0] = __nv_bfloat162(h0, h1);
    ((__nv_bfloat162*)hi)[i * 2 + 1] = __nv_bfloat162(h2, h3);
    ((__nv_bfloat162*)lo)[i * 2 + 0] = __nv_bfloat162(l0, l1);
    ((__nv_bfloat162*)lo)[i * 2 + 1] = __nv_bfloat162(l2, l3);
}

// ---------------------------------------------------------------------------
// HMMA GEMM: C = A @ W^T + bias, 3-term bf16 split, cp.async double-buffered.
// OM=0: fp32 single output. OM=2: bf16 hi/lo split pair output.
// Dynamic smem: 2 stages x 4 tiles x (128 x TSTR) bf16 = 81920 B.
// ---------------------------------------------------------------------------
#define BK    32
#define TSTR  40
#define GTILE (128 * TSTR)           // bf16 per tile buffer
#define GSTAGE_B (4 * GTILE * 2)     // bytes per stage
#define GSMEM (2 * GSTAGE_B)         // 81920

template <int OM>
__global__ __launch_bounds__(256) void gemm_mma_kernel(
    const __nv_bfloat16* __restrict__ Ahi, const __nv_bfloat16* __restrict__ Alo,
    const __nv_bfloat16* __restrict__ Whi, const __nv_bfloat16* __restrict__ Wlo,
    const float* __restrict__ bias, void* __restrict__ Cout, void* __restrict__ Cout2)
{
    extern __shared__ __align__(16) __nv_bfloat16 dsm[];

    const int tid  = threadIdx.x;
    const int wid  = tid >> 5;
    const int lane = tid & 31;
    const int wm   = wid >> 2;
    const int wn   = wid & 3;
    const int row0 = blockIdx.y * 128;
    const int col0 = blockIdx.x * 128;

    const uint32_t uS = smem_u32(dsm);
    const uint32_t aLane = (uint32_t)(((lane & 15) * TSTR + (lane >> 4) * 8) * 2);
    const uint32_t bLane = (uint32_t)(((((lane >> 4) << 3) + (lane & 7)) * TSTR + ((lane >> 3) & 1) * 8) * 2);

    // Per-thread load coordinates (2 chunks per tile buffer)
    const int lr0 = tid >> 2,         lc0 = tid & 3;
    const int lr1 = (tid + 256) >> 2, lc1 = (tid + 256) & 3;
    const uint32_t sd0 = (uint32_t)((lr0 * TSTR + lc0 * 8) * 2);
    const uint32_t sd1 = (uint32_t)((lr1 * TSTR + lc1 * 8) * 2);

    auto load_stage = [&](int s, int kt) {
        uint32_t base = uS + (uint32_t)(s * GSTAGE_B);
        size_t ga0 = (size_t)(row0 + lr0) * EMB + kt + lc0 * 8;
        size_t gw0 = (size_t)(col0 + lr0) * EMB + kt + lc0 * 8;
        size_t ga1 = (size_t)(row0 + lr1) * EMB + kt + lc1 * 8;
        size_t gw1 = (size_t)(col0 + lr1) * EMB + kt + lc1 * 8;
        cp_async16(base + sd0,                 &Ahi[ga0]);
        cp_async16(base + GTILE * 2 + sd0,     &Alo[ga0]);
        cp_async16(base + 2 * GTILE * 2 + sd0, &Whi[gw0]);
        cp_async16(base + 3 * GTILE * 2 + sd0, &Wlo[gw0]);
        cp_async16(base + sd1,                 &Ahi[ga1]);
        cp_async16(base + GTILE * 2 + sd1,     &Alo[ga1]);
        cp_async16(base + 2 * GTILE * 2 + sd1, &Whi[gw1]);
        cp_async16(base + 3 * GTILE * 2 + sd1, &Wlo[gw1]);
    };

    float acc[4][4][4];
#pragma unroll
    for (int mi = 0; mi < 4; mi++)
#pragma unroll
        for (int ni = 0; ni < 4; ni++)
#pragma unroll
            for (int r = 0; r < 4; r++) acc[mi][ni][r] = 0.0f;

    load_stage(0, 0);
    CP_COMMIT();

    for (int t = 0; t < EMB / BK; t++) {
        if (t + 1 < EMB / BK) load_stage((t + 1) & 1, (t + 1) * BK);
        CP_COMMIT();
        CP_WAIT1();
        __syncthreads();

        const uint32_t uAhi = uS + (uint32_t)((t & 1) * GSTAGE_B);
        const uint32_t uAlo = uAhi + GTILE * 2;
        const uint32_t uBhi = uAhi + 2 * GTILE * 2;
        const uint32_t uBlo = uAhi + 3 * GTILE * 2;

#pragma unroll
        for (int ks = 0; ks < 2; ks++) {
            uint32_t bh[2][4], bl[2][4];
#pragma unroll
            for (int nb = 0; nb < 2; nb++) {
                uint32_t boff = (uint32_t)(((wn * 32 + nb * 16) * TSTR + ks * 16) * 2) + bLane;
                ldsm_x4(bh[nb], uBhi + boff);
                ldsm_x4(bl[nb], uBlo + boff);
            }
#pragma unroll
            for (int mi = 0; mi < 4; mi++) {
                uint32_t aoff = (uint32_t)(((wm * 64 + mi * 16) * TSTR + ks * 16) * 2) + aLane;
                uint32_t ah[4], al[4];
                ldsm_x4(ah, uAhi + aoff);
                ldsm_x4(al, uAlo + aoff);
#pragma unroll
                for (int ni = 0; ni < 4; ni++) {
                    uint32_t b0h = bh[ni >> 1][(ni & 1) * 2];
                    uint32_t b1h = bh[ni >> 1][(ni & 1) * 2 + 1];
                    uint32_t b0l = bl[ni >> 1][(ni & 1) * 2];
                    uint32_t b1l = bl[ni >> 1][(ni & 1) * 2 + 1];
                    mma_bf16(acc[mi][ni], ah, b0h, b1h);
                    mma_bf16(acc[mi][ni], ah, b0l, b1l);
                    mma_bf16(acc[mi][ni], al, b0h, b1h);
                }
            }
        }
        __syncthreads();
    }

    const int er = lane >> 2;
    const int ec = (lane & 3) * 2;
#pragma unroll
    for (int mi = 0; mi < 4; mi++) {
#pragma unroll
        for (int ni = 0; ni < 4; ni++) {
            int r = row0 + wm * 64 + mi * 16 + er;
            int c = col0 + wn * 32 + ni * 8 + ec;
            float b0 = bias[c], b1 = bias[c + 1];
            float v00 = acc[mi][ni][0] + b0, v01 = acc[mi][ni][1] + b1;
            float v10 = acc[mi][ni][2] + b0, v11 = acc[mi][ni][3] + b1;
            if (OM == 0) {
                float* C = (float*)Cout;
                *(float2*)&C[(size_t)r * EMB + c] = make_float2(v00, v01);
                *(float2*)&C[(size_t)(r + 8) * EMB + c] = make_float2(v10, v11);
            } else {
                __nv_bfloat16* Ch = (__nv_bfloat16*)Cout;
                __nv_bfloat16* Cl = (__nv_bfloat16*)Cout2;
                float h00 = __bfloat162float(__float2bfloat16(v00));
                float h01 = __bfloat162float(__float2bfloat16(v01));
                float h10 = __bfloat162float(__float2bfloat16(v10));
                float h11 = __bfloat162float(__float2bfloat16(v11));
                *(uint32_t*)&Ch[(size_t)r * EMB + c]       = pack_bf16x2(h00, h01);
                *(uint32_t*)&Ch[(size_t)(r + 8) * EMB + c] = pack_bf16x2(h10, h11);
                *(uint32_t*)&Cl[(size_t)r * EMB + c]       = pack_bf16x2(v00 - h00, v01 - h01);
                *(uint32_t*)&Cl[(size_t)(r + 8) * EMB + c] = pack_bf16x2(v10 - h10, v11 - h11);
            }
        }
    }
}

// ---------------------------------------------------------------------------
// V transpose (hi+lo): [n*2048+j][h*64+d] -> [(n*16+h)*64+d][j]
// ---------------------------------------------------------------------------
__global__ __launch_bounds__(256) void vt_kernel(
    const __nv_bfloat16* __restrict__ vhi, const __nv_bfloat16* __restrict__ vlo,
    __nv_bfloat16* __restrict__ vthi, __nv_bfloat16* __restrict__ vtlo)
{
    __shared__ __nv_bfloat16 th[32][33];
    __shared__ __nv_bfloat16 tl[32][33];
    const int tx = threadIdx.x & 31;
    const int ty = threadIdx.x >> 5;
    const int j0 = blockIdx.x * 32;
    const int d0 = blockIdx.y * 32;
    const int nh = blockIdx.z;
    const int n  = nh >> 4;
    const int h  = nh & 15;

#pragma unroll
    for (int k = 0; k < 4; k++) {
        int j = j0 + ty + 8 * k;
        size_t src = (size_t)(n * LSEQ + j) * EMB + h * HD + d0 + tx;
        th[ty + 8 * k][tx] = vhi[src];
        tl[ty + 8 * k][tx] = vlo[src];
    }
    __syncthreads();
#pragma unroll
    for (int k = 0; k < 4; k++) {
        int d = d0 + ty + 8 * k;
        size_t dst = (size_t)(nh * HD + d) * LSEQ + j0 + tx;
        vthi[dst] = th[tx][ty + 8 * k];
        vtlo[dst] = tl[tx][ty + 8 * k];
    }
}

// ---------------------------------------------------------------------------
// Tensor-core flash attention, 3-term split QK and PV, cp.async double-buffered.
// Dynamic smem: 2 stages x (4 x 64 x ATSTR) bf16 = 73728 B.
// Stage layout: Khi | Klo | Vhi | Vlo, each 64*ATSTR bf16 (9216 B).
// Q preload borrows stage 0 (Q frags hoisted to regs before pipeline starts).
// ---------------------------------------------------------------------------
#define ATSTR 72
#define ATILE_B (64 * ATSTR * 2)     // 9216
#define ASTAGE_B (4 * ATILE_B)       // 36864
#define ASMEM (2 * ASTAGE_B)         // 73728

__global__ __launch_bounds__(256, 1) void attn_mma_kernel()
{
    extern __shared__ __align__(16) __nv_bfloat16 asm_buf[];

    const int tid  = threadIdx.x;
    const int wid  = tid >> 5;
    const int lane = tid & 31;
    const int q0 = blockIdx.x * 128;
    const int h  = blockIdx.y;
    const int n  = blockIdx.z;

    const uint32_t uS = smem_u32(asm_buf);
    const uint32_t aLane = (uint32_t)(((lane & 15) * ATSTR + (lane >> 4) * 8) * 2);
    const uint32_t bLane = (uint32_t)(((((lane >> 4) << 3) + (lane & 7)) * ATSTR + ((lane >> 3) & 1) * 8) * 2);

    // Per-thread K/V load coordinates (2 chunks per tile buffer)
    const int kr0 = tid >> 3,         kc0 = tid & 7;
    const int kr1 = (tid + 256) >> 3, kc1 = (tid + 256) & 7;
    const uint32_t ksd0 = (uint32_t)((kr0 * ATSTR + kc0 * 8) * 2);
    const uint32_t ksd1 = (uint32_t)((kr1 * ATSTR + kc1 * 8) * 2);

    auto load_kv = [&](int s, int kt) {
        uint32_t base = uS + (uint32_t)(s * ASTAGE_B);
        size_t kb0 = (size_t)(n * LSEQ + kt + kr0) * EMB + h * HD + kc0 * 8;
        size_t vb0 = (size_t)((n * NH + h) * HD + kr0) * LSEQ + kt + kc0 * 8;
        size_t kb1 = (size_t)(n * LSEQ + kt + kr1) * EMB + h * HD + kc1 * 8;
        size_t vb1 = (size_t)((n * NH + h) * HD + kr1) * LSEQ + kt + kc1 * 8;
        cp_async16(base + ksd0,               &g_khi[kb0]);
        cp_async16(base + ATILE_B + ksd0,     &g_klo[kb0]);
        cp_async16(base + 2 * ATILE_B + ksd0, &g_vthi[vb0]);
        cp_async16(base + 3 * ATILE_B + ksd0, &g_vtlo[vb0]);
        cp_async16(base + ksd1,               &g_khi[kb1]);
        cp_async16(base + ATILE_B + ksd1,     &g_klo[kb1]);
        cp_async16(base + 2 * ATILE_B + ksd1, &g_vthi[vb1]);
        cp_async16(base + 3 * ATILE_B + ksd1, &g_vtlo[vb1]);
    };

    // Phase 1: load Qhi (rows 0..127) / Qlo (rows 128..255) into stage 0, scaled by 1/8
    const __nv_bfloat162 sc2 = __float2bfloat162_rn(0.125f);
#pragma unroll
    for (int i = 0; i < 4; i++) {
        int idx = tid + i * 256;
        int r = idx >> 3;
        int c = idx & 7;
        size_t src = (size_t)(n * LSEQ + q0 + r) * EMB + h * HD + c * 8;
        int4 vh = *(const int4*)&g_qhi[src];
        int4 vl = *(const int4*)&g_qlo[src];
        __nv_bfloat162* ph = (__nv_bfloat162*)&vh;
        __nv_bfloat162* pl = (__nv_bfloat162*)&vl;
#pragma unroll
        for (int z = 0; z < 4; z++) { ph[z] = __hmul2(ph[z], sc2); pl[z] = __hmul2(pl[z], sc2); }
        *(int4*)&asm_buf[r * ATSTR + c * 8] = vh;
        *(int4*)&asm_buf[(size_t)(128 + r) * ATSTR + c * 8] = vl;
    }
    __syncthreads();

    uint32_t qh[4][4], ql[4][4];
#pragma unroll
    for (int kk = 0; kk < 4; kk++) {
        ldsm_x4(qh[kk], uS + (uint32_t)((wid * 16 * ATSTR + kk * 16) * 2) + aLane);
        ldsm_x4(ql[kk], uS + (uint32_t)(((128 + wid * 16) * ATSTR + kk * 16) * 2) + aLane);
    }
    __syncthreads();   // Q frags in regs; stage 0 reusable

    float oo[8][4];
#pragma unroll
    for (int ni = 0; ni < 8; ni++)
#pragma unroll
        for (int r = 0; r < 4; r++) oo[ni][r] = 0.0f;
    float m0 = -1e30f, m1 = -1e30f, l0 = 0.0f, l1 = 0.0f;

    load_kv(0, 0);
    CP_COMMIT();

    for (int t = 0; t < LSEQ / 64; t++) {
        if (t + 1 < LSEQ / 64) load_kv((t + 1) & 1, (t + 1) * 64);
        CP_COMMIT();
        CP_WAIT1();
        __syncthreads();

        const uint32_t oKh = uS + (uint32_t)((t & 1) * ASTAGE_B);
        const uint32_t oKl = oKh + ATILE_B;
        const uint32_t oVh = oKh + 2 * ATILE_B;
        const uint32_t oVl = oKh + 3 * ATILE_B;

        // S = Q @ K^T (3-term split)
        float sS[8][4];
#pragma unroll
        for (int ni = 0; ni < 8; ni++)
#pragma unroll
            for (int r = 0; r < 4; r++) sS[ni][r] = 0.0f;
#pragma unroll
        for (int nb = 0; nb < 4; nb++) {
            uint32_t kh[4][4], kl[4][4];
#pragma unroll
            for (int kk = 0; kk < 4; kk++) {
                uint32_t off = (uint32_t)((nb * 16 * ATSTR + kk * 16) * 2) + bLane;
                ldsm_x4(kh[kk], oKh + off);
                ldsm_x4(kl[kk], oKl + off);
            }
#pragma unroll
            for (int kk = 0; kk < 4; kk++)
#pragma unroll
                for (int i = 0; i < 2; i++) {
                    mma_bf16(sS[nb * 2 + i], qh[kk], kh[kk][i * 2], kh[kk][i * 2 + 1]);
                    mma_bf16(sS[nb * 2 + i], qh[kk], kl[kk][i * 2], kl[kk][i * 2 + 1]);
                    mma_bf16(sS[nb * 2 + i], ql[kk], kh[kk][i * 2], kh[kk][i * 2 + 1]);
                }
        }

        // Online softmax
        float mt0 = -1e30f, mt1 = -1e30f;
#pragma unroll
        for (int ni = 0; ni < 8; ni++) {
            mt0 = fmaxf(mt0, fmaxf(sS[ni][0], sS[ni][1]));
            mt1 = fmaxf(mt1, fmaxf(sS[ni][2], sS[ni][3]));
        }
#pragma unroll
        for (int off = 1; off <= 2; off <<= 1) {
            mt0 = fmaxf(mt0, __shfl_xor_sync(0xffffffffu, mt0, off));
            mt1 = fmaxf(mt1, __shfl_xor_sync(0xffffffffu, mt1, off));
        }
        float mn0 = fmaxf(m0, mt0), mn1 = fmaxf(m1, mt1);
        float c0 = __expf(m0 - mn0), c1 = __expf(m1 - mn1);

        uint32_t pfh[4][4], pfl[4][4];
        float s0 = 0.0f, s1 = 0.0f;
#pragma unroll
        for (int ni = 0; ni < 8; ni++) {
            float p0 = __expf(sS[ni][0] - mn0);
            float p1 = __expf(sS[ni][1] - mn0);
            float p2 = __expf(sS[ni][2] - mn1);
            float p3 = __expf(sS[ni][3] - mn1);
            s0 += p0 + p1; s1 += p2 + p3;
            float h0 = __bfloat162float(__float2bfloat16(p0));
            float h1 = __bfloat162float(__float2bfloat16(p1));
            float h2 = __bfloat162float(__float2bfloat16(p2));
            float h3 = __bfloat162float(__float2bfloat16(p3));
            pfh[ni >> 1][(ni & 1) * 2 + 0] = pack_bf16x2(h0, h1);
            pfh[ni >> 1][(ni & 1) * 2 + 1] = pack_bf16x2(h2, h3);
            pfl[ni >> 1][(ni & 1) * 2 + 0] = pack_bf16x2(p0 - h0, p1 - h1);
            pfl[ni >> 1][(ni & 1) * 2 + 1] = pack_bf16x2(p2 - h2, p3 - h3);
        }
#pragma unroll
        for (int off = 1; off <= 2; off <<= 1) {
            s0 += __shfl_xor_sync(0xffffffffu, s0, off);
            s1 += __shfl_xor_sync(0xffffffffu, s1, off);
        }
        l0 = l0 * c0 + s0;
        l1 = l1 * c1 + s1;
        m0 = mn0; m1 = mn1;
#pragma unroll
        for (int ni = 0; ni < 8; ni++) {
            oo[ni][0] *= c0; oo[ni][1] *= c0;
            oo[ni][2] *= c1; oo[ni][3] *= c1;
        }

        // O += P @ V (3-term split)
#pragma unroll
        for (int nbd = 0; nbd < 4; nbd++) {
            uint32_t vh[4][4], vl[4][4];
#pragma unroll
            for (int kk = 0; kk < 4; kk++) {
                uint32_t off = (uint32_t)((nbd * 16 * ATSTR + kk * 16) * 2) + bLane;
                ldsm_x4(vh[kk], oVh + off);
                ldsm_x4(vl[kk], oVl + off);
            }
#pragma unroll
            for (int kk = 0; kk < 4; kk++)
#pragma unroll
                for (int i = 0; i < 2; i++) {
                    mma_bf16(oo[nbd * 2 + i], pfh[kk], vh[kk][i * 2], vh[kk][i * 2 + 1]);
                    mma_bf16(oo[nbd * 2 + i], pfh[kk], vl[kk][i * 2], vl[kk][i * 2 + 1]);
                    mma_bf16(oo[nbd * 2 + i], pfl[kk], vh[kk][i * 2], vh[kk][i * 2 + 1]);
                }
        }
        __syncthreads();
    }

    // Epilogue: normalize, split hi/lo, store for output projection
    float inv0 = 1.0f / l0, inv1 = 1.0f / l1;
    const int er = lane >> 2;
    const int ec = (lane & 3) * 2;
#pragma unroll
    for (int ni = 0; ni < 8; ni++) {
        int r = n * LSEQ + q0 + wid * 16 + er;
        int c = h * HD + ni * 8 + ec;
        float v00 = oo[ni][0] * inv0, v01 = oo[ni][1] * inv0;
        float v10 = oo[ni][2] * inv1, v11 = oo[ni][3] * inv1;
        float h00 = __bfloat162float(__float2bfloat16(v00));
        float h01 = __bfloat162float(__float2bfloat16(v01));
        float h10 = __bfloat162float(__float2bfloat16(v10));
        float h11 = __bfloat162float(__float2bfloat16(v11));
        *(uint32_t*)&g_ahi[(size_t)r * EMB + c]       = pack_bf16x2(h00, h01);
        *(uint32_t*)&g_ahi[(size_t)(r + 8) * EMB + c] = pack_bf16x2(h10, h11);
        *(uint32_t*)&g_alo[(size_t)r * EMB + c]       = pack_bf16x2(v00 - h00, v01 - h01);
        *(uint32_t*)&g_alo[(size_t)(r + 8) * EMB + c] = pack_bf16x2(v10 - h10, v11 - h11);
    }
}

// ---------------------------------------------------------------------------
// Launch
// ---------------------------------------------------------------------------
extern "C" void kernel_launch(void* const* d_in, const int* in_sizes, int n_in,
                              void* d_out, int out_size)
{
    const float* Q  = (const float*)d_in[0];
    const float* K  = (const float*)d_in[1];
    const float* V  = (const float*)d_in[2];
    const float* Wq = (const float*)d_in[3];
    const float* bq = (const float*)d_in[4];
    const float* Wk = (const float*)d_in[5];
    const float* bk = (const float*)d_in[6];
    const float* Wv = (const float*)d_in[7];
    const float* bv = (const float*)d_in[8];
    const float* Wo = (const float*)d_in[9];
    const float* bo = (const float*)d_in[10];
    float* out = (float*)d_out;

    __nv_bfloat16 *qhi, *qlo, *khi, *klo, *vhi, *vlo, *vthi, *vtlo, *ahi, *alo, *whi, *wlo;
    cudaGetSymbolAddress((void**)&qhi,  g_qhi);
    cudaGetSymbolAddress((void**)&qlo,  g_qlo);
    cudaGetSymbolAddress((void**)&khi,  g_khi);
    cudaGetSymbolAddress((void**)&klo,  g_klo);
    cudaGetSymbolAddress((void**)&vhi,  g_vhi);
    cudaGetSymbolAddress((void**)&vlo,  g_vlo);
    cudaGetSymbolAddress((void**)&vthi, g_vthi);
    cudaGetSymbolAddress((void**)&vtlo, g_vtlo);
    cudaGetSymbolAddress((void**)&ahi,  g_ahi);
    cudaGetSymbolAddress((void**)&alo,  g_alo);
    cudaGetSymbolAddress((void**)&whi,  g_whi);
    cudaGetSymbolAddress((void**)&wlo,  g_wlo);

    // Opt-in smem limits (idempotent; host-side attribute, no allocation)
    cudaFuncSetAttribute(gemm_mma_kernel<0>, cudaFuncAttributeMaxDynamicSharedMemorySize, GSMEM);
    cudaFuncSetAttribute(gemm_mma_kernel<2>, cudaFuncAttributeMaxDynamicSharedMemorySize, GSMEM);
    cudaFuncSetAttribute(attn_mma_kernel,    cudaFuncAttributeMaxDynamicSharedMemorySize, ASMEM);

    const int nA4 = MROWS * EMB / 4;
    const int nW4 = EMB * EMB / 4;
    dim3 gg(EMB / 128, MROWS / 128);   // (8, 64)

    // Q projection -> split bf16
    split_bf16_kernel<<<(nA4 + 255) / 256, 256>>>(Q, ahi, alo, nA4);
    split_bf16_kernel<<<(nW4 + 255) / 256, 256>>>(Wq, whi, wlo, nW4);
    gemm_mma_kernel<2><<<gg, 256, GSMEM>>>(ahi, alo, whi, wlo, bq, qhi, qlo);
    // K projection -> split bf16
    split_bf16_kernel<<<(nA4 + 255) / 256, 256>>>(K, ahi, alo, nA4);
    split_bf16_kernel<<<(nW4 + 255) / 256, 256>>>(Wk, whi, wlo, nW4);
    gemm_mma_kernel<2><<<gg, 256, GSMEM>>>(ahi, alo, whi, wlo, bk, khi, klo);
    // V projection -> split bf16, then transpose both
    split_bf16_kernel<<<(nA4 + 255) / 256, 256>>>(V, ahi, alo, nA4);
    split_bf16_kernel<<<(nW4 + 255) / 256, 256>>>(Wv, whi, wlo, nW4);
    gemm_mma_kernel<2><<<gg, 256, GSMEM>>>(ahi, alo, whi, wlo, bv, vhi, vlo);
    vt_kernel<<<dim3(LSEQ / 32, HD / 32, NB * NH), 256>>>(vhi, vlo, vthi, vtlo);

    // Full-split tensor-core attention (writes g_ahi/g_alo)
    attn_mma_kernel<<<dim3(LSEQ / 128, NH, NB), 256, ASMEM>>>();

    // Output projection (fp32 out)
    split_bf16_kernel<<<(nW4 + 255) / 256, 256>>>(Wo, whi, wlo, nW4);
    gemm_mma_kernel<0><<<gg, 256, GSMEM>>>(ahi, alo, whi, wlo, bo, out, nullptr);
}

// round 7
// speedup vs baseline: 3.7379x; 1.0025x over previous
#include <cuda_runtime.h>
#include <cuda_bf16.h>
#include <cstdint>

// Problem constants
#define NB    4
#define LSEQ  2048
#define EMB   1024
#define NH    16
#define HD    64
#define MROWS (NB * LSEQ)   // 8192

// Scratch (static device arrays — no allocation allowed)
// Input splits (A-side) for Q/K/V projections
__device__ __nv_bfloat16 g_sqhi[MROWS * EMB];
__device__ __nv_bfloat16 g_sqlo[MROWS * EMB];
__device__ __nv_bfloat16 g_skhi[MROWS * EMB];
__device__ __nv_bfloat16 g_sklo[MROWS * EMB];
__device__ __nv_bfloat16 g_svhi[MROWS * EMB];
__device__ __nv_bfloat16 g_svlo[MROWS * EMB];
// Weight splits
__device__ __nv_bfloat16 g_wqhi[EMB * EMB];
__device__ __nv_bfloat16 g_wqlo[EMB * EMB];
__device__ __nv_bfloat16 g_wkhi[EMB * EMB];
__device__ __nv_bfloat16 g_wklo[EMB * EMB];
__device__ __nv_bfloat16 g_wvhi[EMB * EMB];
__device__ __nv_bfloat16 g_wvlo[EMB * EMB];
__device__ __nv_bfloat16 g_wohi[EMB * EMB];
__device__ __nv_bfloat16 g_wolo[EMB * EMB];
// Projection outputs (split)
__device__ __nv_bfloat16 g_qhi[MROWS * EMB];
__device__ __nv_bfloat16 g_qlo[MROWS * EMB];
__device__ __nv_bfloat16 g_khi[MROWS * EMB];
__device__ __nv_bfloat16 g_klo[MROWS * EMB];
__device__ __nv_bfloat16 g_vhi[MROWS * EMB];
__device__ __nv_bfloat16 g_vlo[MROWS * EMB];
__device__ __nv_bfloat16 g_vthi[MROWS * EMB];  // transposed: [(n*16+h)*64+d][j]
__device__ __nv_bfloat16 g_vtlo[MROWS * EMB];
// Attention output (split)
__device__ __nv_bfloat16 g_ahi[MROWS * EMB];
__device__ __nv_bfloat16 g_alo[MROWS * EMB];

// ---------------------------------------------------------------------------
// Warp-level tensor-core + async-copy primitives (baseline ISA on compute_103)
// ---------------------------------------------------------------------------
__device__ __forceinline__ uint32_t smem_u32(const void* p) {
    uint32_t a;
    asm("{ .reg .u64 t; cvta.to.shared.u64 t, %1; cvt.u32.u64 %0, t; }" : "=r"(a) : "l"(p));
    return a;
}

__device__ __forceinline__ void ldsm_x4(uint32_t* r, uint32_t addr) {
    asm volatile("ldmatrix.sync.aligned.m8n8.x4.shared.b16 {%0,%1,%2,%3}, [%4];"
        : "=r"(r[0]), "=r"(r[1]), "=r"(r[2]), "=r"(r[3]) : "r"(addr));
}

__device__ __forceinline__ void mma_bf16(float* d, const uint32_t* a, uint32_t b0, uint32_t b1) {
    asm volatile(
        "mma.sync.aligned.m16n8k16.row.col.f32.bf16.bf16.f32 "
        "{%0,%1,%2,%3}, {%4,%5,%6,%7}, {%8,%9}, {%0,%1,%2,%3};"
        : "+f"(d[0]), "+f"(d[1]), "+f"(d[2]), "+f"(d[3])
        : "r"(a[0]), "r"(a[1]), "r"(a[2]), "r"(a[3]), "r"(b0), "r"(b1));
}

__device__ __forceinline__ uint32_t pack_bf16x2(float lo, float hi) {
    __nv_bfloat162 p = __float22bfloat162_rn(make_float2(lo, hi));
    return *(uint32_t*)&p;
}

__device__ __forceinline__ void cp_async16(uint32_t saddr, const void* g) {
    asm volatile("cp.async.cg.shared.global [%0], [%1], 16;" :: "r"(saddr), "l"(g));
}
#define CP_COMMIT() asm volatile("cp.async.commit_group;")
#define CP_WAIT1()  asm volatile("cp.async.wait_group 1;")

// ---------------------------------------------------------------------------
// Batched fp32 -> bf16 hi/lo splits
// ---------------------------------------------------------------------------
struct SplitB3 { const float* in[3]; __nv_bfloat16* hi[3]; __nv_bfloat16* lo[3]; };
struct SplitB4 { const float* in[4]; __nv_bfloat16* hi[4]; __nv_bfloat16* lo[4]; };

__device__ __forceinline__ void split_body(const float* __restrict__ in,
                                           __nv_bfloat16* __restrict__ hi,
                                           __nv_bfloat16* __restrict__ lo, int i)
{
    float4 x = ((const float4*)in)[i];
    __nv_bfloat16 h0 = __float2bfloat16(x.x), h1 = __float2bfloat16(x.y);
    __nv_bfloat16 h2 = __float2bfloat16(x.z), h3 = __float2bfloat16(x.w);
    __nv_bfloat16 l0 = __float2bfloat16(x.x - __bfloat162float(h0));
    __nv_bfloat16 l1 = __float2bfloat16(x.y - __bfloat162float(h1));
    __nv_bfloat16 l2 = __float2bfloat16(x.z - __bfloat162float(h2));
    __nv_bfloat16 l3 = __float2bfloat16(x.w - __bfloat162float(h3));
    ((__nv_bfloat162*)hi)[i * 2 + 0] = __nv_bfloat162(h0, h1);
    ((__nv_bfloat162*)hi)[i * 2 + 1] = __nv_bfloat162(h2, h3);
    ((__nv_bfloat162*)lo)[i * 2 + 0] = __nv_bfloat162(l0, l1);
    ((__nv_bfloat162*)lo)[i * 2 + 1] = __nv_bfloat162(l2, l3);
}

__global__ __launch_bounds__(256) void split3_kernel(SplitB3 P, int n4)
{
    int i = blockIdx.x * 256 + threadIdx.x;
    int z = blockIdx.y;
    if (i >= n4) return;
    split_body(P.in[z], P.hi[z], P.lo[z], i);
}

__global__ __launch_bounds__(256) void split4_kernel(SplitB4 P, int n4)
{
    int i = blockIdx.x * 256 + threadIdx.x;
    int z = blockIdx.y;
    if (i >= n4) return;
    split_body(P.in[z], P.hi[z], P.lo[z], i);
}

// ---------------------------------------------------------------------------
// HMMA GEMM body: C = A @ W^T + bias, 3-term bf16 split, cp.async 2-stage.
// OM=0: fp32 single output. OM=2: bf16 hi/lo split pair output.
// ---------------------------------------------------------------------------
#define BK    32
#define TSTR  40
#define GTILE (128 * TSTR)
#define GSTAGE_B (4 * GTILE * 2)
#define GSMEM (2 * GSTAGE_B)   // 81920

template <int OM>
__device__ __forceinline__ void gemm_body(
    const __nv_bfloat16* __restrict__ Ahi, const __nv_bfloat16* __restrict__ Alo,
    const __nv_bfloat16* __restrict__ Whi, const __nv_bfloat16* __restrict__ Wlo,
    const float* __restrict__ bias, void* __restrict__ Cout, void* __restrict__ Cout2,
    __nv_bfloat16* dsm)
{
    const int tid  = threadIdx.x;
    const int wid  = tid >> 5;
    const int lane = tid & 31;
    const int wm   = wid >> 2;
    const int wn   = wid & 3;
    const int row0 = blockIdx.y * 128;
    const int col0 = blockIdx.x * 128;

    const uint32_t uS = smem_u32(dsm);
    const uint32_t aLane = (uint32_t)(((lane & 15) * TSTR + (lane >> 4) * 8) * 2);
    const uint32_t bLane = (uint32_t)(((((lane >> 4) << 3) + (lane & 7)) * TSTR + ((lane >> 3) & 1) * 8) * 2);

    const int lr0 = tid >> 2,         lc0 = tid & 3;
    const int lr1 = (tid + 256) >> 2, lc1 = (tid + 256) & 3;
    const uint32_t sd0 = (uint32_t)((lr0 * TSTR + lc0 * 8) * 2);
    const uint32_t sd1 = (uint32_t)((lr1 * TSTR + lc1 * 8) * 2);

    auto load_stage = [&](int s, int kt) {
        uint32_t base = uS + (uint32_t)(s * GSTAGE_B);
        size_t ga0 = (size_t)(row0 + lr0) * EMB + kt + lc0 * 8;
        size_t gw0 = (size_t)(col0 + lr0) * EMB + kt + lc0 * 8;
        size_t ga1 = (size_t)(row0 + lr1) * EMB + kt + lc1 * 8;
        size_t gw1 = (size_t)(col0 + lr1) * EMB + kt + lc1 * 8;
        cp_async16(base + sd0,                 &Ahi[ga0]);
        cp_async16(base + GTILE * 2 + sd0,     &Alo[ga0]);
        cp_async16(base + 2 * GTILE * 2 + sd0, &Whi[gw0]);
        cp_async16(base + 3 * GTILE * 2 + sd0, &Wlo[gw0]);
        cp_async16(base + sd1,                 &Ahi[ga1]);
        cp_async16(base + GTILE * 2 + sd1,     &Alo[ga1]);
        cp_async16(base + 2 * GTILE * 2 + sd1, &Whi[gw1]);
        cp_async16(base + 3 * GTILE * 2 + sd1, &Wlo[gw1]);
    };

    float acc[4][4][4];
#pragma unroll
    for (int mi = 0; mi < 4; mi++)
#pragma unroll
        for (int ni = 0; ni < 4; ni++)
#pragma unroll
            for (int r = 0; r < 4; r++) acc[mi][ni][r] = 0.0f;

    load_stage(0, 0);
    CP_COMMIT();

    for (int t = 0; t < EMB / BK; t++) {
        if (t + 1 < EMB / BK) load_stage((t + 1) & 1, (t + 1) * BK);
        CP_COMMIT();
        CP_WAIT1();
        __syncthreads();

        const uint32_t uAhi = uS + (uint32_t)((t & 1) * GSTAGE_B);
        const uint32_t uAlo = uAhi + GTILE * 2;
        const uint32_t uBhi = uAhi + 2 * GTILE * 2;
        const uint32_t uBlo = uAhi + 3 * GTILE * 2;

#pragma unroll
        for (int ks = 0; ks < 2; ks++) {
            uint32_t bh[2][4], bl[2][4];
#pragma unroll
            for (int nb = 0; nb < 2; nb++) {
                uint32_t boff = (uint32_t)(((wn * 32 + nb * 16) * TSTR + ks * 16) * 2) + bLane;
                ldsm_x4(bh[nb], uBhi + boff);
                ldsm_x4(bl[nb], uBlo + boff);
            }
#pragma unroll
            for (int mi = 0; mi < 4; mi++) {
                uint32_t aoff = (uint32_t)(((wm * 64 + mi * 16) * TSTR + ks * 16) * 2) + aLane;
                uint32_t ah[4], al[4];
                ldsm_x4(ah, uAhi + aoff);
                ldsm_x4(al, uAlo + aoff);
                // term-major: same-acc reuse distance = 4 MMAs
#pragma unroll
                for (int ni = 0; ni < 4; ni++)
                    mma_bf16(acc[mi][ni], ah, bh[ni >> 1][(ni & 1) * 2], bh[ni >> 1][(ni & 1) * 2 + 1]);
#pragma unroll
                for (int ni = 0; ni < 4; ni++)
                    mma_bf16(acc[mi][ni], ah, bl[ni >> 1][(ni & 1) * 2], bl[ni >> 1][(ni & 1) * 2 + 1]);
#pragma unroll
                for (int ni = 0; ni < 4; ni++)
                    mma_bf16(acc[mi][ni], al, bh[ni >> 1][(ni & 1) * 2], bh[ni >> 1][(ni & 1) * 2 + 1]);
            }
        }
        __syncthreads();
    }

    const int er = lane >> 2;
    const int ec = (lane & 3) * 2;
#pragma unroll
    for (int mi = 0; mi < 4; mi++) {
#pragma unroll
        for (int ni = 0; ni < 4; ni++) {
            int r = row0 + wm * 64 + mi * 16 + er;
            int c = col0 + wn * 32 + ni * 8 + ec;
            float b0 = bias[c], b1 = bias[c + 1];
            float v00 = acc[mi][ni][0] + b0, v01 = acc[mi][ni][1] + b1;
            float v10 = acc[mi][ni][2] + b0, v11 = acc[mi][ni][3] + b1;
            if (OM == 0) {
                float* C = (float*)Cout;
                *(float2*)&C[(size_t)r * EMB + c] = make_float2(v00, v01);
                *(float2*)&C[(size_t)(r + 8) * EMB + c] = make_float2(v10, v11);
            } else {
                __nv_bfloat16* Ch = (__nv_bfloat16*)Cout;
                __nv_bfloat16* Cl = (__nv_bfloat16*)Cout2;
                float h00 = __bfloat162float(__float2bfloat16(v00));
                float h01 = __bfloat162float(__float2bfloat16(v01));
                float h10 = __bfloat162float(__float2bfloat16(v10));
                float h11 = __bfloat162float(__float2bfloat16(v11));
                *(uint32_t*)&Ch[(size_t)r * EMB + c]       = pack_bf16x2(h00, h01);
                *(uint32_t*)&Ch[(size_t)(r + 8) * EMB + c] = pack_bf16x2(h10, h11);
                *(uint32_t*)&Cl[(size_t)r * EMB + c]       = pack_bf16x2(v00 - h00, v01 - h01);
                *(uint32_t*)&Cl[(size_t)(r + 8) * EMB + c] = pack_bf16x2(v10 - h10, v11 - h11);
            }
        }
    }
}

struct GemmQKV {
    const __nv_bfloat16 *Ahi[3], *Alo[3], *Whi[3], *Wlo[3];
    const float* bias[3];
    __nv_bfloat16 *Chi[3], *Clo[3];
};

__global__ __launch_bounds__(256, 2) void gemm_qkv_kernel(GemmQKV P)
{
    extern __shared__ __align__(16) __nv_bfloat16 dsm[];
    const int z = blockIdx.z;
    gemm_body<2>(P.Ahi[z], P.Alo[z], P.Whi[z], P.Wlo[z], P.bias[z],
                 P.Chi[z], P.Clo[z], dsm);
}

__global__ __launch_bounds__(256, 2) void gemm_final_kernel(
    const __nv_bfloat16* __restrict__ Ahi, const __nv_bfloat16* __restrict__ Alo,
    const __nv_bfloat16* __restrict__ Whi, const __nv_bfloat16* __restrict__ Wlo,
    const float* __restrict__ bias, float* __restrict__ Cout)
{
    extern __shared__ __align__(16) __nv_bfloat16 dsm[];
    gemm_body<0>(Ahi, Alo, Whi, Wlo, bias, Cout, nullptr, dsm);
}

// ---------------------------------------------------------------------------
// V transpose (hi+lo): [n*2048+j][h*64+d] -> [(n*16+h)*64+d][j]
// ---------------------------------------------------------------------------
__global__ __launch_bounds__(256) void vt_kernel(
    const __nv_bfloat16* __restrict__ vhi, const __nv_bfloat16* __restrict__ vlo,
    __nv_bfloat16* __restrict__ vthi, __nv_bfloat16* __restrict__ vtlo)
{
    __shared__ __nv_bfloat16 th[32][33];
    __shared__ __nv_bfloat16 tl[32][33];
    const int tx = threadIdx.x & 31;
    const int ty = threadIdx.x >> 5;
    const int j0 = blockIdx.x * 32;
    const int d0 = blockIdx.y * 32;
    const int nh = blockIdx.z;
    const int n  = nh >> 4;
    const int h  = nh & 15;

#pragma unroll
    for (int k = 0; k < 4; k++) {
        int j = j0 + ty + 8 * k;
        size_t src = (size_t)(n * LSEQ + j) * EMB + h * HD + d0 + tx;
        th[ty + 8 * k][tx] = vhi[src];
        tl[ty + 8 * k][tx] = vlo[src];
    }
    __syncthreads();
#pragma unroll
    for (int k = 0; k < 4; k++) {
        int d = d0 + ty + 8 * k;
        size_t dst = (size_t)(nh * HD + d) * LSEQ + j0 + tx;
        vthi[dst] = th[tx][ty + 8 * k];
        vtlo[dst] = tl[tx][ty + 8 * k];
    }
}

// ---------------------------------------------------------------------------
// Tensor-core flash attention, 3-term split QK/PV, cp.async double-buffered.
// nb-paired fragment loads -> 4 independent accumulator chains per phase.
// ---------------------------------------------------------------------------
#define ATSTR 72
#define ATILE_B (64 * ATSTR * 2)
#define ASTAGE_B (4 * ATILE_B)
#define ASMEM (2 * ASTAGE_B)

__global__ __launch_bounds__(256, 1) void attn_mma_kernel()
{
    extern __shared__ __align__(16) __nv_bfloat16 asm_buf[];

    const int tid  = threadIdx.x;
    const int wid  = tid >> 5;
    const int lane = tid & 31;
    const int q0 = blockIdx.x * 128;
    const int h  = blockIdx.y;
    const int n  = blockIdx.z;

    const uint32_t uS = smem_u32(asm_buf);
    const uint32_t aLane = (uint32_t)(((lane & 15) * ATSTR + (lane >> 4) * 8) * 2);
    const uint32_t bLane = (uint32_t)(((((lane >> 4) << 3) + (lane & 7)) * ATSTR + ((lane >> 3) & 1) * 8) * 2);

    const int kr0 = tid >> 3,         kc0 = tid & 7;
    const int kr1 = (tid + 256) >> 3, kc1 = (tid + 256) & 7;
    const uint32_t ksd0 = (uint32_t)((kr0 * ATSTR + kc0 * 8) * 2);
    const uint32_t ksd1 = (uint32_t)((kr1 * ATSTR + kc1 * 8) * 2);

    auto load_kv = [&](int s, int kt) {
        uint32_t base = uS + (uint32_t)(s * ASTAGE_B);
        size_t kb0 = (size_t)(n * LSEQ + kt + kr0) * EMB + h * HD + kc0 * 8;
        size_t vb0 = (size_t)((n * NH + h) * HD + kr0) * LSEQ + kt + kc0 * 8;
        size_t kb1 = (size_t)(n * LSEQ + kt + kr1) * EMB + h * HD + kc1 * 8;
        size_t vb1 = (size_t)((n * NH + h) * HD + kr1) * LSEQ + kt + kc1 * 8;
        cp_async16(base + ksd0,               &g_khi[kb0]);
        cp_async16(base + ATILE_B + ksd0,     &g_klo[kb0]);
        cp_async16(base + 2 * ATILE_B + ksd0, &g_vthi[vb0]);
        cp_async16(base + 3 * ATILE_B + ksd0, &g_vtlo[vb0]);
        cp_async16(base + ksd1,               &g_khi[kb1]);
        cp_async16(base + ATILE_B + ksd1,     &g_klo[kb1]);
        cp_async16(base + 2 * ATILE_B + ksd1, &g_vthi[vb1]);
        cp_async16(base + 3 * ATILE_B + ksd1, &g_vtlo[vb1]);
    };

    // Phase 1: Qhi/Qlo into stage 0 (scaled by 1/8), hoist frags
    const __nv_bfloat162 sc2 = __float2bfloat162_rn(0.125f);
#pragma unroll
    for (int i = 0; i < 4; i++) {
        int idx = tid + i * 256;
        int r = idx >> 3;
        int c = idx & 7;
        size_t src = (size_t)(n * LSEQ + q0 + r) * EMB + h * HD + c * 8;
        int4 vh = *(const int4*)&g_qhi[src];
        int4 vl = *(const int4*)&g_qlo[src];
        __nv_bfloat162* ph = (__nv_bfloat162*)&vh;
        __nv_bfloat162* pl = (__nv_bfloat162*)&vl;
#pragma unroll
        for (int z = 0; z < 4; z++) { ph[z] = __hmul2(ph[z], sc2); pl[z] = __hmul2(pl[z], sc2); }
        *(int4*)&asm_buf[r * ATSTR + c * 8] = vh;
        *(int4*)&asm_buf[(size_t)(128 + r) * ATSTR + c * 8] = vl;
    }
    __syncthreads();

    uint32_t qh[4][4], ql[4][4];
#pragma unroll
    for (int kk = 0; kk < 4; kk++) {
        ldsm_x4(qh[kk], uS + (uint32_t)((wid * 16 * ATSTR + kk * 16) * 2) + aLane);
        ldsm_x4(ql[kk], uS + (uint32_t)(((128 + wid * 16) * ATSTR + kk * 16) * 2) + aLane);
    }
    __syncthreads();

    float oo[8][4];
#pragma unroll
    for (int ni = 0; ni < 8; ni++)
#pragma unroll
        for (int r = 0; r < 4; r++) oo[ni][r] = 0.0f;
    float m0 = -1e30f, m1 = -1e30f, l0 = 0.0f, l1 = 0.0f;

    load_kv(0, 0);
    CP_COMMIT();

    for (int t = 0; t < LSEQ / 64; t++) {
        if (t + 1 < LSEQ / 64) load_kv((t + 1) & 1, (t + 1) * 64);
        CP_COMMIT();
        CP_WAIT1();
        __syncthreads();

        const uint32_t oKh = uS + (uint32_t)((t & 1) * ASTAGE_B);
        const uint32_t oKl = oKh + ATILE_B;
        const uint32_t oVh = oKh + 2 * ATILE_B;
        const uint32_t oVl = oKh + 3 * ATILE_B;

        // S = Q @ K^T (3-term split), nb pairs -> 4 acc chains
        float sS[8][4];
#pragma unroll
        for (int ni = 0; ni < 8; ni++)
#pragma unroll
            for (int r = 0; r < 4; r++) sS[ni][r] = 0.0f;
#pragma unroll
        for (int nbp = 0; nbp < 2; nbp++) {
            uint32_t kh[2][4][4], kl[2][4][4];
#pragma unroll
            for (int b = 0; b < 2; b++)
#pragma unroll
                for (int kk = 0; kk < 4; kk++) {
                    uint32_t off = (uint32_t)(((nbp * 2 + b) * 16 * ATSTR + kk * 16) * 2) + bLane;
                    ldsm_x4(kh[b][kk], oKh + off);
                    ldsm_x4(kl[b][kk], oKl + off);
                }
#pragma unroll
            for (int kk = 0; kk < 4; kk++)
#pragma unroll
                for (int b = 0; b < 2; b++)
#pragma unroll
                    for (int i = 0; i < 2; i++)
                        mma_bf16(sS[(nbp * 2 + b) * 2 + i], qh[kk], kh[b][kk][i * 2], kh[b][kk][i * 2 + 1]);
#pragma unroll
            for (int kk = 0; kk < 4; kk++)
#pragma unroll
                for (int b = 0; b < 2; b++)
#pragma unroll
                    for (int i = 0; i < 2; i++)
                        mma_bf16(sS[(nbp * 2 + b) * 2 + i], qh[kk], kl[b][kk][i * 2], kl[b][kk][i * 2 + 1]);
#pragma unroll
            for (int kk = 0; kk < 4; kk++)
#pragma unroll
                for (int b = 0; b < 2; b++)
#pragma unroll
                    for (int i = 0; i < 2; i++)
                        mma_bf16(sS[(nbp * 2 + b) * 2 + i], ql[kk], kh[b][kk][i * 2], kh[b][kk][i * 2 + 1]);
        }

        // Online softmax
        float mt0 = -1e30f, mt1 = -1e30f;
#pragma unroll
        for (int ni = 0; ni < 8; ni++) {
            mt0 = fmaxf(mt0, fmaxf(sS[ni][0], sS[ni][1]));
            mt1 = fmaxf(mt1, fmaxf(sS[ni][2], sS[ni][3]));
        }
#pragma unroll
        for (int off = 1; off <= 2; off <<= 1) {
            mt0 = fmaxf(mt0, __shfl_xor_sync(0xffffffffu, mt0, off));
            mt1 = fmaxf(mt1, __shfl_xor_sync(0xffffffffu, mt1, off));
        }
        float mn0 = fmaxf(m0, mt0), mn1 = fmaxf(m1, mt1);
        float c0 = __expf(m0 - mn0), c1 = __expf(m1 - mn1);

        uint32_t pfh[4][4], pfl[4][4];
        float s0 = 0.0f, s1 = 0.0f;
#pragma unroll
        for (int ni = 0; ni < 8; ni++) {
            float p0 = __expf(sS[ni][0] - mn0);
            float p1 = __expf(sS[ni][1] - mn0);
            float p2 = __expf(sS[ni][2] - mn1);
            float p3 = __expf(sS[ni][3] - mn1);
            s0 += p0 + p1; s1 += p2 + p3;
            float h0 = __bfloat162float(__float2bfloat16(p0));
            float h1 = __bfloat162float(__float2bfloat16(p1));
            float h2 = __bfloat162float(__float2bfloat16(p2));
            float h3 = __bfloat162float(__float2bfloat16(p3));
            pfh[ni >> 1][(ni & 1) * 2 + 0] = pack_bf16x2(h0, h1);
            pfh[ni >> 1][(ni & 1) * 2 + 1] = pack_bf16x2(h2, h3);
            pfl[ni >> 1][(ni & 1) * 2 + 0] = pack_bf16x2(p0 - h0, p1 - h1);
            pfl[ni >> 1][(ni & 1) * 2 + 1] = pack_bf16x2(p2 - h2, p3 - h3);
        }
#pragma unroll
        for (int off = 1; off <= 2; off <<= 1) {
            s0 += __shfl_xor_sync(0xffffffffu, s0, off);
            s1 += __shfl_xor_sync(0xffffffffu, s1, off);
        }
        l0 = l0 * c0 + s0;
        l1 = l1 * c1 + s1;
        m0 = mn0; m1 = mn1;
#pragma unroll
        for (int ni = 0; ni < 8; ni++) {
            oo[ni][0] *= c0; oo[ni][1] *= c0;
            oo[ni][2] *= c1; oo[ni][3] *= c1;
        }

        // O += P @ V (3-term split), nb pairs
#pragma unroll
        for (int nbp = 0; nbp < 2; nbp++) {
            uint32_t vh[2][4][4], vl[2][4][4];
#pragma unroll
            for (int b = 0; b < 2; b++)
#pragma unroll
                for (int kk = 0; kk < 4; kk++) {
                    uint32_t off = (uint32_t)(((nbp * 2 + b) * 16 * ATSTR + kk * 16) * 2) + bLane;
                    ldsm_x4(vh[b][kk], oVh + off);
                    ldsm_x4(vl[b][kk], oVl + off);
                }
#pragma unroll
            for (int kk = 0; kk < 4; kk++)
#pragma unroll
                for (int b = 0; b < 2; b++)
#pragma unroll
                    for (int i = 0; i < 2; i++)
                        mma_bf16(oo[(nbp * 2 + b) * 2 + i], pfh[kk], vh[b][kk][i * 2], vh[b][kk][i * 2 + 1]);
#pragma unroll
            for (int kk = 0; kk < 4; kk++)
#pragma unroll
                for (int b = 0; b < 2; b++)
#pragma unroll
                    for (int i = 0; i < 2; i++)
                        mma_bf16(oo[(nbp * 2 + b) * 2 + i], pfh[kk], vl[b][kk][i * 2], vl[b][kk][i * 2 + 1]);
#pragma unroll
            for (int kk = 0; kk < 4; kk++)
#pragma unroll
                for (int b = 0; b < 2; b++)
#pragma unroll
                    for (int i = 0; i < 2; i++)
                        mma_bf16(oo[(nbp * 2 + b) * 2 + i], pfl[kk], vh[b][kk][i * 2], vh[b][kk][i * 2 + 1]);
        }
        __syncthreads();
    }

    // Epilogue: normalize, split hi/lo, store
    float inv0 = 1.0f / l0, inv1 = 1.0f / l1;
    const int er = lane >> 2;
    const int ec = (lane & 3) * 2;
#pragma unroll
    for (int ni = 0; ni < 8; ni++) {
        int r = n * LSEQ + q0 + wid * 16 + er;
        int c = h * HD + ni * 8 + ec;
        float v00 = oo[ni][0] * inv0, v01 = oo[ni][1] * inv0;
        float v10 = oo[ni][2] * inv1, v11 = oo[ni][3] * inv1;
        float h00 = __bfloat162float(__float2bfloat16(v00));
        float h01 = __bfloat162float(__float2bfloat16(v01));
        float h10 = __bfloat162float(__float2bfloat16(v10));
        float h11 = __bfloat162float(__float2bfloat16(v11));
        *(uint32_t*)&g_ahi[(size_t)r * EMB + c]       = pack_bf16x2(h00, h01);
        *(uint32_t*)&g_ahi[(size_t)(r + 8) * EMB + c] = pack_bf16x2(h10, h11);
        *(uint32_t*)&g_alo[(size_t)r * EMB + c]       = pack_bf16x2(v00 - h00, v01 - h01);
        *(uint32_t*)&g_alo[(size_t)(r + 8) * EMB + c] = pack_bf16x2(v10 - h10, v11 - h11);
    }
}

// ---------------------------------------------------------------------------
// Launch
// ---------------------------------------------------------------------------
extern "C" void kernel_launch(void* const* d_in, const int* in_sizes, int n_in,
                              void* d_out, int out_size)
{
    const float* Q  = (const float*)d_in[0];
    const float* K  = (const float*)d_in[1];
    const float* V  = (const float*)d_in[2];
    const float* Wq = (const float*)d_in[3];
    const float* bq = (const float*)d_in[4];
    const float* Wk = (const float*)d_in[5];
    const float* bk = (const float*)d_in[6];
    const float* Wv = (const float*)d_in[7];
    const float* bv = (const float*)d_in[8];
    const float* Wo = (const float*)d_in[9];
    const float* bo = (const float*)d_in[10];
    float* out = (float*)d_out;

    __nv_bfloat16 *sqhi, *sqlo, *skhi, *sklo, *svhi, *svlo;
    __nv_bfloat16 *wqhi, *wqlo, *wkhi, *wklo, *wvhi, *wvlo, *wohi, *wolo;
    __nv_bfloat16 *qhi, *qlo, *khi, *klo, *vhi, *vlo, *vthi, *vtlo, *ahi, *alo;
    cudaGetSymbolAddress((void**)&sqhi, g_sqhi); cudaGetSymbolAddress((void**)&sqlo, g_sqlo);
    cudaGetSymbolAddress((void**)&skhi, g_skhi); cudaGetSymbolAddress((void**)&sklo, g_sklo);
    cudaGetSymbolAddress((void**)&svhi, g_svhi); cudaGetSymbolAddress((void**)&svlo, g_svlo);
    cudaGetSymbolAddress((void**)&wqhi, g_wqhi); cudaGetSymbolAddress((void**)&wqlo, g_wqlo);
    cudaGetSymbolAddress((void**)&wkhi, g_wkhi); cudaGetSymbolAddress((void**)&wklo, g_wklo);
    cudaGetSymbolAddress((void**)&wvhi, g_wvhi); cudaGetSymbolAddress((void**)&wvlo, g_wvlo);
    cudaGetSymbolAddress((void**)&wohi, g_wohi); cudaGetSymbolAddress((void**)&wolo, g_wolo);
    cudaGetSymbolAddress((void**)&qhi,  g_qhi);  cudaGetSymbolAddress((void**)&qlo,  g_qlo);
    cudaGetSymbolAddress((void**)&khi,  g_khi);  cudaGetSymbolAddress((void**)&klo,  g_klo);
    cudaGetSymbolAddress((void**)&vhi,  g_vhi);  cudaGetSymbolAddress((void**)&vlo,  g_vlo);
    cudaGetSymbolAddress((void**)&vthi, g_vthi); cudaGetSymbolAddress((void**)&vtlo, g_vtlo);
    cudaGetSymbolAddress((void**)&ahi,  g_ahi);  cudaGetSymbolAddress((void**)&alo,  g_alo);

    cudaFuncSetAttribute(gemm_qkv_kernel,   cudaFuncAttributeMaxDynamicSharedMemorySize, GSMEM);
    cudaFuncSetAttribute(gemm_final_kernel, cudaFuncAttributeMaxDynamicSharedMemorySize, GSMEM);
    cudaFuncSetAttribute(attn_mma_kernel,   cudaFuncAttributeMaxDynamicSharedMemorySize, ASMEM);

    const int nA4 = MROWS * EMB / 4;
    const int nW4 = EMB * EMB / 4;

    // Split all inputs + weights (2 launches)
    SplitB3 s3;
    s3.in[0] = Q; s3.in[1] = K; s3.in[2] = V;
    s3.hi[0] = sqhi; s3.hi[1] = skhi; s3.hi[2] = svhi;
    s3.lo[0] = sqlo; s3.lo[1] = sklo; s3.lo[2] = svlo;
    split3_kernel<<<dim3(nA4 / 256, 3), 256>>>(s3, nA4);

    SplitB4 s4;
    s4.in[0] = Wq; s4.in[1] = Wk; s4.in[2] = Wv; s4.in[3] = Wo;
    s4.hi[0] = wqhi; s4.hi[1] = wkhi; s4.hi[2] = wvhi; s4.hi[3] = wohi;
    s4.lo[0] = wqlo; s4.lo[1] = wklo; s4.lo[2] = wvlo; s4.lo[3] = wolo;
    split4_kernel<<<dim3(nW4 / 256, 4), 256>>>(s4, nW4);

    // Q/K/V projections in one batched launch
    GemmQKV gp;
    gp.Ahi[0] = sqhi; gp.Alo[0] = sqlo; gp.Whi[0] = wqhi; gp.Wlo[0] = wqlo; gp.bias[0] = bq; gp.Chi[0] = qhi; gp.Clo[0] = qlo;
    gp.Ahi[1] = skhi; gp.Alo[1] = sklo; gp.Whi[1] = wkhi; gp.Wlo[1] = wklo; gp.bias[1] = bk; gp.Chi[1] = khi; gp.Clo[1] = klo;
    gp.Ahi[2] = svhi; gp.Alo[2] = svlo; gp.Whi[2] = wvhi; gp.Wlo[2] = wvlo; gp.bias[2] = bv; gp.Chi[2] = vhi; gp.Clo[2] = vlo;
    gemm_qkv_kernel<<<dim3(EMB / 128, MROWS / 128, 3), 256, GSMEM>>>(gp);

    // V transpose
    vt_kernel<<<dim3(LSEQ / 32, HD / 32, NB * NH), 256>>>(vhi, vlo, vthi, vtlo);

    // Attention (writes g_ahi/g_alo)
    attn_mma_kernel<<<dim3(LSEQ / 128, NH, NB), 256, ASMEM>>>();

    // Output projection
    gemm_final_kernel<<<dim3(EMB / 128, MROWS / 128), 256, GSMEM>>>(ahi, alo, wohi, wolo, bo, out);
}

// round 8
// speedup vs baseline: 5.4133x; 1.4482x over previous
#include <cuda_runtime.h>
#include <cuda_bf16.h>
#include <cuda_fp16.h>
#include <cstdint>

// Problem constants
#define NB    4
#define LSEQ  2048
#define EMB   1024
#define NH    16
#define HD    64
#define MROWS (NB * LSEQ)   // 8192

// Scratch (static device arrays — no allocation allowed)
// Input splits (A-side) for Q/K/V projections (bf16 3-term GEMM)
__device__ __nv_bfloat16 g_sqhi[MROWS * EMB];
__device__ __nv_bfloat16 g_sqlo[MROWS * EMB];
__device__ __nv_bfloat16 g_skhi[MROWS * EMB];
__device__ __nv_bfloat16 g_sklo[MROWS * EMB];
__device__ __nv_bfloat16 g_svhi[MROWS * EMB];
__device__ __nv_bfloat16 g_svlo[MROWS * EMB];
// Weight splits
__device__ __nv_bfloat16 g_wqhi[EMB * EMB];
__device__ __nv_bfloat16 g_wqlo[EMB * EMB];
__device__ __nv_bfloat16 g_wkhi[EMB * EMB];
__device__ __nv_bfloat16 g_wklo[EMB * EMB];
__device__ __nv_bfloat16 g_wvhi[EMB * EMB];
__device__ __nv_bfloat16 g_wvlo[EMB * EMB];
__device__ __nv_bfloat16 g_wohi[EMB * EMB];
__device__ __nv_bfloat16 g_wolo[EMB * EMB];
// Projection outputs: fp16 single precision (attention operands)
__device__ __half g_q16[MROWS * EMB];
__device__ __half g_k16[MROWS * EMB];
__device__ __half g_v16[MROWS * EMB];
__device__ __half g_vt16[MROWS * EMB];   // transposed: [(n*16+h)*64+d][j]
// Attention output (bf16 hi/lo split for O-projection)
__device__ __nv_bfloat16 g_ahi[MROWS * EMB];
__device__ __nv_bfloat16 g_alo[MROWS * EMB];

// ---------------------------------------------------------------------------
// Warp-level tensor-core + async-copy primitives (baseline ISA on compute_103)
// ---------------------------------------------------------------------------
__device__ __forceinline__ uint32_t smem_u32(const void* p) {
    uint32_t a;
    asm("{ .reg .u64 t; cvta.to.shared.u64 t, %1; cvt.u32.u64 %0, t; }" : "=r"(a) : "l"(p));
    return a;
}

__device__ __forceinline__ void ldsm_x4(uint32_t* r, uint32_t addr) {
    asm volatile("ldmatrix.sync.aligned.m8n8.x4.shared.b16 {%0,%1,%2,%3}, [%4];"
        : "=r"(r[0]), "=r"(r[1]), "=r"(r[2]), "=r"(r[3]) : "r"(addr));
}

__device__ __forceinline__ void mma_bf16(float* d, const uint32_t* a, uint32_t b0, uint32_t b1) {
    asm volatile(
        "mma.sync.aligned.m16n8k16.row.col.f32.bf16.bf16.f32 "
        "{%0,%1,%2,%3}, {%4,%5,%6,%7}, {%8,%9}, {%0,%1,%2,%3};"
        : "+f"(d[0]), "+f"(d[1]), "+f"(d[2]), "+f"(d[3])
        : "r"(a[0]), "r"(a[1]), "r"(a[2]), "r"(a[3]), "r"(b0), "r"(b1));
}

__device__ __forceinline__ void mma_f16(float* d, const uint32_t* a, uint32_t b0, uint32_t b1) {
    asm volatile(
        "mma.sync.aligned.m16n8k16.row.col.f32.f16.f16.f32 "
        "{%0,%1,%2,%3}, {%4,%5,%6,%7}, {%8,%9}, {%0,%1,%2,%3};"
        : "+f"(d[0]), "+f"(d[1]), "+f"(d[2]), "+f"(d[3])
        : "r"(a[0]), "r"(a[1]), "r"(a[2]), "r"(a[3]), "r"(b0), "r"(b1));
}

__device__ __forceinline__ uint32_t pack_bf16x2(float lo, float hi) {
    __nv_bfloat162 p = __float22bfloat162_rn(make_float2(lo, hi));
    return *(uint32_t*)&p;
}

__device__ __forceinline__ uint32_t pack_f16x2(float lo, float hi) {
    __half2 p = __floats2half2_rn(lo, hi);
    return *(uint32_t*)&p;
}

__device__ __forceinline__ void cp_async16(uint32_t saddr, const void* g) {
    asm volatile("cp.async.cg.shared.global [%0], [%1], 16;" :: "r"(saddr), "l"(g));
}
#define CP_COMMIT() asm volatile("cp.async.commit_group;")
#define CP_WAIT1()  asm volatile("cp.async.wait_group 1;")

// ---------------------------------------------------------------------------
// Batched fp32 -> bf16 hi/lo splits
// ---------------------------------------------------------------------------
struct SplitB3 { const float* in[3]; __nv_bfloat16* hi[3]; __nv_bfloat16* lo[3]; };
struct SplitB4 { const float* in[4]; __nv_bfloat16* hi[4]; __nv_bfloat16* lo[4]; };

__device__ __forceinline__ void split_body(const float* __restrict__ in,
                                           __nv_bfloat16* __restrict__ hi,
                                           __nv_bfloat16* __restrict__ lo, int i)
{
    float4 x = ((const float4*)in)[i];
    __nv_bfloat16 h0 = __float2bfloat16(x.x), h1 = __float2bfloat16(x.y);
    __nv_bfloat16 h2 = __float2bfloat16(x.z), h3 = __float2bfloat16(x.w);
    __nv_bfloat16 l0 = __float2bfloat16(x.x - __bfloat162float(h0));
    __nv_bfloat16 l1 = __float2bfloat16(x.y - __bfloat162float(h1));
    __nv_bfloat16 l2 = __float2bfloat16(x.z - __bfloat162float(h2));
    __nv_bfloat16 l3 = __float2bfloat16(x.w - __bfloat162float(h3));
    ((__nv_bfloat162*)hi)[i * 2 + 0] = __nv_bfloat162(h0, h1);
    ((__nv_bfloat162*)hi)[i * 2 + 1] = __nv_bfloat162(h2, h3);
    ((__nv_bfloat162*)lo)[i * 2 + 0] = __nv_bfloat162(l0, l1);
    ((__nv_bfloat162*)lo)[i * 2 + 1] = __nv_bfloat162(l2, l3);
}

__global__ __launch_bounds__(256) void split3_kernel(SplitB3 P, int n4)
{
    int i = blockIdx.x * 256 + threadIdx.x;
    int z = blockIdx.y;
    if (i >= n4) return;
    split_body(P.in[z], P.hi[z], P.lo[z], i);
}

__global__ __launch_bounds__(256) void split4_kernel(SplitB4 P, int n4)
{
    int i = blockIdx.x * 256 + threadIdx.x;
    int z = blockIdx.y;
    if (i >= n4) return;
    split_body(P.in[z], P.hi[z], P.lo[z], i);
}

// ---------------------------------------------------------------------------
// HMMA GEMM body: C = A @ W^T + bias, 3-term bf16 split, cp.async 2-stage.
// OM=0: fp32 output. OM=2: fp16 single output (attention operands).
// ---------------------------------------------------------------------------
#define BK    32
#define TSTR  40
#define GTILE (128 * TSTR)
#define GSTAGE_B (4 * GTILE * 2)
#define GSMEM (2 * GSTAGE_B)   // 81920

template <int OM>
__device__ __forceinline__ void gemm_body(
    const __nv_bfloat16* __restrict__ Ahi, const __nv_bfloat16* __restrict__ Alo,
    const __nv_bfloat16* __restrict__ Whi, const __nv_bfloat16* __restrict__ Wlo,
    const float* __restrict__ bias, void* __restrict__ Cout,
    __nv_bfloat16* dsm)
{
    const int tid  = threadIdx.x;
    const int wid  = tid >> 5;
    const int lane = tid & 31;
    const int wm   = wid >> 2;
    const int wn   = wid & 3;
    const int row0 = blockIdx.y * 128;
    const int col0 = blockIdx.x * 128;

    const uint32_t uS = smem_u32(dsm);
    const uint32_t aLane = (uint32_t)(((lane & 15) * TSTR + (lane >> 4) * 8) * 2);
    const uint32_t bLane = (uint32_t)(((((lane >> 4) << 3) + (lane & 7)) * TSTR + ((lane >> 3) & 1) * 8) * 2);

    const int lr0 = tid >> 2,         lc0 = tid & 3;
    const int lr1 = (tid + 256) >> 2, lc1 = (tid + 256) & 3;
    const uint32_t sd0 = (uint32_t)((lr0 * TSTR + lc0 * 8) * 2);
    const uint32_t sd1 = (uint32_t)((lr1 * TSTR + lc1 * 8) * 2);

    auto load_stage = [&](int s, int kt) {
        uint32_t base = uS + (uint32_t)(s * GSTAGE_B);
        size_t ga0 = (size_t)(row0 + lr0) * EMB + kt + lc0 * 8;
        size_t gw0 = (size_t)(col0 + lr0) * EMB + kt + lc0 * 8;
        size_t ga1 = (size_t)(row0 + lr1) * EMB + kt + lc1 * 8;
        size_t gw1 = (size_t)(col0 + lr1) * EMB + kt + lc1 * 8;
        cp_async16(base + sd0,                 &Ahi[ga0]);
        cp_async16(base + GTILE * 2 + sd0,     &Alo[ga0]);
        cp_async16(base + 2 * GTILE * 2 + sd0, &Whi[gw0]);
        cp_async16(base + 3 * GTILE * 2 + sd0, &Wlo[gw0]);
        cp_async16(base + sd1,                 &Ahi[ga1]);
        cp_async16(base + GTILE * 2 + sd1,     &Alo[ga1]);
        cp_async16(base + 2 * GTILE * 2 + sd1, &Whi[gw1]);
        cp_async16(base + 3 * GTILE * 2 + sd1, &Wlo[gw1]);
    };

    float acc[4][4][4];
#pragma unroll
    for (int mi = 0; mi < 4; mi++)
#pragma unroll
        for (int ni = 0; ni < 4; ni++)
#pragma unroll
            for (int r = 0; r < 4; r++) acc[mi][ni][r] = 0.0f;

    load_stage(0, 0);
    CP_COMMIT();

    for (int t = 0; t < EMB / BK; t++) {
        if (t + 1 < EMB / BK) load_stage((t + 1) & 1, (t + 1) * BK);
        CP_COMMIT();
        CP_WAIT1();
        __syncthreads();

        const uint32_t uAhi = uS + (uint32_t)((t & 1) * GSTAGE_B);
        const uint32_t uAlo = uAhi + GTILE * 2;
        const uint32_t uBhi = uAhi + 2 * GTILE * 2;
        const uint32_t uBlo = uAhi + 3 * GTILE * 2;

#pragma unroll
        for (int ks = 0; ks < 2; ks++) {
            uint32_t bh[2][4], bl[2][4];
#pragma unroll
            for (int nb = 0; nb < 2; nb++) {
                uint32_t boff = (uint32_t)(((wn * 32 + nb * 16) * TSTR + ks * 16) * 2) + bLane;
                ldsm_x4(bh[nb], uBhi + boff);
                ldsm_x4(bl[nb], uBlo + boff);
            }
#pragma unroll
            for (int mi = 0; mi < 4; mi++) {
                uint32_t aoff = (uint32_t)(((wm * 64 + mi * 16) * TSTR + ks * 16) * 2) + aLane;
                uint32_t ah[4], al[4];
                ldsm_x4(ah, uAhi + aoff);
                ldsm_x4(al, uAlo + aoff);
#pragma unroll
                for (int ni = 0; ni < 4; ni++)
                    mma_bf16(acc[mi][ni], ah, bh[ni >> 1][(ni & 1) * 2], bh[ni >> 1][(ni & 1) * 2 + 1]);
#pragma unroll
                for (int ni = 0; ni < 4; ni++)
                    mma_bf16(acc[mi][ni], ah, bl[ni >> 1][(ni & 1) * 2], bl[ni >> 1][(ni & 1) * 2 + 1]);
#pragma unroll
                for (int ni = 0; ni < 4; ni++)
                    mma_bf16(acc[mi][ni], al, bh[ni >> 1][(ni & 1) * 2], bh[ni >> 1][(ni & 1) * 2 + 1]);
            }
        }
        __syncthreads();
    }

    const int er = lane >> 2;
    const int ec = (lane & 3) * 2;
#pragma unroll
    for (int mi = 0; mi < 4; mi++) {
#pragma unroll
        for (int ni = 0; ni < 4; ni++) {
            int r = row0 + wm * 64 + mi * 16 + er;
            int c = col0 + wn * 32 + ni * 8 + ec;
            float b0 = bias[c], b1 = bias[c + 1];
            float v00 = acc[mi][ni][0] + b0, v01 = acc[mi][ni][1] + b1;
            float v10 = acc[mi][ni][2] + b0, v11 = acc[mi][ni][3] + b1;
            if (OM == 0) {
                float* C = (float*)Cout;
                *(float2*)&C[(size_t)r * EMB + c] = make_float2(v00, v01);
                *(float2*)&C[(size_t)(r + 8) * EMB + c] = make_float2(v10, v11);
            } else {
                __half* C = (__half*)Cout;
                *(uint32_t*)&C[(size_t)r * EMB + c]       = pack_f16x2(v00, v01);
                *(uint32_t*)&C[(size_t)(r + 8) * EMB + c] = pack_f16x2(v10, v11);
            }
        }
    }
}

struct GemmQKV {
    const __nv_bfloat16 *Ahi[3], *Alo[3], *Whi[3], *Wlo[3];
    const float* bias[3];
    __half* Cout[3];
};

__global__ __launch_bounds__(256, 2) void gemm_qkv_kernel(GemmQKV P)
{
    extern __shared__ __align__(16) __nv_bfloat16 dsm[];
    const int z = blockIdx.z;
    gemm_body<2>(P.Ahi[z], P.Alo[z], P.Whi[z], P.Wlo[z], P.bias[z], P.Cout[z], dsm);
}

__global__ __launch_bounds__(256, 2) void gemm_final_kernel(
    const __nv_bfloat16* __restrict__ Ahi, const __nv_bfloat16* __restrict__ Alo,
    const __nv_bfloat16* __restrict__ Whi, const __nv_bfloat16* __restrict__ Wlo,
    const float* __restrict__ bias, float* __restrict__ Cout)
{
    extern __shared__ __align__(16) __nv_bfloat16 dsm[];
    gemm_body<0>(Ahi, Alo, Whi, Wlo, bias, Cout, dsm);
}

// ---------------------------------------------------------------------------
// V transpose (fp16): [n*2048+j][h*64+d] -> [(n*16+h)*64+d][j]
// ---------------------------------------------------------------------------
__global__ __launch_bounds__(256) void vt_kernel(
    const __half* __restrict__ v16, __half* __restrict__ vt16)
{
    __shared__ __half th[32][33];
    const int tx = threadIdx.x & 31;
    const int ty = threadIdx.x >> 5;
    const int j0 = blockIdx.x * 32;
    const int d0 = blockIdx.y * 32;
    const int nh = blockIdx.z;
    const int n  = nh >> 4;
    const int h  = nh & 15;

#pragma unroll
    for (int k = 0; k < 4; k++) {
        int j = j0 + ty + 8 * k;
        th[ty + 8 * k][tx] = v16[(size_t)(n * LSEQ + j) * EMB + h * HD + d0 + tx];
    }
    __syncthreads();
#pragma unroll
    for (int k = 0; k < 4; k++) {
        int d = d0 + ty + 8 * k;
        vt16[(size_t)(nh * HD + d) * LSEQ + j0 + tx] = th[tx][ty + 8 * k];
    }
}

// ---------------------------------------------------------------------------
// Tensor-core flash attention: fp16 single-pass QK and PV, fp32 softmax/accum.
// Smem: 2 stages x (K + V) x 64 x ATSTR fp16 = 36864 B -> 2 CTAs/SM.
// ---------------------------------------------------------------------------
#define ATSTR 72
#define ATILE_B (64 * ATSTR * 2)       // 9216
#define ASTAGE_B (2 * ATILE_B)         // 18432
#define ASMEM (2 * ASTAGE_B)           // 36864

__global__ __launch_bounds__(256, 2) void attn_mma_kernel()
{
    extern __shared__ __align__(16) __half asm_buf[];

    const int tid  = threadIdx.x;
    const int wid  = tid >> 5;
    const int lane = tid & 31;
    const int q0 = blockIdx.x * 128;
    const int h  = blockIdx.y;
    const int n  = blockIdx.z;

    const uint32_t uS = smem_u32(asm_buf);
    const uint32_t aLane = (uint32_t)(((lane & 15) * ATSTR + (lane >> 4) * 8) * 2);
    const uint32_t bLane = (uint32_t)(((((lane >> 4) << 3) + (lane & 7)) * ATSTR + ((lane >> 3) & 1) * 8) * 2);

    const int kr0 = tid >> 3,         kc0 = tid & 7;
    const int kr1 = (tid + 256) >> 3, kc1 = (tid + 256) & 7;
    const uint32_t ksd0 = (uint32_t)((kr0 * ATSTR + kc0 * 8) * 2);
    const uint32_t ksd1 = (uint32_t)((kr1 * ATSTR + kc1 * 8) * 2);

    auto load_kv = [&](int s, int kt) {
        uint32_t base = uS + (uint32_t)(s * ASTAGE_B);
        size_t kb0 = (size_t)(n * LSEQ + kt + kr0) * EMB + h * HD + kc0 * 8;
        size_t vb0 = (size_t)((n * NH + h) * HD + kr0) * LSEQ + kt + kc0 * 8;
        size_t kb1 = (size_t)(n * LSEQ + kt + kr1) * EMB + h * HD + kc1 * 8;
        size_t vb1 = (size_t)((n * NH + h) * HD + kr1) * LSEQ + kt + kc1 * 8;
        cp_async16(base + ksd0,           &g_k16[kb0]);
        cp_async16(base + ATILE_B + ksd0, &g_vt16[vb0]);
        cp_async16(base + ksd1,           &g_k16[kb1]);
        cp_async16(base + ATILE_B + ksd1, &g_vt16[vb1]);
    };

    // Phase 1: load Q (scaled by 1/8) into stage 0, hoist fragments
    const __half2 sc2 = __floats2half2_rn(0.125f, 0.125f);
#pragma unroll
    for (int i = 0; i < 2; i++) {
        int idx = tid + i * 256;           // 0..511
        int r = idx >> 2;                  // 0..127
        int c = idx & 3;                   // 4 chunks of 16B = 32 halfs... (8 halfs per chunk)
        // 128 rows x 64 halfs = 8192 halfs = 1024 16B chunks; 512 threads*2 -> 2 chunks each
        int cc = c * 2;                    // chunk pair start
#pragma unroll
        for (int u = 0; u < 2; u++) {
            size_t src = (size_t)(n * LSEQ + q0 + r) * EMB + h * HD + (cc + u) * 8;
            int4 v = *(const int4*)&g_q16[src];
            __half2* p = (__half2*)&v;
#pragma unroll
            for (int z = 0; z < 4; z++) p[z] = __hmul2(p[z], sc2);
            *(int4*)&asm_buf[r * ATSTR + (cc + u) * 8] = v;
        }
    }
    __syncthreads();

    uint32_t qf[4][4];
#pragma unroll
    for (int kk = 0; kk < 4; kk++)
        ldsm_x4(qf[kk], uS + (uint32_t)((wid * 16 * ATSTR + kk * 16) * 2) + aLane);
    __syncthreads();   // Q frags in regs; stage 0 reusable

    float oo[8][4];
#pragma unroll
    for (int ni = 0; ni < 8; ni++)
#pragma unroll
        for (int r = 0; r < 4; r++) oo[ni][r] = 0.0f;
    float m0 = -1e30f, m1 = -1e30f, l0 = 0.0f, l1 = 0.0f;

    load_kv(0, 0);
    CP_COMMIT();

    for (int t = 0; t < LSEQ / 64; t++) {
        if (t + 1 < LSEQ / 64) load_kv((t + 1) & 1, (t + 1) * 64);
        CP_COMMIT();
        CP_WAIT1();
        __syncthreads();

        const uint32_t oK = uS + (uint32_t)((t & 1) * ASTAGE_B);
        const uint32_t oV = oK + ATILE_B;

        // S = Q @ K^T (fp16 single pass)
        float sS[8][4];
#pragma unroll
        for (int ni = 0; ni < 8; ni++)
#pragma unroll
            for (int r = 0; r < 4; r++) sS[ni][r] = 0.0f;
#pragma unroll
        for (int nb = 0; nb < 4; nb++) {
            uint32_t kf[4][4];
#pragma unroll
            for (int kk = 0; kk < 4; kk++)
                ldsm_x4(kf[kk], oK + (uint32_t)((nb * 16 * ATSTR + kk * 16) * 2) + bLane);
#pragma unroll
            for (int kk = 0; kk < 4; kk++)
#pragma unroll
                for (int i = 0; i < 2; i++)
                    mma_f16(sS[nb * 2 + i], qf[kk], kf[kk][i * 2], kf[kk][i * 2 + 1]);
        }

        // Online softmax (fp32)
        float mt0 = -1e30f, mt1 = -1e30f;
#pragma unroll
        for (int ni = 0; ni < 8; ni++) {
            mt0 = fmaxf(mt0, fmaxf(sS[ni][0], sS[ni][1]));
            mt1 = fmaxf(mt1, fmaxf(sS[ni][2], sS[ni][3]));
        }
#pragma unroll
        for (int off = 1; off <= 2; off <<= 1) {
            mt0 = fmaxf(mt0, __shfl_xor_sync(0xffffffffu, mt0, off));
            mt1 = fmaxf(mt1, __shfl_xor_sync(0xffffffffu, mt1, off));
        }
        float mn0 = fmaxf(m0, mt0), mn1 = fmaxf(m1, mt1);
        float c0 = __expf(m0 - mn0), c1 = __expf(m1 - mn1);

        uint32_t pf[4][4];
        float s0 = 0.0f, s1 = 0.0f;
#pragma unroll
        for (int ni = 0; ni < 8; ni++) {
            float p0 = __expf(sS[ni][0] - mn0);
            float p1 = __expf(sS[ni][1] - mn0);
            float p2 = __expf(sS[ni][2] - mn1);
            float p3 = __expf(sS[ni][3] - mn1);
            s0 += p0 + p1; s1 += p2 + p3;
            pf[ni >> 1][(ni & 1) * 2 + 0] = pack_f16x2(p0, p1);
            pf[ni >> 1][(ni & 1) * 2 + 1] = pack_f16x2(p2, p3);
        }
#pragma unroll
        for (int off = 1; off <= 2; off <<= 1) {
            s0 += __shfl_xor_sync(0xffffffffu, s0, off);
            s1 += __shfl_xor_sync(0xffffffffu, s1, off);
        }
        l0 = l0 * c0 + s0;
        l1 = l1 * c1 + s1;
        m0 = mn0; m1 = mn1;
#pragma unroll
        for (int ni = 0; ni < 8; ni++) {
            oo[ni][0] *= c0; oo[ni][1] *= c0;
            oo[ni][2] *= c1; oo[ni][3] *= c1;
        }

        // O += P @ V (fp16 single pass)
#pragma unroll
        for (int nbd = 0; nbd < 4; nbd++) {
            uint32_t vf[4][4];
#pragma unroll
            for (int kk = 0; kk < 4; kk++)
                ldsm_x4(vf[kk], oV + (uint32_t)((nbd * 16 * ATSTR + kk * 16) * 2) + bLane);
#pragma unroll
            for (int kk = 0; kk < 4; kk++)
#pragma unroll
                for (int i = 0; i < 2; i++)
                    mma_f16(oo[nbd * 2 + i], pf[kk], vf[kk][i * 2], vf[kk][i * 2 + 1]);
        }
        __syncthreads();
    }

    // Epilogue: normalize, bf16 hi/lo split, store for O-projection
    float inv0 = 1.0f / l0, inv1 = 1.0f / l1;
    const int er = lane >> 2;
    const int ec = (lane & 3) * 2;
#pragma unroll
    for (int ni = 0; ni < 8; ni++) {
        int r = n * LSEQ + q0 + wid * 16 + er;
        int c = h * HD + ni * 8 + ec;
        float v00 = oo[ni][0] * inv0, v01 = oo[ni][1] * inv0;
        float v10 = oo[ni][2] * inv1, v11 = oo[ni][3] * inv1;
        float h00 = __bfloat162float(__float2bfloat16(v00));
        float h01 = __bfloat162float(__float2bfloat16(v01));
        float h10 = __bfloat162float(__float2bfloat16(v10));
        float h11 = __bfloat162float(__float2bfloat16(v11));
        *(uint32_t*)&g_ahi[(size_t)r * EMB + c]       = pack_bf16x2(h00, h01);
        *(uint32_t*)&g_ahi[(size_t)(r + 8) * EMB + c] = pack_bf16x2(h10, h11);
        *(uint32_t*)&g_alo[(size_t)r * EMB + c]       = pack_bf16x2(v00 - h00, v01 - h01);
        *(uint32_t*)&g_alo[(size_t)(r + 8) * EMB + c] = pack_bf16x2(v10 - h10, v11 - h11);
    }
}

// ---------------------------------------------------------------------------
// Launch
// ---------------------------------------------------------------------------
extern "C" void kernel_launch(void* const* d_in, const int* in_sizes, int n_in,
                              void* d_out, int out_size)
{
    const float* Q  = (const float*)d_in[0];
    const float* K  = (const float*)d_in[1];
    const float* V  = (const float*)d_in[2];
    const float* Wq = (const float*)d_in[3];
    const float* bq = (const float*)d_in[4];
    const float* Wk = (const float*)d_in[5];
    const float* bk = (const float*)d_in[6];
    const float* Wv = (const float*)d_in[7];
    const float* bv = (const float*)d_in[8];
    const float* Wo = (const float*)d_in[9];
    const float* bo = (const float*)d_in[10];
    float* out = (float*)d_out;

    __nv_bfloat16 *sqhi, *sqlo, *skhi, *sklo, *svhi, *svlo;
    __nv_bfloat16 *wqhi, *wqlo, *wkhi, *wklo, *wvhi, *wvlo, *wohi, *wolo;
    __nv_bfloat16 *ahi, *alo;
    __half *q16, *k16, *v16, *vt16;
    cudaGetSymbolAddress((void**)&sqhi, g_sqhi); cudaGetSymbolAddress((void**)&sqlo, g_sqlo);
    cudaGetSymbolAddress((void**)&skhi, g_skhi); cudaGetSymbolAddress((void**)&sklo, g_sklo);
    cudaGetSymbolAddress((void**)&svhi, g_svhi); cudaGetSymbolAddress((void**)&svlo, g_svlo);
    cudaGetSymbolAddress((void**)&wqhi, g_wqhi); cudaGetSymbolAddress((void**)&wqlo, g_wqlo);
    cudaGetSymbolAddress((void**)&wkhi, g_wkhi); cudaGetSymbolAddress((void**)&wklo, g_wklo);
    cudaGetSymbolAddress((void**)&wvhi, g_wvhi); cudaGetSymbolAddress((void**)&wvlo, g_wvlo);
    cudaGetSymbolAddress((void**)&wohi, g_wohi); cudaGetSymbolAddress((void**)&wolo, g_wolo);
    cudaGetSymbolAddress((void**)&q16,  g_q16);  cudaGetSymbolAddress((void**)&k16,  g_k16);
    cudaGetSymbolAddress((void**)&v16,  g_v16);  cudaGetSymbolAddress((void**)&vt16, g_vt16);
    cudaGetSymbolAddress((void**)&ahi,  g_ahi);  cudaGetSymbolAddress((void**)&alo,  g_alo);

    cudaFuncSetAttribute(gemm_qkv_kernel,   cudaFuncAttributeMaxDynamicSharedMemorySize, GSMEM);
    cudaFuncSetAttribute(gemm_final_kernel, cudaFuncAttributeMaxDynamicSharedMemorySize, GSMEM);
    cudaFuncSetAttribute(attn_mma_kernel,   cudaFuncAttributeMaxDynamicSharedMemorySize, ASMEM);

    const int nA4 = MROWS * EMB / 4;
    const int nW4 = EMB * EMB / 4;

    // Split inputs + weights (2 launches)
    SplitB3 s3;
    s3.in[0] = Q; s3.in[1] = K; s3.in[2] = V;
    s3.hi[0] = sqhi; s3.hi[1] = skhi; s3.hi[2] = svhi;
    s3.lo[0] = sqlo; s3.lo[1] = sklo; s3.lo[2] = svlo;
    split3_kernel<<<dim3(nA4 / 256, 3), 256>>>(s3, nA4);

    SplitB4 s4;
    s4.in[0] = Wq; s4.in[1] = Wk; s4.in[2] = Wv; s4.in[3] = Wo;
    s4.hi[0] = wqhi; s4.hi[1] = wkhi; s4.hi[2] = wvhi; s4.hi[3] = wohi;
    s4.lo[0] = wqlo; s4.lo[1] = wklo; s4.lo[2] = wvlo; s4.lo[3] = wolo;
    split4_kernel<<<dim3(nW4 / 256, 4), 256>>>(s4, nW4);

    // Q/K/V projections (bf16 3-term, fp16 output) in one batched launch
    GemmQKV gp;
    gp.Ahi[0] = sqhi; gp.Alo[0] = sqlo; gp.Whi[0] = wqhi; gp.Wlo[0] = wqlo; gp.bias[0] = bq; gp.Cout[0] = q16;
    gp.Ahi[1] = skhi; gp.Alo[1] = sklo; gp.Whi[1] = wkhi; gp.Wlo[1] = wklo; gp.bias[1] = bk; gp.Cout[1] = k16;
    gp.Ahi[2] = svhi; gp.Alo[2] = svlo; gp.Whi[2] = wvhi; gp.Wlo[2] = wvlo; gp.bias[2] = bv; gp.Cout[2] = v16;
    gemm_qkv_kernel<<<dim3(EMB / 128, MROWS / 128, 3), 256, GSMEM>>>(gp);

    // V transpose (fp16)
    vt_kernel<<<dim3(LSEQ / 32, HD / 32, NB * NH), 256>>>(v16, vt16);

    // Attention (fp16 single-pass; writes g_ahi/g_alo)
    attn_mma_kernel<<<dim3(LSEQ / 128, NH, NB), 256, ASMEM>>>();

    // Output projection (bf16 3-term, fp32 out)
    gemm_final_kernel<<<dim3(EMB / 128, MROWS / 128), 256, GSMEM>>>(ahi, alo, wohi, wolo, bo, out);
}

// round 9
// speedup vs baseline: 6.7981x; 1.2558x over previous
#include <cuda_runtime.h>
#include <cuda_bf16.h>
#include <cuda_fp16.h>
#include <cstdint>

// Problem constants
#define NB    4
#define LSEQ  2048
#define EMB   1024
#define NH    16
#define HD    64
#define MROWS (NB * LSEQ)   // 8192

// Scratch (static device arrays — no allocation allowed)
// fp16 A-side inputs for Q/K/V projections
__device__ __half g_xq16[MROWS * EMB];
__device__ __half g_xk16[MROWS * EMB];
__device__ __half g_xv16[MROWS * EMB];
// Weight splits: fp16 hi/lo of (W * 2^10)
__device__ __half g_wqhi[EMB * EMB];
__device__ __half g_wqlo[EMB * EMB];
__device__ __half g_wkhi[EMB * EMB];
__device__ __half g_wklo[EMB * EMB];
__device__ __half g_wvhi[EMB * EMB];
__device__ __half g_wvlo[EMB * EMB];
__device__ __half g_wohi[EMB * EMB];
__device__ __half g_wolo[EMB * EMB];
// Projection outputs (fp16, attention operands)
__device__ __half g_q16[MROWS * EMB];
__device__ __half g_k16[MROWS * EMB];
__device__ __half g_v16[MROWS * EMB];
__device__ __half g_vt16[MROWS * EMB];   // transposed: [(n*16+h)*64+d][j]
// Attention output (fp16, A-side of O-projection)
__device__ __half g_a16[MROWS * EMB];

// ---------------------------------------------------------------------------
// Warp-level tensor-core + async-copy primitives (baseline ISA on compute_103)
// ---------------------------------------------------------------------------
__device__ __forceinline__ uint32_t smem_u32(const void* p) {
    uint32_t a;
    asm("{ .reg .u64 t; cvta.to.shared.u64 t, %1; cvt.u32.u64 %0, t; }" : "=r"(a) : "l"(p));
    return a;
}

__device__ __forceinline__ void ldsm_x4(uint32_t* r, uint32_t addr) {
    asm volatile("ldmatrix.sync.aligned.m8n8.x4.shared.b16 {%0,%1,%2,%3}, [%4];"
        : "=r"(r[0]), "=r"(r[1]), "=r"(r[2]), "=r"(r[3]) : "r"(addr));
}

__device__ __forceinline__ void mma_f16(float* d, const uint32_t* a, uint32_t b0, uint32_t b1) {
    asm volatile(
        "mma.sync.aligned.m16n8k16.row.col.f32.f16.f16.f32 "
        "{%0,%1,%2,%3}, {%4,%5,%6,%7}, {%8,%9}, {%0,%1,%2,%3};"
        : "+f"(d[0]), "+f"(d[1]), "+f"(d[2]), "+f"(d[3])
        : "r"(a[0]), "r"(a[1]), "r"(a[2]), "r"(a[3]), "r"(b0), "r"(b1));
}

__device__ __forceinline__ uint32_t pack_f16x2(float lo, float hi) {
    __half2 p = __floats2half2_rn(lo, hi);
    return *(uint32_t*)&p;
}

__device__ __forceinline__ void cp_async16(uint32_t saddr, const void* g) {
    asm volatile("cp.async.cg.shared.global [%0], [%1], 16;" :: "r"(saddr), "l"(g));
}
#define CP_COMMIT() asm volatile("cp.async.commit_group;")
#define CP_WAIT1()  asm volatile("cp.async.wait_group 1;")

// ---------------------------------------------------------------------------
// fp32 -> fp16 convert (batched, 3 tensors)
// ---------------------------------------------------------------------------
struct Cvt3 { const float* in[3]; __half* out[3]; };

__global__ __launch_bounds__(256) void cvt3_kernel(Cvt3 P, int n4)
{
    int i = blockIdx.x * 256 + threadIdx.x;
    int z = blockIdx.y;
    if (i >= n4) return;
    float4 x = ((const float4*)P.in[z])[i];
    uint2 o;
    o.x = pack_f16x2(x.x, x.y);
    o.y = pack_f16x2(x.z, x.w);
    ((uint2*)P.out[z])[i] = o;
}

// ---------------------------------------------------------------------------
// Weight split: W -> fp16 hi/lo of (W * 1024)  (keeps lo in normal fp16 range)
// ---------------------------------------------------------------------------
struct WSplit4 { const float* in[4]; __half* hi[4]; __half* lo[4]; };

__global__ __launch_bounds__(256) void wsplit4_kernel(WSplit4 P, int n4)
{
    int i = blockIdx.x * 256 + threadIdx.x;
    int z = blockIdx.y;
    if (i >= n4) return;
    float4 x = ((const float4*)P.in[z])[i];
    x.x *= 1024.0f; x.y *= 1024.0f; x.z *= 1024.0f; x.w *= 1024.0f;
    __half h0 = __float2half_rn(x.x), h1 = __float2half_rn(x.y);
    __half h2 = __float2half_rn(x.z), h3 = __float2half_rn(x.w);
    __half l0 = __float2half_rn(x.x - __half2float(h0));
    __half l1 = __float2half_rn(x.y - __half2float(h1));
    __half l2 = __float2half_rn(x.z - __half2float(h2));
    __half l3 = __float2half_rn(x.w - __half2float(h3));
    uint2 oh, ol;
    oh.x = *(uint32_t*)&__halves2half2(h0, h1);
    oh.y = *(uint32_t*)&__halves2half2(h2, h3);
    ol.x = *(uint32_t*)&__halves2half2(l0, l1);
    ol.y = *(uint32_t*)&__halves2half2(l2, l3);
    ((uint2*)P.hi[z])[i] = oh;
    ((uint2*)P.lo[z])[i] = ol;
}

// ---------------------------------------------------------------------------
// HMMA GEMM body: C = A @ W^T + bias.  fp16 2-term: A*Whi' + A*Wlo', epilogue
// multiplies by 2^-10. OM=0: fp32 output. OM=2: fp16 output.
// Smem: 2 stages x 3 tiles x (128 x TSTR) fp16 = 61440 B.
// ---------------------------------------------------------------------------
#define BK    32
#define TSTR  40
#define GTILE (128 * TSTR)
#define GSTAGE_B (3 * GTILE * 2)
#define GSMEM (2 * GSTAGE_B)   // 61440

template <int OM>
__device__ __forceinline__ void gemm_body(
    const __half* __restrict__ A,
    const __half* __restrict__ Whi, const __half* __restrict__ Wlo,
    const float* __restrict__ bias, void* __restrict__ Cout,
    __half* dsm)
{
    const int tid  = threadIdx.x;
    const int wid  = tid >> 5;
    const int lane = tid & 31;
    const int wm   = wid >> 2;
    const int wn   = wid & 3;
    const int row0 = blockIdx.y * 128;
    const int col0 = blockIdx.x * 128;

    const uint32_t uS = smem_u32(dsm);
    const uint32_t aLane = (uint32_t)(((lane & 15) * TSTR + (lane >> 4) * 8) * 2);
    const uint32_t bLane = (uint32_t)(((((lane >> 4) << 3) + (lane & 7)) * TSTR + ((lane >> 3) & 1) * 8) * 2);

    const int lr0 = tid >> 2,         lc0 = tid & 3;
    const int lr1 = (tid + 256) >> 2, lc1 = (tid + 256) & 3;
    const uint32_t sd0 = (uint32_t)((lr0 * TSTR + lc0 * 8) * 2);
    const uint32_t sd1 = (uint32_t)((lr1 * TSTR + lc1 * 8) * 2);

    auto load_stage = [&](int s, int kt) {
        uint32_t base = uS + (uint32_t)(s * GSTAGE_B);
        size_t ga0 = (size_t)(row0 + lr0) * EMB + kt + lc0 * 8;
        size_t gw0 = (size_t)(col0 + lr0) * EMB + kt + lc0 * 8;
        size_t ga1 = (size_t)(row0 + lr1) * EMB + kt + lc1 * 8;
        size_t gw1 = (size_t)(col0 + lr1) * EMB + kt + lc1 * 8;
        cp_async16(base + sd0,                 &A[ga0]);
        cp_async16(base + GTILE * 2 + sd0,     &Whi[gw0]);
        cp_async16(base + 2 * GTILE * 2 + sd0, &Wlo[gw0]);
        cp_async16(base + sd1,                 &A[ga1]);
        cp_async16(base + GTILE * 2 + sd1,     &Whi[gw1]);
        cp_async16(base + 2 * GTILE * 2 + sd1, &Wlo[gw1]);
    };

    float acc[4][4][4];
#pragma unroll
    for (int mi = 0; mi < 4; mi++)
#pragma unroll
        for (int ni = 0; ni < 4; ni++)
#pragma unroll
            for (int r = 0; r < 4; r++) acc[mi][ni][r] = 0.0f;

    load_stage(0, 0);
    CP_COMMIT();

    for (int t = 0; t < EMB / BK; t++) {
        if (t + 1 < EMB / BK) load_stage((t + 1) & 1, (t + 1) * BK);
        CP_COMMIT();
        CP_WAIT1();
        __syncthreads();

        const uint32_t uA   = uS + (uint32_t)((t & 1) * GSTAGE_B);
        const uint32_t uBhi = uA + GTILE * 2;
        const uint32_t uBlo = uA + 2 * GTILE * 2;

#pragma unroll
        for (int ks = 0; ks < 2; ks++) {
            uint32_t bh[2][4], bl[2][4];
#pragma unroll
            for (int nb = 0; nb < 2; nb++) {
                uint32_t boff = (uint32_t)(((wn * 32 + nb * 16) * TSTR + ks * 16) * 2) + bLane;
                ldsm_x4(bh[nb], uBhi + boff);
                ldsm_x4(bl[nb], uBlo + boff);
            }
#pragma unroll
            for (int mi = 0; mi < 4; mi++) {
                uint32_t aoff = (uint32_t)(((wm * 64 + mi * 16) * TSTR + ks * 16) * 2) + aLane;
                uint32_t af[4];
                ldsm_x4(af, uA + aoff);
#pragma unroll
                for (int ni = 0; ni < 4; ni++)
                    mma_f16(acc[mi][ni], af, bh[ni >> 1][(ni & 1) * 2], bh[ni >> 1][(ni & 1) * 2 + 1]);
#pragma unroll
                for (int ni = 0; ni < 4; ni++)
                    mma_f16(acc[mi][ni], af, bl[ni >> 1][(ni & 1) * 2], bl[ni >> 1][(ni & 1) * 2 + 1]);
            }
        }
        __syncthreads();
    }

    const float iw = 1.0f / 1024.0f;   // undo W pre-scale (exact power of 2)
    const int er = lane >> 2;
    const int ec = (lane & 3) * 2;
#pragma unroll
    for (int mi = 0; mi < 4; mi++) {
#pragma unroll
        for (int ni = 0; ni < 4; ni++) {
            int r = row0 + wm * 64 + mi * 16 + er;
            int c = col0 + wn * 32 + ni * 8 + ec;
            float b0 = bias[c], b1 = bias[c + 1];
            float v00 = acc[mi][ni][0] * iw + b0, v01 = acc[mi][ni][1] * iw + b1;
            float v10 = acc[mi][ni][2] * iw + b0, v11 = acc[mi][ni][3] * iw + b1;
            if (OM == 0) {
                float* C = (float*)Cout;
                *(float2*)&C[(size_t)r * EMB + c] = make_float2(v00, v01);
                *(float2*)&C[(size_t)(r + 8) * EMB + c] = make_float2(v10, v11);
            } else {
                __half* C = (__half*)Cout;
                *(uint32_t*)&C[(size_t)r * EMB + c]       = pack_f16x2(v00, v01);
                *(uint32_t*)&C[(size_t)(r + 8) * EMB + c] = pack_f16x2(v10, v11);
            }
        }
    }
}

struct GemmQKV {
    const __half *A[3], *Whi[3], *Wlo[3];
    const float* bias[3];
    __half* Cout[3];
};

__global__ __launch_bounds__(256, 2) void gemm_qkv_kernel(GemmQKV P)
{
    extern __shared__ __align__(16) __half dsm[];
    const int z = blockIdx.z;
    gemm_body<2>(P.A[z], P.Whi[z], P.Wlo[z], P.bias[z], P.Cout[z], dsm);
}

__global__ __launch_bounds__(256, 2) void gemm_final_kernel(
    const __half* __restrict__ A,
    const __half* __restrict__ Whi, const __half* __restrict__ Wlo,
    const float* __restrict__ bias, float* __restrict__ Cout)
{
    extern __shared__ __align__(16) __half dsm[];
    gemm_body<0>(A, Whi, Wlo, bias, Cout, dsm);
}

// ---------------------------------------------------------------------------
// V transpose (fp16): [n*2048+j][h*64+d] -> [(n*16+h)*64+d][j]
// ---------------------------------------------------------------------------
__global__ __launch_bounds__(256) void vt_kernel(
    const __half* __restrict__ v16, __half* __restrict__ vt16)
{
    __shared__ __half th[32][33];
    const int tx = threadIdx.x & 31;
    const int ty = threadIdx.x >> 5;
    const int j0 = blockIdx.x * 32;
    const int d0 = blockIdx.y * 32;
    const int nh = blockIdx.z;
    const int n  = nh >> 4;
    const int h  = nh & 15;

#pragma unroll
    for (int k = 0; k < 4; k++) {
        int j = j0 + ty + 8 * k;
        th[ty + 8 * k][tx] = v16[(size_t)(n * LSEQ + j) * EMB + h * HD + d0 + tx];
    }
    __syncthreads();
#pragma unroll
    for (int k = 0; k < 4; k++) {
        int d = d0 + ty + 8 * k;
        vt16[(size_t)(nh * HD + d) * LSEQ + j0 + tx] = th[tx][ty + 8 * k];
    }
}

// ---------------------------------------------------------------------------
// Tensor-core flash attention: fp16 single-pass QK and PV, fp32 softmax/accum.
// Smem: 2 stages x (K + V) x 64 x ATSTR fp16 = 36864 B -> 2 CTAs/SM.
// ---------------------------------------------------------------------------
#define ATSTR 72
#define ATILE_B (64 * ATSTR * 2)       // 9216
#define ASTAGE_B (2 * ATILE_B)         // 18432
#define ASMEM (2 * ASTAGE_B)           // 36864

__global__ __launch_bounds__(256, 2) void attn_mma_kernel()
{
    extern __shared__ __align__(16) __half asm_buf[];

    const int tid  = threadIdx.x;
    const int wid  = tid >> 5;
    const int lane = tid & 31;
    const int q0 = blockIdx.x * 128;
    const int h  = blockIdx.y;
    const int n  = blockIdx.z;

    const uint32_t uS = smem_u32(asm_buf);
    const uint32_t aLane = (uint32_t)(((lane & 15) * ATSTR + (lane >> 4) * 8) * 2);
    const uint32_t bLane = (uint32_t)(((((lane >> 4) << 3) + (lane & 7)) * ATSTR + ((lane >> 3) & 1) * 8) * 2);

    const int kr0 = tid >> 3,         kc0 = tid & 7;
    const int kr1 = (tid + 256) >> 3, kc1 = (tid + 256) & 7;
    const uint32_t ksd0 = (uint32_t)((kr0 * ATSTR + kc0 * 8) * 2);
    const uint32_t ksd1 = (uint32_t)((kr1 * ATSTR + kc1 * 8) * 2);

    auto load_kv = [&](int s, int kt) {
        uint32_t base = uS + (uint32_t)(s * ASTAGE_B);
        size_t kb0 = (size_t)(n * LSEQ + kt + kr0) * EMB + h * HD + kc0 * 8;
        size_t vb0 = (size_t)((n * NH + h) * HD + kr0) * LSEQ + kt + kc0 * 8;
        size_t kb1 = (size_t)(n * LSEQ + kt + kr1) * EMB + h * HD + kc1 * 8;
        size_t vb1 = (size_t)((n * NH + h) * HD + kr1) * LSEQ + kt + kc1 * 8;
        cp_async16(base + ksd0,           &g_k16[kb0]);
        cp_async16(base + ATILE_B + ksd0, &g_vt16[vb0]);
        cp_async16(base + ksd1,           &g_k16[kb1]);
        cp_async16(base + ATILE_B + ksd1, &g_vt16[vb1]);
    };

    // Phase 1: load Q (scaled by 1/8) into stage 0, hoist fragments
    const __half2 sc2 = __floats2half2_rn(0.125f, 0.125f);
#pragma unroll
    for (int i = 0; i < 2; i++) {
        int idx = tid + i * 256;           // 0..511
        int r = idx >> 2;                  // 0..127
        int c = idx & 3;
        int cc = c * 2;
#pragma unroll
        for (int u = 0; u < 2; u++) {
            size_t src = (size_t)(n * LSEQ + q0 + r) * EMB + h * HD + (cc + u) * 8;
            int4 v = *(const int4*)&g_q16[src];
            __half2* p = (__half2*)&v;
#pragma unroll
            for (int z = 0; z < 4; z++) p[z] = __hmul2(p[z], sc2);
            *(int4*)&asm_buf[r * ATSTR + (cc + u) * 8] = v;
        }
    }
    __syncthreads();

    uint32_t qf[4][4];
#pragma unroll
    for (int kk = 0; kk < 4; kk++)
        ldsm_x4(qf[kk], uS + (uint32_t)((wid * 16 * ATSTR + kk * 16) * 2) + aLane);
    __syncthreads();   // Q frags in regs; stage 0 reusable

    float oo[8][4];
#pragma unroll
    for (int ni = 0; ni < 8; ni++)
#pragma unroll
        for (int r = 0; r < 4; r++) oo[ni][r] = 0.0f;
    float m0 = -1e30f, m1 = -1e30f, l0 = 0.0f, l1 = 0.0f;

    load_kv(0, 0);
    CP_COMMIT();

    for (int t = 0; t < LSEQ / 64; t++) {
        if (t + 1 < LSEQ / 64) load_kv((t + 1) & 1, (t + 1) * 64);
        CP_COMMIT();
        CP_WAIT1();
        __syncthreads();

        const uint32_t oK = uS + (uint32_t)((t & 1) * ASTAGE_B);
        const uint32_t oV = oK + ATILE_B;

        // S = Q @ K^T
        float sS[8][4];
#pragma unroll
        for (int ni = 0; ni < 8; ni++)
#pragma unroll
            for (int r = 0; r < 4; r++) sS[ni][r] = 0.0f;
#pragma unroll
        for (int nb = 0; nb < 4; nb++) {
            uint32_t kf[4][4];
#pragma unroll
            for (int kk = 0; kk < 4; kk++)
                ldsm_x4(kf[kk], oK + (uint32_t)((nb * 16 * ATSTR + kk * 16) * 2) + bLane);
#pragma unroll
            for (int kk = 0; kk < 4; kk++)
#pragma unroll
                for (int i = 0; i < 2; i++)
                    mma_f16(sS[nb * 2 + i], qf[kk], kf[kk][i * 2], kf[kk][i * 2 + 1]);
        }

        // Online softmax (fp32)
        float mt0 = -1e30f, mt1 = -1e30f;
#pragma unroll
        for (int ni = 0; ni < 8; ni++) {
            mt0 = fmaxf(mt0, fmaxf(sS[ni][0], sS[ni][1]));
            mt1 = fmaxf(mt1, fmaxf(sS[ni][2], sS[ni][3]));
        }
#pragma unroll
        for (int off = 1; off <= 2; off <<= 1) {
            mt0 = fmaxf(mt0, __shfl_xor_sync(0xffffffffu, mt0, off));
            mt1 = fmaxf(mt1, __shfl_xor_sync(0xffffffffu, mt1, off));
        }
        float mn0 = fmaxf(m0, mt0), mn1 = fmaxf(m1, mt1);
        float c0 = __expf(m0 - mn0), c1 = __expf(m1 - mn1);

        uint32_t pf[4][4];
        float s0 = 0.0f, s1 = 0.0f;
#pragma unroll
        for (int ni = 0; ni < 8; ni++) {
            float p0 = __expf(sS[ni][0] - mn0);
            float p1 = __expf(sS[ni][1] - mn0);
            float p2 = __expf(sS[ni][2] - mn1);
            float p3 = __expf(sS[ni][3] - mn1);
            s0 += p0 + p1; s1 += p2 + p3;
            pf[ni >> 1][(ni & 1) * 2 + 0] = pack_f16x2(p0, p1);
            pf[ni >> 1][(ni & 1) * 2 + 1] = pack_f16x2(p2, p3);
        }
#pragma unroll
        for (int off = 1; off <= 2; off <<= 1) {
            s0 += __shfl_xor_sync(0xffffffffu, s0, off);
            s1 += __shfl_xor_sync(0xffffffffu, s1, off);
        }
        l0 = l0 * c0 + s0;
        l1 = l1 * c1 + s1;
        m0 = mn0; m1 = mn1;
#pragma unroll
        for (int ni = 0; ni < 8; ni++) {
            oo[ni][0] *= c0; oo[ni][1] *= c0;
            oo[ni][2] *= c1; oo[ni][3] *= c1;
        }

        // O += P @ V
#pragma unroll
        for (int nbd = 0; nbd < 4; nbd++) {
            uint32_t vf[4][4];
#pragma unroll
            for (int kk = 0; kk < 4; kk++)
                ldsm_x4(vf[kk], oV + (uint32_t)((nbd * 16 * ATSTR + kk * 16) * 2) + bLane);
#pragma unroll
            for (int kk = 0; kk < 4; kk++)
#pragma unroll
                for (int i = 0; i < 2; i++)
                    mma_f16(oo[nbd * 2 + i], pf[kk], vf[kk][i * 2], vf[kk][i * 2 + 1]);
        }
        __syncthreads();
    }

    // Epilogue: normalize, store fp16 (A-side of O-projection)
    float inv0 = 1.0f / l0, inv1 = 1.0f / l1;
    const int er = lane >> 2;
    const int ec = (lane & 3) * 2;
#pragma unroll
    for (int ni = 0; ni < 8; ni++) {
        int r = n * LSEQ + q0 + wid * 16 + er;
        int c = h * HD + ni * 8 + ec;
        *(uint32_t*)&g_a16[(size_t)r * EMB + c] =
            pack_f16x2(oo[ni][0] * inv0, oo[ni][1] * inv0);
        *(uint32_t*)&g_a16[(size_t)(r + 8) * EMB + c] =
            pack_f16x2(oo[ni][2] * inv1, oo[ni][3] * inv1);
    }
}

// ---------------------------------------------------------------------------
// Launch
// ---------------------------------------------------------------------------
extern "C" void kernel_launch(void* const* d_in, const int* in_sizes, int n_in,
                              void* d_out, int out_size)
{
    const float* Q  = (const float*)d_in[0];
    const float* K  = (const float*)d_in[1];
    const float* V  = (const float*)d_in[2];
    const float* Wq = (const float*)d_in[3];
    const float* bq = (const float*)d_in[4];
    const float* Wk = (const float*)d_in[5];
    const float* bk = (const float*)d_in[6];
    const float* Wv = (const float*)d_in[7];
    const float* bv = (const float*)d_in[8];
    const float* Wo = (const float*)d_in[9];
    const float* bo = (const float*)d_in[10];
    float* out = (float*)d_out;

    __half *xq16, *xk16, *xv16;
    __half *wqhi, *wqlo, *wkhi, *wklo, *wvhi, *wvlo, *wohi, *wolo;
    __half *q16, *k16, *v16, *vt16, *a16;
    cudaGetSymbolAddress((void**)&xq16, g_xq16);
    cudaGetSymbolAddress((void**)&xk16, g_xk16);
    cudaGetSymbolAddress((void**)&xv16, g_xv16);
    cudaGetSymbolAddress((void**)&wqhi, g_wqhi); cudaGetSymbolAddress((void**)&wqlo, g_wqlo);
    cudaGetSymbolAddress((void**)&wkhi, g_wkhi); cudaGetSymbolAddress((void**)&wklo, g_wklo);
    cudaGetSymbolAddress((void**)&wvhi, g_wvhi); cudaGetSymbolAddress((void**)&wvlo, g_wvlo);
    cudaGetSymbolAddress((void**)&wohi, g_wohi); cudaGetSymbolAddress((void**)&wolo, g_wolo);
    cudaGetSymbolAddress((void**)&q16,  g_q16);  cudaGetSymbolAddress((void**)&k16,  g_k16);
    cudaGetSymbolAddress((void**)&v16,  g_v16);  cudaGetSymbolAddress((void**)&vt16, g_vt16);
    cudaGetSymbolAddress((void**)&a16,  g_a16);

    cudaFuncSetAttribute(gemm_qkv_kernel,   cudaFuncAttributeMaxDynamicSharedMemorySize, GSMEM);
    cudaFuncSetAttribute(gemm_final_kernel, cudaFuncAttributeMaxDynamicSharedMemorySize, GSMEM);
    cudaFuncSetAttribute(attn_mma_kernel,   cudaFuncAttributeMaxDynamicSharedMemorySize, ASMEM);

    const int nA4 = MROWS * EMB / 4;
    const int nW4 = EMB * EMB / 4;

    // Convert inputs to fp16; split weights (scaled) into fp16 hi/lo
    Cvt3 c3;
    c3.in[0] = Q; c3.in[1] = K; c3.in[2] = V;
    c3.out[0] = xq16; c3.out[1] = xk16; c3.out[2] = xv16;
    cvt3_kernel<<<dim3(nA4 / 256, 3), 256>>>(c3, nA4);

    WSplit4 w4;
    w4.in[0] = Wq; w4.in[1] = Wk; w4.in[2] = Wv; w4.in[3] = Wo;
    w4.hi[0] = wqhi; w4.hi[1] = wkhi; w4.hi[2] = wvhi; w4.hi[3] = wohi;
    w4.lo[0] = wqlo; w4.lo[1] = wklo; w4.lo[2] = wvlo; w4.lo[3] = wolo;
    wsplit4_kernel<<<dim3(nW4 / 256, 4), 256>>>(w4, nW4);

    // Q/K/V projections (fp16 2-term) in one batched launch
    GemmQKV gp;
    gp.A[0] = xq16; gp.Whi[0] = wqhi; gp.Wlo[0] = wqlo; gp.bias[0] = bq; gp.Cout[0] = q16;
    gp.A[1] = xk16; gp.Whi[1] = wkhi; gp.Wlo[1] = wklo; gp.bias[1] = bk; gp.Cout[1] = k16;
    gp.A[2] = xv16; gp.Whi[2] = wvhi; gp.Wlo[2] = wvlo; gp.bias[2] = bv; gp.Cout[2] = v16;
    gemm_qkv_kernel<<<dim3(EMB / 128, MROWS / 128, 3), 256, GSMEM>>>(gp);

    // V transpose (fp16)
    vt_kernel<<<dim3(LSEQ / 32, HD / 32, NB * NH), 256>>>(v16, vt16);

    // Attention (fp16 single-pass; writes g_a16)
    attn_mma_kernel<<<dim3(LSEQ / 128, NH, NB), 256, ASMEM>>>();

    // Output projection (fp16 2-term, fp32 out)
    gemm_final_kernel<<<dim3(EMB / 128, MROWS / 128), 256, GSMEM>>>(a16, wohi, wolo, bo, out);
}

// round 10
// speedup vs baseline: 9.0025x; 1.3243x over previous
#include <cuda_runtime.h>
#include <cuda_bf16.h>
#include <cuda_fp16.h>
#include <cstdint>

// Problem constants
#define NB    4
#define LSEQ  2048
#define EMB   1024
#define NH    16
#define HD    64
#define MROWS (NB * LSEQ)   // 8192

// Scratch (static device arrays — no allocation allowed)
// fp16 A-side inputs for Q/K/V projections
__device__ __half g_xq16[MROWS * EMB];
__device__ __half g_xk16[MROWS * EMB];
__device__ __half g_xv16[MROWS * EMB];
// fp16 weights (pre-scaled by 2^10)
__device__ __half g_wq16[EMB * EMB];
__device__ __half g_wk16[EMB * EMB];
__device__ __half g_wv16[EMB * EMB];
__device__ __half g_wo16[EMB * EMB];
// Projection outputs (fp16, attention operands)
__device__ __half g_q16[MROWS * EMB];
__device__ __half g_k16[MROWS * EMB];
__device__ __half g_v16[MROWS * EMB];
__device__ __half g_vt16[MROWS * EMB];   // transposed: [(n*16+h)*64+d][j]
// Attention output (fp16, A-side of O-projection)
__device__ __half g_a16[MROWS * EMB];

// ---------------------------------------------------------------------------
// Warp-level tensor-core + async-copy primitives (baseline ISA on compute_103)
// ---------------------------------------------------------------------------
__device__ __forceinline__ uint32_t smem_u32(const void* p) {
    uint32_t a;
    asm("{ .reg .u64 t; cvta.to.shared.u64 t, %1; cvt.u32.u64 %0, t; }" : "=r"(a) : "l"(p));
    return a;
}

__device__ __forceinline__ void ldsm_x4(uint32_t* r, uint32_t addr) {
    asm volatile("ldmatrix.sync.aligned.m8n8.x4.shared.b16 {%0,%1,%2,%3}, [%4];"
        : "=r"(r[0]), "=r"(r[1]), "=r"(r[2]), "=r"(r[3]) : "r"(addr));
}

__device__ __forceinline__ void mma_f16(float* d, const uint32_t* a, uint32_t b0, uint32_t b1) {
    asm volatile(
        "mma.sync.aligned.m16n8k16.row.col.f32.f16.f16.f32 "
        "{%0,%1,%2,%3}, {%4,%5,%6,%7}, {%8,%9}, {%0,%1,%2,%3};"
        : "+f"(d[0]), "+f"(d[1]), "+f"(d[2]), "+f"(d[3])
        : "r"(a[0]), "r"(a[1]), "r"(a[2]), "r"(a[3]), "r"(b0), "r"(b1));
}

__device__ __forceinline__ uint32_t pack_f16x2(float lo, float hi) {
    __half2 p = __floats2half2_rn(lo, hi);
    return *(uint32_t*)&p;
}

__device__ __forceinline__ void cp_async16(uint32_t saddr, const void* g) {
    asm volatile("cp.async.cg.shared.global [%0], [%1], 16;" :: "r"(saddr), "l"(g));
}
#define CP_COMMIT() asm volatile("cp.async.commit_group;")
#define CP_WAIT1()  asm volatile("cp.async.wait_group 1;")

// ---------------------------------------------------------------------------
// fp32 -> fp16 convert: 3 input tensors (scale 1) + 4 weights (scale 1024)
// ---------------------------------------------------------------------------
struct Cvt3 { const float* in[3]; __half* out[3]; };
struct Cvt4 { const float* in[4]; __half* out[4]; };

__global__ __launch_bounds__(256) void cvt3_kernel(Cvt3 P, int n4)
{
    int i = blockIdx.x * 256 + threadIdx.x;
    int z = blockIdx.y;
    if (i >= n4) return;
    float4 x = ((const float4*)P.in[z])[i];
    uint2 o;
    o.x = pack_f16x2(x.x, x.y);
    o.y = pack_f16x2(x.z, x.w);
    ((uint2*)P.out[z])[i] = o;
}

__global__ __launch_bounds__(256) void wcvt4_kernel(Cvt4 P, int n4)
{
    int i = blockIdx.x * 256 + threadIdx.x;
    int z = blockIdx.y;
    if (i >= n4) return;
    float4 x = ((const float4*)P.in[z])[i];
    uint2 o;
    o.x = pack_f16x2(x.x * 1024.0f, x.y * 1024.0f);
    o.y = pack_f16x2(x.z * 1024.0f, x.w * 1024.0f);
    ((uint2*)P.out[z])[i] = o;
}

// ---------------------------------------------------------------------------
// HMMA GEMM body: C = A @ W^T + bias, single fp16 pass (W pre-scaled 2^10,
// epilogue multiplies by 2^-10). OM=0: fp32 out. OM=2: fp16 out.
// Smem: 2 stages x 2 tiles x (128 x TSTR) fp16 = 40960 B.
// ---------------------------------------------------------------------------
#define BK    32
#define TSTR  40
#define GTILE (128 * TSTR)
#define GSTAGE_B (2 * GTILE * 2)
#define GSMEM (2 * GSTAGE_B)   // 40960

template <int OM>
__device__ __forceinline__ void gemm_body(
    const __half* __restrict__ A, const __half* __restrict__ W,
    const float* __restrict__ bias, void* __restrict__ Cout,
    __half* dsm)
{
    const int tid  = threadIdx.x;
    const int wid  = tid >> 5;
    const int lane = tid & 31;
    const int wm   = wid >> 2;
    const int wn   = wid & 3;
    const int row0 = blockIdx.y * 128;
    const int col0 = blockIdx.x * 128;

    const uint32_t uS = smem_u32(dsm);
    const uint32_t aLane = (uint32_t)(((lane & 15) * TSTR + (lane >> 4) * 8) * 2);
    const uint32_t bLane = (uint32_t)(((((lane >> 4) << 3) + (lane & 7)) * TSTR + ((lane >> 3) & 1) * 8) * 2);

    const int lr0 = tid >> 2,         lc0 = tid & 3;
    const int lr1 = (tid + 256) >> 2, lc1 = (tid + 256) & 3;
    const uint32_t sd0 = (uint32_t)((lr0 * TSTR + lc0 * 8) * 2);
    const uint32_t sd1 = (uint32_t)((lr1 * TSTR + lc1 * 8) * 2);

    auto load_stage = [&](int s, int kt) {
        uint32_t base = uS + (uint32_t)(s * GSTAGE_B);
        size_t ga0 = (size_t)(row0 + lr0) * EMB + kt + lc0 * 8;
        size_t gw0 = (size_t)(col0 + lr0) * EMB + kt + lc0 * 8;
        size_t ga1 = (size_t)(row0 + lr1) * EMB + kt + lc1 * 8;
        size_t gw1 = (size_t)(col0 + lr1) * EMB + kt + lc1 * 8;
        cp_async16(base + sd0,             &A[ga0]);
        cp_async16(base + GTILE * 2 + sd0, &W[gw0]);
        cp_async16(base + sd1,             &A[ga1]);
        cp_async16(base + GTILE * 2 + sd1, &W[gw1]);
    };

    float acc[4][4][4];
#pragma unroll
    for (int mi = 0; mi < 4; mi++)
#pragma unroll
        for (int ni = 0; ni < 4; ni++)
#pragma unroll
            for (int r = 0; r < 4; r++) acc[mi][ni][r] = 0.0f;

    load_stage(0, 0);
    CP_COMMIT();

    for (int t = 0; t < EMB / BK; t++) {
        if (t + 1 < EMB / BK) load_stage((t + 1) & 1, (t + 1) * BK);
        CP_COMMIT();
        CP_WAIT1();
        __syncthreads();

        const uint32_t uA = uS + (uint32_t)((t & 1) * GSTAGE_B);
        const uint32_t uB = uA + GTILE * 2;

#pragma unroll
        for (int ks = 0; ks < 2; ks++) {
            uint32_t bf[2][4];
#pragma unroll
            for (int nb = 0; nb < 2; nb++) {
                uint32_t boff = (uint32_t)(((wn * 32 + nb * 16) * TSTR + ks * 16) * 2) + bLane;
                ldsm_x4(bf[nb], uB + boff);
            }
#pragma unroll
            for (int mi = 0; mi < 4; mi++) {
                uint32_t aoff = (uint32_t)(((wm * 64 + mi * 16) * TSTR + ks * 16) * 2) + aLane;
                uint32_t af[4];
                ldsm_x4(af, uA + aoff);
#pragma unroll
                for (int ni = 0; ni < 4; ni++)
                    mma_f16(acc[mi][ni], af, bf[ni >> 1][(ni & 1) * 2], bf[ni >> 1][(ni & 1) * 2 + 1]);
            }
        }
        __syncthreads();
    }

    const float iw = 1.0f / 1024.0f;   // undo W pre-scale (exact power of 2)
    const int er = lane >> 2;
    const int ec = (lane & 3) * 2;
#pragma unroll
    for (int mi = 0; mi < 4; mi++) {
#pragma unroll
        for (int ni = 0; ni < 4; ni++) {
            int r = row0 + wm * 64 + mi * 16 + er;
            int c = col0 + wn * 32 + ni * 8 + ec;
            float b0 = bias[c], b1 = bias[c + 1];
            float v00 = acc[mi][ni][0] * iw + b0, v01 = acc[mi][ni][1] * iw + b1;
            float v10 = acc[mi][ni][2] * iw + b0, v11 = acc[mi][ni][3] * iw + b1;
            if (OM == 0) {
                float* C = (float*)Cout;
                *(float2*)&C[(size_t)r * EMB + c] = make_float2(v00, v01);
                *(float2*)&C[(size_t)(r + 8) * EMB + c] = make_float2(v10, v11);
            } else {
                __half* C = (__half*)Cout;
                *(uint32_t*)&C[(size_t)r * EMB + c]       = pack_f16x2(v00, v01);
                *(uint32_t*)&C[(size_t)(r + 8) * EMB + c] = pack_f16x2(v10, v11);
            }
        }
    }
}

struct GemmQKV {
    const __half *A[3], *W[3];
    const float* bias[3];
    __half* Cout[3];
};

__global__ __launch_bounds__(256, 2) void gemm_qkv_kernel(GemmQKV P)
{
    extern __shared__ __align__(16) __half dsm[];
    const int z = blockIdx.z;
    gemm_body<2>(P.A[z], P.W[z], P.bias[z], P.Cout[z], dsm);
}

__global__ __launch_bounds__(256, 2) void gemm_final_kernel(
    const __half* __restrict__ A, const __half* __restrict__ W,
    const float* __restrict__ bias, float* __restrict__ Cout)
{
    extern __shared__ __align__(16) __half dsm[];
    gemm_body<0>(A, W, bias, Cout, dsm);
}

// ---------------------------------------------------------------------------
// V transpose (fp16): [n*2048+j][h*64+d] -> [(n*16+h)*64+d][j]
// ---------------------------------------------------------------------------
__global__ __launch_bounds__(256) void vt_kernel(
    const __half* __restrict__ v16, __half* __restrict__ vt16)
{
    __shared__ __half th[32][33];
    const int tx = threadIdx.x & 31;
    const int ty = threadIdx.x >> 5;
    const int j0 = blockIdx.x * 32;
    const int d0 = blockIdx.y * 32;
    const int nh = blockIdx.z;
    const int n  = nh >> 4;
    const int h  = nh & 15;

#pragma unroll
    for (int k = 0; k < 4; k++) {
        int j = j0 + ty + 8 * k;
        th[ty + 8 * k][tx] = v16[(size_t)(n * LSEQ + j) * EMB + h * HD + d0 + tx];
    }
    __syncthreads();
#pragma unroll
    for (int k = 0; k < 4; k++) {
        int d = d0 + ty + 8 * k;
        vt16[(size_t)(nh * HD + d) * LSEQ + j0 + tx] = th[tx][ty + 8 * k];
    }
}

// ---------------------------------------------------------------------------
// Tensor-core flash attention: fp16 single-pass QK and PV, fp32 softmax/accum.
// Smem: 2 stages x (K + V) x 64 x ATSTR fp16 = 36864 B -> 2 CTAs/SM.
// ---------------------------------------------------------------------------
#define ATSTR 72
#define ATILE_B (64 * ATSTR * 2)       // 9216
#define ASTAGE_B (2 * ATILE_B)         // 18432
#define ASMEM (2 * ASTAGE_B)           // 36864

__global__ __launch_bounds__(256, 2) void attn_mma_kernel()
{
    extern __shared__ __align__(16) __half asm_buf[];

    const int tid  = threadIdx.x;
    const int wid  = tid >> 5;
    const int lane = tid & 31;
    const int q0 = blockIdx.x * 128;
    const int h  = blockIdx.y;
    const int n  = blockIdx.z;

    const uint32_t uS = smem_u32(asm_buf);
    const uint32_t aLane = (uint32_t)(((lane & 15) * ATSTR + (lane >> 4) * 8) * 2);
    const uint32_t bLane = (uint32_t)(((((lane >> 4) << 3) + (lane & 7)) * ATSTR + ((lane >> 3) & 1) * 8) * 2);

    const int kr0 = tid >> 3,         kc0 = tid & 7;
    const int kr1 = (tid + 256) >> 3, kc1 = (tid + 256) & 7;
    const uint32_t ksd0 = (uint32_t)((kr0 * ATSTR + kc0 * 8) * 2);
    const uint32_t ksd1 = (uint32_t)((kr1 * ATSTR + kc1 * 8) * 2);

    auto load_kv = [&](int s, int kt) {
        uint32_t base = uS + (uint32_t)(s * ASTAGE_B);
        size_t kb0 = (size_t)(n * LSEQ + kt + kr0) * EMB + h * HD + kc0 * 8;
        size_t vb0 = (size_t)((n * NH + h) * HD + kr0) * LSEQ + kt + kc0 * 8;
        size_t kb1 = (size_t)(n * LSEQ + kt + kr1) * EMB + h * HD + kc1 * 8;
        size_t vb1 = (size_t)((n * NH + h) * HD + kr1) * LSEQ + kt + kc1 * 8;
        cp_async16(base + ksd0,           &g_k16[kb0]);
        cp_async16(base + ATILE_B + ksd0, &g_vt16[vb0]);
        cp_async16(base + ksd1,           &g_k16[kb1]);
        cp_async16(base + ATILE_B + ksd1, &g_vt16[vb1]);
    };

    // Phase 1: load Q (scaled by 1/8) into stage 0, hoist fragments
    const __half2 sc2 = __floats2half2_rn(0.125f, 0.125f);
#pragma unroll
    for (int i = 0; i < 2; i++) {
        int idx = tid + i * 256;           // 0..511
        int r = idx >> 2;                  // 0..127
        int c = idx & 3;
        int cc = c * 2;
#pragma unroll
        for (int u = 0; u < 2; u++) {
            size_t src = (size_t)(n * LSEQ + q0 + r) * EMB + h * HD + (cc + u) * 8;
            int4 v = *(const int4*)&g_q16[src];
            __half2* p = (__half2*)&v;
#pragma unroll
            for (int z = 0; z < 4; z++) p[z] = __hmul2(p[z], sc2);
            *(int4*)&asm_buf[r * ATSTR + (cc + u) * 8] = v;
        }
    }
    __syncthreads();

    uint32_t qf[4][4];
#pragma unroll
    for (int kk = 0; kk < 4; kk++)
        ldsm_x4(qf[kk], uS + (uint32_t)((wid * 16 * ATSTR + kk * 16) * 2) + aLane);
    __syncthreads();   // Q frags in regs; stage 0 reusable

    float oo[8][4];
#pragma unroll
    for (int ni = 0; ni < 8; ni++)
#pragma unroll
        for (int r = 0; r < 4; r++) oo[ni][r] = 0.0f;
    float m0 = -1e30f, m1 = -1e30f, l0 = 0.0f, l1 = 0.0f;

    load_kv(0, 0);
    CP_COMMIT();

    for (int t = 0; t < LSEQ / 64; t++) {
        if (t + 1 < LSEQ / 64) load_kv((t + 1) & 1, (t + 1) * 64);
        CP_COMMIT();
        CP_WAIT1();
        __syncthreads();

        const uint32_t oK = uS + (uint32_t)((t & 1) * ASTAGE_B);
        const uint32_t oV = oK + ATILE_B;

        // S = Q @ K^T
        float sS[8][4];
#pragma unroll
        for (int ni = 0; ni < 8; ni++)
#pragma unroll
            for (int r = 0; r < 4; r++) sS[ni][r] = 0.0f;
#pragma unroll
        for (int nb = 0; nb < 4; nb++) {
            uint32_t kf[4][4];
#pragma unroll
            for (int kk = 0; kk < 4; kk++)
                ldsm_x4(kf[kk], oK + (uint32_t)((nb * 16 * ATSTR + kk * 16) * 2) + bLane);
#pragma unroll
            for (int kk = 0; kk < 4; kk++)
#pragma unroll
                for (int i = 0; i < 2; i++)
                    mma_f16(sS[nb * 2 + i], qf[kk], kf[kk][i * 2], kf[kk][i * 2 + 1]);
        }

        // Online softmax (fp32)
        float mt0 = -1e30f, mt1 = -1e30f;
#pragma unroll
        for (int ni = 0; ni < 8; ni++) {
            mt0 = fmaxf(mt0, fmaxf(sS[ni][0], sS[ni][1]));
            mt1 = fmaxf(mt1, fmaxf(sS[ni][2], sS[ni][3]));
        }
#pragma unroll
        for (int off = 1; off <= 2; off <<= 1) {
            mt0 = fmaxf(mt0, __shfl_xor_sync(0xffffffffu, mt0, off));
            mt1 = fmaxf(mt1, __shfl_xor_sync(0xffffffffu, mt1, off));
        }
        float mn0 = fmaxf(m0, mt0), mn1 = fmaxf(m1, mt1);
        float c0 = __expf(m0 - mn0), c1 = __expf(m1 - mn1);

        uint32_t pf[4][4];
        float s0 = 0.0f, s1 = 0.0f;
#pragma unroll
        for (int ni = 0; ni < 8; ni++) {
            float p0 = __expf(sS[ni][0] - mn0);
            float p1 = __expf(sS[ni][1] - mn0);
            float p2 = __expf(sS[ni][2] - mn1);
            float p3 = __expf(sS[ni][3] - mn1);
            s0 += p0 + p1; s1 += p2 + p3;
            pf[ni >> 1][(ni & 1) * 2 + 0] = pack_f16x2(p0, p1);
            pf[ni >> 1][(ni & 1) * 2 + 1] = pack_f16x2(p2, p3);
        }
#pragma unroll
        for (int off = 1; off <= 2; off <<= 1) {
            s0 += __shfl_xor_sync(0xffffffffu, s0, off);
            s1 += __shfl_xor_sync(0xffffffffu, s1, off);
        }
        l0 = l0 * c0 + s0;
        l1 = l1 * c1 + s1;
        m0 = mn0; m1 = mn1;
#pragma unroll
        for (int ni = 0; ni < 8; ni++) {
            oo[ni][0] *= c0; oo[ni][1] *= c0;
            oo[ni][2] *= c1; oo[ni][3] *= c1;
        }

        // O += P @ V
#pragma unroll
        for (int nbd = 0; nbd < 4; nbd++) {
            uint32_t vf[4][4];
#pragma unroll
            for (int kk = 0; kk < 4; kk++)
                ldsm_x4(vf[kk], oV + (uint32_t)((nbd * 16 * ATSTR + kk * 16) * 2) + bLane);
#pragma unroll
            for (int kk = 0; kk < 4; kk++)
#pragma unroll
                for (int i = 0; i < 2; i++)
                    mma_f16(oo[nbd * 2 + i], pf[kk], vf[kk][i * 2], vf[kk][i * 2 + 1]);
        }
        __syncthreads();
    }

    // Epilogue: normalize, store fp16 (A-side of O-projection)
    float inv0 = 1.0f / l0, inv1 = 1.0f / l1;
    const int er = lane >> 2;
    const int ec = (lane & 3) * 2;
#pragma unroll
    for (int ni = 0; ni < 8; ni++) {
        int r = n * LSEQ + q0 + wid * 16 + er;
        int c = h * HD + ni * 8 + ec;
        *(uint32_t*)&g_a16[(size_t)r * EMB + c] =
            pack_f16x2(oo[ni][0] * inv0, oo[ni][1] * inv0);
        *(uint32_t*)&g_a16[(size_t)(r + 8) * EMB + c] =
            pack_f16x2(oo[ni][2] * inv1, oo[ni][3] * inv1);
    }
}

// ---------------------------------------------------------------------------
// Launch
// ---------------------------------------------------------------------------
extern "C" void kernel_launch(void* const* d_in, const int* in_sizes, int n_in,
                              void* d_out, int out_size)
{
    const float* Q  = (const float*)d_in[0];
    const float* K  = (const float*)d_in[1];
    const float* V  = (const float*)d_in[2];
    const float* Wq = (const float*)d_in[3];
    const float* bq = (const float*)d_in[4];
    const float* Wk = (const float*)d_in[5];
    const float* bk = (const float*)d_in[6];
    const float* Wv = (const float*)d_in[7];
    const float* bv = (const float*)d_in[8];
    const float* Wo = (const float*)d_in[9];
    const float* bo = (const float*)d_in[10];
    float* out = (float*)d_out;

    __half *xq16, *xk16, *xv16;
    __half *wq16, *wk16, *wv16, *wo16;
    __half *q16, *k16, *v16, *vt16, *a16;
    cudaGetSymbolAddress((void**)&xq16, g_xq16);
    cudaGetSymbolAddress((void**)&xk16, g_xk16);
    cudaGetSymbolAddress((void**)&xv16, g_xv16);
    cudaGetSymbolAddress((void**)&wq16, g_wq16);
    cudaGetSymbolAddress((void**)&wk16, g_wk16);
    cudaGetSymbolAddress((void**)&wv16, g_wv16);
    cudaGetSymbolAddress((void**)&wo16, g_wo16);
    cudaGetSymbolAddress((void**)&q16,  g_q16);
    cudaGetSymbolAddress((void**)&k16,  g_k16);
    cudaGetSymbolAddress((void**)&v16,  g_v16);
    cudaGetSymbolAddress((void**)&vt16, g_vt16);
    cudaGetSymbolAddress((void**)&a16,  g_a16);

    cudaFuncSetAttribute(gemm_qkv_kernel,   cudaFuncAttributeMaxDynamicSharedMemorySize, GSMEM);
    cudaFuncSetAttribute(gemm_final_kernel, cudaFuncAttributeMaxDynamicSharedMemorySize, GSMEM);
    cudaFuncSetAttribute(attn_mma_kernel,   cudaFuncAttributeMaxDynamicSharedMemorySize, ASMEM);

    const int nA4 = MROWS * EMB / 4;
    const int nW4 = EMB * EMB / 4;

    // Convert inputs (fp16) and weights (fp16, pre-scaled 2^10)
    Cvt3 c3;
    c3.in[0] = Q; c3.in[1] = K; c3.in[2] = V;
    c3.out[0] = xq16; c3.out[1] = xk16; c3.out[2] = xv16;
    cvt3_kernel<<<dim3(nA4 / 256, 3), 256>>>(c3, nA4);

    Cvt4 c4;
    c4.in[0] = Wq; c4.in[1] = Wk; c4.in[2] = Wv; c4.in[3] = Wo;
    c4.out[0] = wq16; c4.out[1] = wk16; c4.out[2] = wv16; c4.out[3] = wo16;
    wcvt4_kernel<<<dim3(nW4 / 256, 4), 256>>>(c4, nW4);

    // Q/K/V projections (single fp16 pass) in one batched launch
    GemmQKV gp;
    gp.A[0] = xq16; gp.W[0] = wq16; gp.bias[0] = bq; gp.Cout[0] = q16;
    gp.A[1] = xk16; gp.W[1] = wk16; gp.bias[1] = bk; gp.Cout[1] = k16;
    gp.A[2] = xv16; gp.W[2] = wv16; gp.bias[2] = bv; gp.Cout[2] = v16;
    gemm_qkv_kernel<<<dim3(EMB / 128, MROWS / 128, 3), 256, GSMEM>>>(gp);

    // V transpose (fp16)
    vt_kernel<<<dim3(LSEQ / 32, HD / 32, NB * NH), 256>>>(v16, vt16);

    // Attention (fp16 single-pass; writes g_a16)
    attn_mma_kernel<<<dim3(LSEQ / 128, NH, NB), 256, ASMEM>>>();

    // Output projection (single fp16 pass, fp32 out)
    gemm_final_kernel<<<dim3(EMB / 128, MROWS / 128), 256, GSMEM>>>(a16, wo16, bo, out);
}